// round 1
// baseline (speedup 1.0000x reference)
#include <cuda_runtime.h>
#include <math.h>

#define SEQ   2048
#define DMOD  1024
#define DIN   2048
#define NHEAD 8
#define DHEAD 256
#define DHID  2048

// ---------------- scratch (allocation-free: __device__ globals) ----------------
__device__ float g_hln [SEQ*DMOD];
__device__ float g_proj[SEQ*2*DIN];
__device__ float g_xc  [SEQ*DIN];
__device__ float g_q   [SEQ*DIN];
__device__ float g_k   [SEQ*DIN];
__device__ float g_v   [SEQ*DIN];
__device__ float g_ig  [NHEAD*SEQ];
__device__ float g_fg  [NHEAD*SEQ];
__device__ float g_rowt[NHEAD*SEQ];
__device__ float g_colt[NHEAD*SEQ];
__device__ float g_expn[NHEAD*SEQ];
__device__ float g_inrm[NHEAD*SEQ];
__device__ float g_C   [(size_t)NHEAD*SEQ*SEQ];
__device__ float g_hfl [SEQ*DIN];
__device__ float g_yin [SEQ*DIN];
__device__ float g_x2  [SEQ*DMOD];
__device__ float g_hf  [SEQ*DMOD];
__device__ float g_p   [SEQ*2*DHID];
__device__ float g_g2  [SEQ*DHID];

// ---------------- GEMM tile config ----------------
#define BM 128
#define BN 128
#define BK 16

// C[m,n] = sum_k A[m,k]*B[n,k]  (+bias[n]) (+resid[m,n])
__global__ __launch_bounds__(256, 2) void sgemm_nt(
    const float* __restrict__ A, const float* __restrict__ B,
    const float* __restrict__ bias, const float* __restrict__ resid,
    float* __restrict__ C, int K, int lda, int ldb, int ldc, int ldr)
{
    __shared__ float As[BK][BM+4];
    __shared__ float Bs[BK][BN+4];
    const int tid = threadIdx.x;
    const int m0 = blockIdx.y * BM;
    const int n0 = blockIdx.x * BN;
    const int tr = tid & 15;
    const int tc = tid >> 4;
    float acc[8][8];
#pragma unroll
    for (int i=0;i<8;i++)
#pragma unroll
        for (int j=0;j<8;j++) acc[i][j]=0.f;

    for (int k0=0;k0<K;k0+=BK) {
#pragma unroll
        for (int i=0;i<2;i++){
            int idx = i*256 + tid;
            int r = idx>>2, c = (idx&3)<<2;
            float4 av = *(const float4*)(A + (size_t)(m0+r)*lda + k0 + c);
            As[c+0][r]=av.x; As[c+1][r]=av.y; As[c+2][r]=av.z; As[c+3][r]=av.w;
            float4 bv = *(const float4*)(B + (size_t)(n0+r)*ldb + k0 + c);
            Bs[c+0][r]=bv.x; Bs[c+1][r]=bv.y; Bs[c+2][r]=bv.z; Bs[c+3][r]=bv.w;
        }
        __syncthreads();
#pragma unroll
        for (int kk=0;kk<BK;kk++){
            float4 a0 = *(const float4*)&As[kk][tr*8];
            float4 a1 = *(const float4*)&As[kk][tr*8+4];
            float4 b0 = *(const float4*)&Bs[kk][tc*8];
            float4 b1 = *(const float4*)&Bs[kk][tc*8+4];
            float a[8]={a0.x,a0.y,a0.z,a0.w,a1.x,a1.y,a1.z,a1.w};
            float b[8]={b0.x,b0.y,b0.z,b0.w,b1.x,b1.y,b1.z,b1.w};
#pragma unroll
            for(int i=0;i<8;i++)
#pragma unroll
                for(int j=0;j<8;j++) acc[i][j] = fmaf(a[i],b[j],acc[i][j]);
        }
        __syncthreads();
    }
#pragma unroll
    for (int i=0;i<8;i++){
        int row = m0 + tr*8 + i;
        float* crow = C + (size_t)row*ldc + n0 + tc*8;
        const float* rrow = resid ? (resid + (size_t)row*ldr + n0 + tc*8) : (const float*)0;
#pragma unroll
        for (int j=0;j<8;j++){
            float v = acc[i][j];
            if (bias) v += bias[n0+tc*8+j];
            if (rrow) v += rrow[j];
            crow[j] = v;
        }
    }
}

// batched NN: C[b][m,n] = sum_k A[b][m,k]*B[b][k,n]
__global__ __launch_bounds__(256, 2) void sgemm_nn_b(
    const float* __restrict__ A, const float* __restrict__ B, float* __restrict__ C,
    int K, int lda, int ldb, int ldc,
    long long sA, long long sB, long long sC)
{
    A += (long long)blockIdx.z * sA;
    B += (long long)blockIdx.z * sB;
    C += (long long)blockIdx.z * sC;
    __shared__ float As[BK][BM+4];
    __shared__ float Bs[BK][BN+4];
    const int tid = threadIdx.x;
    const int m0 = blockIdx.y * BM;
    const int n0 = blockIdx.x * BN;
    const int tr = tid & 15;
    const int tc = tid >> 4;
    float acc[8][8];
#pragma unroll
    for (int i=0;i<8;i++)
#pragma unroll
        for (int j=0;j<8;j++) acc[i][j]=0.f;

    for (int k0=0;k0<K;k0+=BK) {
#pragma unroll
        for (int i=0;i<2;i++){
            int idx = i*256 + tid;
            int r = idx>>2, c = (idx&3)<<2;
            float4 av = *(const float4*)(A + (size_t)(m0+r)*lda + k0 + c);
            As[c+0][r]=av.x; As[c+1][r]=av.y; As[c+2][r]=av.z; As[c+3][r]=av.w;
            int kk = idx>>5, cc = (idx&31)<<2;
            float4 bv = *(const float4*)(B + (size_t)(k0+kk)*ldb + n0 + cc);
            *(float4*)&Bs[kk][cc] = bv;
        }
        __syncthreads();
#pragma unroll
        for (int kk=0;kk<BK;kk++){
            float4 a0 = *(const float4*)&As[kk][tr*8];
            float4 a1 = *(const float4*)&As[kk][tr*8+4];
            float4 b0 = *(const float4*)&Bs[kk][tc*8];
            float4 b1 = *(const float4*)&Bs[kk][tc*8+4];
            float a[8]={a0.x,a0.y,a0.z,a0.w,a1.x,a1.y,a1.z,a1.w};
            float b[8]={b0.x,b0.y,b0.z,b0.w,b1.x,b1.y,b1.z,b1.w};
#pragma unroll
            for(int i=0;i<8;i++)
#pragma unroll
                for(int j=0;j<8;j++) acc[i][j] = fmaf(a[i],b[j],acc[i][j]);
        }
        __syncthreads();
    }
#pragma unroll
    for (int i=0;i<8;i++){
        int row = m0 + tr*8 + i;
        float* crow = C + (size_t)row*ldc + n0 + tc*8;
#pragma unroll
        for (int j=0;j<8;j++) crow[j] = acc[i][j];
    }
}

// scores: C[h][l,m] = (q_h[l]·k_h[m])/16 * exp(rowt[l]+colt[m]) for m<=l else 0
__global__ __launch_bounds__(256, 2) void score_kernel()
{
    const int h  = blockIdx.z;
    const int l0 = blockIdx.y * BM;
    const int m0 = blockIdx.x * BN;
    if (m0 >= l0 + BM) return;     // fully masked tile: skip (never read downstream)
    const float* A = g_q + h*DHEAD;
    const float* B = g_k + h*DHEAD;
    __shared__ float As[BK][BM+4];
    __shared__ float Bs[BK][BN+4];
    const int tid = threadIdx.x;
    const int tr = tid & 15;
    const int tc = tid >> 4;
    float acc[8][8];
#pragma unroll
    for (int i=0;i<8;i++)
#pragma unroll
        for (int j=0;j<8;j++) acc[i][j]=0.f;

    for (int k0=0;k0<DHEAD;k0+=BK) {
#pragma unroll
        for (int i=0;i<2;i++){
            int idx = i*256 + tid;
            int r = idx>>2, c = (idx&3)<<2;
            float4 av = *(const float4*)(A + (size_t)(l0+r)*DIN + k0 + c);
            As[c+0][r]=av.x; As[c+1][r]=av.y; As[c+2][r]=av.z; As[c+3][r]=av.w;
            float4 bv = *(const float4*)(B + (size_t)(m0+r)*DIN + k0 + c);
            Bs[c+0][r]=bv.x; Bs[c+1][r]=bv.y; Bs[c+2][r]=bv.z; Bs[c+3][r]=bv.w;
        }
        __syncthreads();
#pragma unroll
        for (int kk=0;kk<BK;kk++){
            float4 a0 = *(const float4*)&As[kk][tr*8];
            float4 a1 = *(const float4*)&As[kk][tr*8+4];
            float4 b0 = *(const float4*)&Bs[kk][tc*8];
            float4 b1 = *(const float4*)&Bs[kk][tc*8+4];
            float a[8]={a0.x,a0.y,a0.z,a0.w,a1.x,a1.y,a1.z,a1.w};
            float b[8]={b0.x,b0.y,b0.z,b0.w,b1.x,b1.y,b1.z,b1.w};
#pragma unroll
            for(int i=0;i<8;i++)
#pragma unroll
                for(int j=0;j<8;j++) acc[i][j] = fmaf(a[i],b[j],acc[i][j]);
        }
        __syncthreads();
    }
    const float* rt = g_rowt + h*SEQ;
    const float* ct = g_colt + h*SEQ;
    float* Cb = g_C + (size_t)h*SEQ*SEQ;
#pragma unroll
    for (int i=0;i<8;i++){
        int l = l0 + tr*8 + i;
        float rl = rt[l];
#pragma unroll
        for (int j=0;j<8;j++){
            int m = m0 + tc*8 + j;
            float val = 0.f;
            if (m <= l) val = acc[i][j] * 0.0625f * expf(rl + ct[m]);
            Cb[(size_t)l*SEQ + m] = val;
        }
    }
}

// out: hflat[l, h*256+d] = invnorm[h,l] * sum_{m<=l} C[h][l,m]*v[m, h*256+d]
__global__ __launch_bounds__(256, 2) void pav_kernel()
{
    const int h  = blockIdx.z;
    const int l0 = blockIdx.y * BM;
    const int n0 = blockIdx.x * BN;
    const float* A = g_C + (size_t)h*SEQ*SEQ;
    const float* B = g_v + h*DHEAD;
    const int Kmax = l0 + BM;           // causal bound
    __shared__ float As[BK][BM+4];
    __shared__ float Bs[BK][BN+4];
    const int tid = threadIdx.x;
    const int tr = tid & 15;
    const int tc = tid >> 4;
    float acc[8][8];
#pragma unroll
    for (int i=0;i<8;i++)
#pragma unroll
        for (int j=0;j<8;j++) acc[i][j]=0.f;

    for (int k0=0;k0<Kmax;k0+=BK) {
#pragma unroll
        for (int i=0;i<2;i++){
            int idx = i*256 + tid;
            int r = idx>>2, c = (idx&3)<<2;
            float4 av = *(const float4*)(A + (size_t)(l0+r)*SEQ + k0 + c);
            As[c+0][r]=av.x; As[c+1][r]=av.y; As[c+2][r]=av.z; As[c+3][r]=av.w;
            int kk = idx>>5, cc = (idx&31)<<2;
            float4 bv = *(const float4*)(B + (size_t)(k0+kk)*DIN + n0 + cc);
            *(float4*)&Bs[kk][cc] = bv;
        }
        __syncthreads();
#pragma unroll
        for (int kk=0;kk<BK;kk++){
            float4 a0 = *(const float4*)&As[kk][tr*8];
            float4 a1 = *(const float4*)&As[kk][tr*8+4];
            float4 b0 = *(const float4*)&Bs[kk][tc*8];
            float4 b1 = *(const float4*)&Bs[kk][tc*8+4];
            float a[8]={a0.x,a0.y,a0.z,a0.w,a1.x,a1.y,a1.z,a1.w};
            float b[8]={b0.x,b0.y,b0.z,b0.w,b1.x,b1.y,b1.z,b1.w};
#pragma unroll
            for(int i=0;i<8;i++)
#pragma unroll
                for(int j=0;j<8;j++) acc[i][j] = fmaf(a[i],b[j],acc[i][j]);
        }
        __syncthreads();
    }
#pragma unroll
    for (int i=0;i<8;i++){
        int l = l0 + tr*8 + i;
        float sc = g_inrm[h*SEQ + l];
        float* crow = g_hfl + (size_t)l*DIN + h*DHEAD + n0 + tc*8;
#pragma unroll
        for (int j=0;j<8;j++) crow[j] = acc[i][j] * sc;
    }
}

// ---------------- elementwise / reduction kernels ----------------
__global__ void layernorm_kernel(const float* __restrict__ x, const float* __restrict__ w,
                                 float* __restrict__ out, int cols)
{
    int row = blockIdx.x, tid = threadIdx.x;
    const float* xr = x + (size_t)row*cols;
    float s = 0.f, ss = 0.f;
    for (int c = tid; c < cols; c += 256){ float v = xr[c]; s += v; ss += v*v; }
    __shared__ float sh1[256], sh2[256];
    sh1[tid]=s; sh2[tid]=ss; __syncthreads();
    for (int off=128; off>0; off>>=1){
        if (tid < off){ sh1[tid]+=sh1[tid+off]; sh2[tid]+=sh2[tid+off]; }
        __syncthreads();
    }
    float mean = sh1[0] / cols;
    float var  = sh2[0] / cols - mean*mean;
    float rstd = rsqrtf(var + 1e-5f);
    for (int c = tid; c < cols; c += 256)
        out[(size_t)row*cols + c] = (xr[c] - mean) * rstd * w[c];
}

__global__ void conv_silu_kernel(const float* __restrict__ ck, const float* __restrict__ cb)
{
    int idx = blockIdx.x*256 + threadIdx.x;
    if (idx >= SEQ*DIN) return;
    int l = idx / DIN, c = idx % DIN;
    float s = cb[c];
#pragma unroll
    for (int t=0;t<4;t++){
        int ls = l - t;
        if (ls >= 0) s = fmaf(g_proj[(size_t)ls*(2*DIN) + c], ck[c*4 + t], s);
    }
    g_xc[idx] = s / (1.f + expf(-s));
}

__global__ __launch_bounds__(256) void gates_kernel(
    const float* __restrict__ igw, const float* __restrict__ igb,
    const float* __restrict__ fgw, const float* __restrict__ fgb)
{
    __shared__ float buf[3*DIN];
    int l = blockIdx.x, tid = threadIdx.x;
    for (int c = tid; c < DIN; c += 256){
        buf[c]         = g_q[(size_t)l*DIN + c];
        buf[DIN + c]   = g_k[(size_t)l*DIN + c];
        buf[2*DIN + c] = g_v[(size_t)l*DIN + c];
    }
    __syncthreads();
    int w = tid >> 5, lane = tid & 31;
    const float* iw = igw + (size_t)w*3*DIN;
    const float* fw = fgw + (size_t)w*3*DIN;
    float si = 0.f, sf = 0.f;
    for (int j = lane; j < 3*DIN; j += 32){
        float g = buf[j];
        si = fmaf(g, iw[j], si);
        sf = fmaf(g, fw[j], sf);
    }
#pragma unroll
    for (int off=16; off>0; off>>=1){
        si += __shfl_xor_sync(0xffffffffu, si, off);
        sf += __shfl_xor_sync(0xffffffffu, sf, off);
    }
    if (lane == 0){
        g_ig[w*SEQ + l] = si + igb[w];
        g_fg[w*SEQ + l] = sf + fgb[w];
    }
}

__global__ __launch_bounds__(256) void scan_kernel()
{
    __shared__ float lf[SEQ];
    __shared__ float tot[256];
    int h = blockIdx.x, tid = threadIdx.x;
    for (int m = tid; m < SEQ; m += 256){
        float f = g_fg[h*SEQ + m];
        lf[m] = fminf(f, 0.f) - log1pf(expf(-fabsf(f)));   // log_sigmoid
    }
    __syncthreads();
    int base = tid * 8;
    float csl[8];
    float run = 0.f;
#pragma unroll
    for (int j=0;j<8;j++){ run += lf[base+j]; csl[j] = run; }
    tot[tid] = run; __syncthreads();
    for (int off=1; off<256; off<<=1){
        float v = (tid >= off) ? tot[tid-off] : 0.f;
        __syncthreads();
        tot[tid] += v;
        __syncthreads();
    }
    float excl = tot[tid] - run;
    float cs[8], cml[8];
    float rmax = -INFINITY;
#pragma unroll
    for (int j=0;j<8;j++){
        cs[j] = csl[j] + excl;                       // cs[m+1]
        float col = g_ig[h*SEQ + base + j] - cs[j];  // ig[m]-cs[m+1]
        g_colt[h*SEQ + base + j] = col;
        rmax = fmaxf(rmax, col);
        cml[j] = rmax;
    }
    tot[tid] = rmax; __syncthreads();
    for (int off=1; off<256; off<<=1){
        float v = (tid >= off) ? tot[tid-off] : -INFINITY;
        __syncthreads();
        tot[tid] = fmaxf(tot[tid], v);
        __syncthreads();
    }
    float em = (tid > 0) ? tot[tid-1] : -INFINITY;
#pragma unroll
    for (int j=0;j<8;j++){
        float rm = fmaxf(em, cml[j]);                // prefix max up to l
        g_rowt[h*SEQ + base + j] = -rm;              // cs[l+1]-max_log_D[l] = -rm
        g_expn[h*SEQ + base + j] = expf(-(cs[j] + rm));  // exp(-max_log_D[l])
    }
}

__global__ void norm_kernel()
{
    int l = blockIdx.x, h = blockIdx.y, tid = threadIdx.x;
    const float* row = g_C + ((size_t)h*SEQ + l)*SEQ;
    float s = 0.f;
    for (int m = tid; m <= l; m += 256) s += row[m];
    __shared__ float sh[256];
    sh[tid] = s; __syncthreads();
    for (int off=128; off>0; off>>=1){
        if (tid < off) sh[tid] += sh[tid+off];
        __syncthreads();
    }
    if (tid == 0){
        float n = fmaxf(fabsf(sh[0]), g_expn[h*SEQ + l]) + 1e-6f;
        g_inrm[h*SEQ + l] = 1.0f / n;
    }
}

__global__ __launch_bounds__(256) void gn_kernel(const float* __restrict__ gnw,
    const float* __restrict__ gnb, const float* __restrict__ skip)
{
    int l = blockIdx.x, tid = threadIdx.x, w = tid >> 5, lane = tid & 31;
    const float* hrow = g_hfl + (size_t)l*DIN + w*DHEAD;
    float vals[8]; float s = 0.f, ss = 0.f;
#pragma unroll
    for (int k2=0;k2<8;k2++){ float v = hrow[lane + k2*32]; vals[k2]=v; s+=v; ss+=v*v; }
#pragma unroll
    for (int off=16; off>0; off>>=1){
        s  += __shfl_xor_sync(0xffffffffu, s,  off);
        ss += __shfl_xor_sync(0xffffffffu, ss, off);
    }
    float mean = s * (1.f/DHEAD);
    float var  = ss * (1.f/DHEAD) - mean*mean;
    float rstd = rsqrtf(var + 1e-5f);
#pragma unroll
    for (int k2=0;k2<8;k2++){
        int c = w*DHEAD + lane + k2*32;
        float hn = (vals[k2] - mean) * rstd;
        float h2 = hn*gnw[c] + gnb[c] + skip[c]*g_xc[(size_t)l*DIN + c];
        float r  = g_proj[(size_t)l*(2*DIN) + DIN + c];
        float sl = r / (1.f + expf(-r));
        g_yin[(size_t)l*DIN + c] = h2 * sl;
    }
}

__global__ void gelu_kernel()
{
    int idx = blockIdx.x*256 + threadIdx.x;
    if (idx >= SEQ*DHID) return;
    int l = idx / DHID, j = idx % DHID;
    float a = g_p[(size_t)l*(2*DHID) + j];
    float z = g_p[(size_t)l*(2*DHID) + DHID + j];
    float t = tanhf(0.7978845608028654f * (a + 0.044715f*a*a*a));
    g_g2[idx] = 0.5f * a * (1.f + t) * z;
}

// ---------------- launch ----------------
extern "C" void kernel_launch(void* const* d_in, const int* in_sizes, int n_in,
                              void* d_out, int out_size)
{
    (void)in_sizes; (void)n_in; (void)out_size;
    const float* x    = (const float*)d_in[0];
    // d_in[1] = mask (tril, implicit)
    const float* ln1w = (const float*)d_in[2];
    const float* winw = (const float*)d_in[3];
    const float* winb = (const float*)d_in[4];
    const float* woutw= (const float*)d_in[5];
    const float* ck   = (const float*)d_in[6];
    const float* cb   = (const float*)d_in[7];
    const float* wq   = (const float*)d_in[8];
    const float* wk   = (const float*)d_in[9];
    const float* wv   = (const float*)d_in[10];
    const float* igw  = (const float*)d_in[11];
    const float* igb  = (const float*)d_in[12];
    const float* fgw  = (const float*)d_in[13];
    const float* fgb  = (const float*)d_in[14];
    const float* gnw  = (const float*)d_in[15];
    const float* gnb  = (const float*)d_in[16];
    const float* skip = (const float*)d_in[17];
    const float* ln2w = (const float*)d_in[18];
    const float* ffnw = (const float*)d_in[19];
    const float* ffnow= (const float*)d_in[20];
    float* out = (float*)d_out;

    float *hln,*proj,*xc,*q,*k,*v,*yin,*x2,*hf,*p,*g2;
    cudaGetSymbolAddress((void**)&hln,  g_hln);
    cudaGetSymbolAddress((void**)&proj, g_proj);
    cudaGetSymbolAddress((void**)&xc,   g_xc);
    cudaGetSymbolAddress((void**)&q,    g_q);
    cudaGetSymbolAddress((void**)&k,    g_k);
    cudaGetSymbolAddress((void**)&v,    g_v);
    cudaGetSymbolAddress((void**)&yin,  g_yin);
    cudaGetSymbolAddress((void**)&x2,   g_x2);
    cudaGetSymbolAddress((void**)&hf,   g_hf);
    cudaGetSymbolAddress((void**)&p,    g_p);
    cudaGetSymbolAddress((void**)&g2,   g_g2);

    // 1. h = LN(x)
    layernorm_kernel<<<SEQ, 256>>>(x, ln1w, hln, DMOD);
    // 2. proj = h @ win_w^T + win_b     [2048,4096]
    sgemm_nt<<<dim3(4096/BN, SEQ/BM), 256>>>(hln, winw, winb, 0, proj, DMOD, DMOD, DMOD, 2*DIN, 0);
    // 3. xc = silu(causal_conv(xi))
    conv_silu_kernel<<<SEQ*DIN/256, 256>>>(ck, cb);
    // 4. q/k from xc, v from xi (per-head 256x256 linear)
    sgemm_nn_b<<<dim3(DHEAD/BN, SEQ/BM, NHEAD), 256>>>(xc,   wq, q, DHEAD, DIN,   DHEAD, DIN, DHEAD, (long long)DHEAD*DHEAD, DHEAD);
    sgemm_nn_b<<<dim3(DHEAD/BN, SEQ/BM, NHEAD), 256>>>(xc,   wk, k, DHEAD, DIN,   DHEAD, DIN, DHEAD, (long long)DHEAD*DHEAD, DHEAD);
    sgemm_nn_b<<<dim3(DHEAD/BN, SEQ/BM, NHEAD), 256>>>(proj, wv, v, DHEAD, 2*DIN, DHEAD, DIN, DHEAD, (long long)DHEAD*DHEAD, DHEAD);
    // 5. input/forget gates
    gates_kernel<<<SEQ, 256>>>(igw, igb, fgw, fgb);
    // 6. per-head scans: colterm / rowterm / exp(-max_log_D)
    scan_kernel<<<NHEAD, 256>>>();
    // 7. C = (QK^T/16) * D   (causal, tile-skipped)
    score_kernel<<<dim3(SEQ/BN, SEQ/BM, NHEAD), 256>>>();
    // 8. row sums -> 1/(norm+1e-6)
    norm_kernel<<<dim3(SEQ, NHEAD), 256>>>();
    // 9. hflat = (C * invnorm) @ V
    pav_kernel<<<dim3(DHEAD/BN, SEQ/BM, NHEAD), 256>>>();
    // 10. group norm + skip*xc, then * silu(res)
    gn_kernel<<<SEQ, 256>>>(gnw, gnb, skip);
    // 11. x2 = x + yin @ wout_w^T
    sgemm_nt<<<dim3(DMOD/BN, SEQ/BM), 256>>>(yin, woutw, 0, x, x2, DIN, DIN, DIN, DMOD, DMOD);
    // 12. hf = LN(x2)
    layernorm_kernel<<<SEQ, 256>>>(x2, ln2w, hf, DMOD);
    // 13. p = hf @ ffn_win_w^T   [2048,4096]
    sgemm_nt<<<dim3(4096/BN, SEQ/BM), 256>>>(hf, ffnw, 0, 0, p, DMOD, DMOD, DMOD, 2*DHID, 0);
    // 14. g2 = gelu(a)*z
    gelu_kernel<<<SEQ*DHID/256, 256>>>();
    // 15. out = x2 + g2 @ ffn_wout_w^T
    sgemm_nt<<<dim3(DMOD/BN, SEQ/BM), 256>>>(g2, ffnow, 0, x2, out, DHID, DHID, DHID, DMOD, DMOD);
}

// round 2
// speedup vs baseline: 2.5416x; 2.5416x over previous
#include <cuda_runtime.h>
#include <math.h>

#define SEQ   2048
#define DMOD  1024
#define DIN   2048
#define NHEAD 8
#define DHEAD 256
#define DHID  2048

// ---------------- scratch (allocation-free: __device__ globals) ----------------
__device__ float g_hln [SEQ*DMOD];
__device__ float g_proj[SEQ*2*DIN];
__device__ float g_xc  [SEQ*DIN];
__device__ float g_q   [SEQ*DIN];
__device__ float g_k   [SEQ*DIN];
__device__ float g_v   [SEQ*DIN];
__device__ float g_ig  [NHEAD*SEQ];
__device__ float g_fg  [NHEAD*SEQ];
__device__ float g_rowt[NHEAD*SEQ];
__device__ float g_colt[NHEAD*SEQ];
__device__ float g_expn[NHEAD*SEQ];
__device__ float g_inrm[NHEAD*SEQ];
__device__ float g_C   [(size_t)NHEAD*SEQ*SEQ];
__device__ float g_hfl [SEQ*DIN];
__device__ float g_yin [SEQ*DIN];
__device__ float g_x2  [SEQ*DMOD];
__device__ float g_hf  [SEQ*DMOD];
__device__ float g_p   [SEQ*2*DHID];
__device__ float g_g2  [SEQ*DHID];

// ---------------- TF32 MMA tile config ----------------
#define BM 128
#define BN 128
#define BK 32
#define LDS_PAD 36   // words per row in staged smem (conflict-free for frag gathers)

__device__ __forceinline__ unsigned f2tf(float x){
    unsigned u; asm("cvt.rna.tf32.f32 %0, %1;" : "=r"(u) : "f"(x)); return u;
}

#define MMA_TF32(d, a, b) \
  asm volatile("mma.sync.aligned.m16n8k8.row.col.f32.tf32.tf32.f32 " \
    "{%0,%1,%2,%3},{%4,%5,%6,%7},{%8,%9},{%0,%1,%2,%3};" \
    : "+f"((d)[0]),"+f"((d)[1]),"+f"((d)[2]),"+f"((d)[3]) \
    : "r"((a)[0]),"r"((a)[1]),"r"((a)[2]),"r"((a)[3]),"r"((b)[0]),"r"((b)[1]))

// stage a 128x32 tile from row-major src[row][k] (ld) into S[row][k] (LDS_PAD)
__device__ __forceinline__ void stage_rowmajor(const float* __restrict__ src, int ld,
      int row0, int k0, unsigned* S, int tid)
{
#pragma unroll
    for (int it=0; it<4; it++){
        int idx = it*256 + tid;
        int r = idx>>3, cc = (idx&7)*4;
        float4 v = *(const float4*)(src + (size_t)(row0+r)*ld + k0 + cc);
        uint4 u; u.x=f2tf(v.x); u.y=f2tf(v.y); u.z=f2tf(v.z); u.w=f2tf(v.w);
        *(uint4*)(S + r*LDS_PAD + cc) = u;
    }
}

// stage a 32x128 tile from src[k][n] (ld) into S[n][k]
__device__ __forceinline__ void stage_colmajor(const float* __restrict__ src, int ld,
      int n0, int k0, unsigned* S, int tid)
{
#pragma unroll
    for (int it=0; it<4; it++){
        int idx = it*256 + tid;
        int kk = idx & 31, cc = (idx>>5)*4;
        float4 v = *(const float4*)(src + (size_t)(k0+kk)*ld + n0 + cc);
        S[(cc+0)*LDS_PAD + kk] = f2tf(v.x);
        S[(cc+1)*LDS_PAD + kk] = f2tf(v.y);
        S[(cc+2)*LDS_PAD + kk] = f2tf(v.z);
        S[(cc+3)*LDS_PAD + kk] = f2tf(v.w);
    }
}

__device__ __forceinline__ void compute_tile(const unsigned* __restrict__ As,
    const unsigned* __restrict__ Bs, float acc[4][4][4], int lane, int wm, int wn)
{
    const int gr = lane>>2, gc = lane&3;
#pragma unroll
    for (int kk=0;kk<4;kk++){
        const int k8 = kk*8;
        unsigned a[4][4], b[4][2];
#pragma unroll
        for (int mt=0;mt<4;mt++){
            const unsigned* p = As + (wm + mt*16 + gr)*LDS_PAD + k8 + gc;
            a[mt][0]=p[0]; a[mt][1]=p[8*LDS_PAD]; a[mt][2]=p[4]; a[mt][3]=p[8*LDS_PAD+4];
        }
#pragma unroll
        for (int nt=0;nt<4;nt++){
            const unsigned* p = Bs + (wn + nt*8 + gr)*LDS_PAD + k8 + gc;
            b[nt][0]=p[0]; b[nt][1]=p[4];
        }
#pragma unroll
        for (int mt=0;mt<4;mt++)
#pragma unroll
            for (int nt=0;nt<4;nt++)
                MMA_TF32(acc[mt][nt], a[mt], b[nt]);
    }
}

// ---------------- GEMM kernels (TF32 tensor-core) ----------------

// C[m,n] = sum_k A[m,k]*B[n,k] (+bias[n]) (+resid[m,n])
__global__ __launch_bounds__(256) void mma_nt(
    const float* __restrict__ A, const float* __restrict__ B,
    const float* __restrict__ bias, const float* __restrict__ resid,
    float* __restrict__ C, int K, int lda, int ldb, int ldc, int ldr)
{
    __shared__ unsigned As[BM*LDS_PAD], Bs[BN*LDS_PAD];
    const int tid=threadIdx.x, lane=tid&31, wid=tid>>5;
    const int wm=(wid>>2)*64, wn=(wid&3)*32;
    const int m0=blockIdx.y*BM, n0=blockIdx.x*BN;
    float acc[4][4][4] = {};
    for (int k0=0;k0<K;k0+=BK){
        stage_rowmajor(A, lda, m0, k0, As, tid);
        stage_rowmajor(B, ldb, n0, k0, Bs, tid);
        __syncthreads();
        compute_tile(As,Bs,acc,lane,wm,wn);
        __syncthreads();
    }
    const int gr=lane>>2, gc=lane&3;
#pragma unroll
    for (int mt=0;mt<4;mt++){
#pragma unroll
        for (int nt=0;nt<4;nt++){
            int row = m0+wm+mt*16+gr;
            int col = n0+wn+nt*8+gc*2;
            float b0=0.f,b1=0.f;
            if (bias){ b0=bias[col]; b1=bias[col+1]; }
            float r00=0,r01=0,r10=0,r11=0;
            if (resid){
                const float* rp  = resid + (size_t)row*ldr + col;
                const float* rp2 = resid + (size_t)(row+8)*ldr + col;
                r00=rp[0]; r01=rp[1]; r10=rp2[0]; r11=rp2[1];
            }
            float2 v0 = {acc[mt][nt][0]+b0+r00, acc[mt][nt][1]+b1+r01};
            float2 v1 = {acc[mt][nt][2]+b0+r10, acc[mt][nt][3]+b1+r11};
            *(float2*)(C + (size_t)row*ldc + col) = v0;
            *(float2*)(C + (size_t)(row+8)*ldc + col) = v1;
        }
    }
}

// batched NN: C[b][m,n] = sum_k A[b][m,k]*B[b][k,n]
__global__ __launch_bounds__(256) void mma_nn_b(
    const float* __restrict__ A, const float* __restrict__ B, float* __restrict__ C,
    int K, int lda, int ldb, int ldc, long long sA, long long sB, long long sC)
{
    A += (long long)blockIdx.z * sA;
    B += (long long)blockIdx.z * sB;
    C += (long long)blockIdx.z * sC;
    __shared__ unsigned As[BM*LDS_PAD], Bs[BN*LDS_PAD];
    const int tid=threadIdx.x, lane=tid&31, wid=tid>>5;
    const int wm=(wid>>2)*64, wn=(wid&3)*32;
    const int m0=blockIdx.y*BM, n0=blockIdx.x*BN;
    float acc[4][4][4] = {};
    for (int k0=0;k0<K;k0+=BK){
        stage_rowmajor(A, lda, m0, k0, As, tid);
        stage_colmajor(B, ldb, n0, k0, Bs, tid);
        __syncthreads();
        compute_tile(As,Bs,acc,lane,wm,wn);
        __syncthreads();
    }
    const int gr=lane>>2, gc=lane&3;
#pragma unroll
    for (int mt=0;mt<4;mt++){
#pragma unroll
        for (int nt=0;nt<4;nt++){
            int row = m0+wm+mt*16+gr;
            int col = n0+wn+nt*8+gc*2;
            *(float2*)(C + (size_t)row*ldc + col)     = make_float2(acc[mt][nt][0], acc[mt][nt][1]);
            *(float2*)(C + (size_t)(row+8)*ldc + col) = make_float2(acc[mt][nt][2], acc[mt][nt][3]);
        }
    }
}

// scores: C[h][l,m] = (q_h[l]·k_h[m])/16 * exp(rowt[l]+colt[m]) for m<=l else 0
__global__ __launch_bounds__(256) void mma_score()
{
    const int h  = blockIdx.z;
    const int l0 = blockIdx.y * BM;
    const int m0 = blockIdx.x * BN;
    if (m0 >= l0 + BM) return;   // fully-masked tile: skipped (never read downstream)
    const float* A = g_q + h*DHEAD;
    const float* B = g_k + h*DHEAD;
    __shared__ unsigned As[BM*LDS_PAD], Bs[BN*LDS_PAD];
    const int tid=threadIdx.x, lane=tid&31, wid=tid>>5;
    const int wm=(wid>>2)*64, wn=(wid&3)*32;
    float acc[4][4][4] = {};
    for (int k0=0;k0<DHEAD;k0+=BK){
        stage_rowmajor(A, DIN, l0, k0, As, tid);
        stage_rowmajor(B, DIN, m0, k0, Bs, tid);
        __syncthreads();
        compute_tile(As,Bs,acc,lane,wm,wn);
        __syncthreads();
    }
    const float* rt = g_rowt + h*SEQ;
    const float* ct = g_colt + h*SEQ;
    float* Cb = g_C + (size_t)h*SEQ*SEQ;
    const int gr=lane>>2, gc=lane&3;
#pragma unroll
    for (int mt=0;mt<4;mt++){
#pragma unroll
        for (int nt=0;nt<4;nt++){
            int l = l0+wm+mt*16+gr;
            int m = m0+wn+nt*8+gc*2;
            float rl0 = rt[l], rl1 = rt[l+8];
            float cm0 = ct[m], cm1 = ct[m+1];
            float v00 = (m   <= l  ) ? acc[mt][nt][0]*0.0625f*expf(rl0+cm0) : 0.f;
            float v01 = (m+1 <= l  ) ? acc[mt][nt][1]*0.0625f*expf(rl0+cm1) : 0.f;
            float v10 = (m   <= l+8) ? acc[mt][nt][2]*0.0625f*expf(rl1+cm0) : 0.f;
            float v11 = (m+1 <= l+8) ? acc[mt][nt][3]*0.0625f*expf(rl1+cm1) : 0.f;
            *(float2*)(Cb + (size_t)l*SEQ + m)     = make_float2(v00, v01);
            *(float2*)(Cb + (size_t)(l+8)*SEQ + m) = make_float2(v10, v11);
        }
    }
}

// hflat[l, h*256+d] = invnorm[h,l] * sum_{m<=l} C[h][l,m]*v[m, h*256+d]
__global__ __launch_bounds__(256) void mma_pav()
{
    const int h  = blockIdx.z;
    const int l0 = blockIdx.y * BM;
    const int n0 = blockIdx.x * BN;
    const float* A = g_C + (size_t)h*SEQ*SEQ;
    const float* B = g_v + h*DHEAD;
    const int Kmax = l0 + BM;   // causal bound
    __shared__ unsigned As[BM*LDS_PAD], Bs[BN*LDS_PAD];
    const int tid=threadIdx.x, lane=tid&31, wid=tid>>5;
    const int wm=(wid>>2)*64, wn=(wid&3)*32;
    float acc[4][4][4] = {};
    for (int k0=0;k0<Kmax;k0+=BK){
        stage_rowmajor(A, SEQ, l0, k0, As, tid);
        stage_colmajor(B, DIN, n0, k0, Bs, tid);
        __syncthreads();
        compute_tile(As,Bs,acc,lane,wm,wn);
        __syncthreads();
    }
    const int gr=lane>>2, gc=lane&3;
#pragma unroll
    for (int mt=0;mt<4;mt++){
#pragma unroll
        for (int nt=0;nt<4;nt++){
            int l = l0+wm+mt*16+gr;
            int col = n0+wn+nt*8+gc*2;
            float s0 = g_inrm[h*SEQ + l];
            float s1 = g_inrm[h*SEQ + l + 8];
            float* c0 = g_hfl + (size_t)l*DIN + h*DHEAD + col;
            float* c1 = g_hfl + (size_t)(l+8)*DIN + h*DHEAD + col;
            *(float2*)c0 = make_float2(acc[mt][nt][0]*s0, acc[mt][nt][1]*s0);
            *(float2*)c1 = make_float2(acc[mt][nt][2]*s1, acc[mt][nt][3]*s1);
        }
    }
}

// ---------------- elementwise / reduction kernels ----------------
__global__ void layernorm_kernel(const float* __restrict__ x, const float* __restrict__ w,
                                 float* __restrict__ out, int cols)
{
    int row = blockIdx.x, tid = threadIdx.x;
    const float* xr = x + (size_t)row*cols;
    float s = 0.f, ss = 0.f;
    for (int c = tid; c < cols; c += 256){ float v = xr[c]; s += v; ss += v*v; }
    __shared__ float sh1[256], sh2[256];
    sh1[tid]=s; sh2[tid]=ss; __syncthreads();
    for (int off=128; off>0; off>>=1){
        if (tid < off){ sh1[tid]+=sh1[tid+off]; sh2[tid]+=sh2[tid+off]; }
        __syncthreads();
    }
    float mean = sh1[0] / cols;
    float var  = sh2[0] / cols - mean*mean;
    float rstd = rsqrtf(var + 1e-5f);
    for (int c = tid; c < cols; c += 256)
        out[(size_t)row*cols + c] = (xr[c] - mean) * rstd * w[c];
}

__global__ void conv_silu_kernel(const float* __restrict__ ck, const float* __restrict__ cb)
{
    int idx = blockIdx.x*256 + threadIdx.x;
    if (idx >= SEQ*DIN) return;
    int l = idx / DIN, c = idx % DIN;
    float s = cb[c];
#pragma unroll
    for (int t=0;t<4;t++){
        int ls = l - t;
        if (ls >= 0) s = fmaf(g_proj[(size_t)ls*(2*DIN) + c], ck[c*4 + t], s);
    }
    g_xc[idx] = s / (1.f + expf(-s));
}

// 2 rows per block; each warp handles one head's (ig, fg) for both rows
__global__ __launch_bounds__(256) void gates_kernel(
    const float* __restrict__ igw, const float* __restrict__ igb,
    const float* __restrict__ fgw, const float* __restrict__ fgb)
{
    __shared__ float buf[2*3*DIN];   // 48KB
    int l0 = blockIdx.x*2, tid = threadIdx.x;
    for (int c = tid; c < DIN; c += 256){
#pragma unroll
        for (int rr=0; rr<2; rr++){
            buf[rr*3*DIN + c]         = g_q[(size_t)(l0+rr)*DIN + c];
            buf[rr*3*DIN + DIN + c]   = g_k[(size_t)(l0+rr)*DIN + c];
            buf[rr*3*DIN + 2*DIN + c] = g_v[(size_t)(l0+rr)*DIN + c];
        }
    }
    __syncthreads();
    int w = tid >> 5, lane = tid & 31;
    const float* iw = igw + (size_t)w*3*DIN;
    const float* fw = fgw + (size_t)w*3*DIN;
    float si0=0.f, sf0=0.f, si1=0.f, sf1=0.f;
    for (int j = lane; j < 3*DIN; j += 32){
        float wi = iw[j], wf = fw[j];
        float g0 = buf[j], g1 = buf[3*DIN + j];
        si0 = fmaf(g0, wi, si0); si1 = fmaf(g1, wi, si1);
        sf0 = fmaf(g0, wf, sf0); sf1 = fmaf(g1, wf, sf1);
    }
#pragma unroll
    for (int off=16; off>0; off>>=1){
        si0 += __shfl_xor_sync(0xffffffffu, si0, off);
        sf0 += __shfl_xor_sync(0xffffffffu, sf0, off);
        si1 += __shfl_xor_sync(0xffffffffu, si1, off);
        sf1 += __shfl_xor_sync(0xffffffffu, sf1, off);
    }
    if (lane == 0){
        g_ig[w*SEQ + l0]   = si0 + igb[w];
        g_fg[w*SEQ + l0]   = sf0 + fgb[w];
        g_ig[w*SEQ + l0+1] = si1 + igb[w];
        g_fg[w*SEQ + l0+1] = sf1 + fgb[w];
    }
}

__global__ __launch_bounds__(256) void scan_kernel()
{
    __shared__ float lf[SEQ];
    __shared__ float tot[256];
    int h = blockIdx.x, tid = threadIdx.x;
    for (int m = tid; m < SEQ; m += 256){
        float f = g_fg[h*SEQ + m];
        lf[m] = fminf(f, 0.f) - log1pf(expf(-fabsf(f)));   // log_sigmoid
    }
    __syncthreads();
    int base = tid * 8;
    float csl[8];
    float run = 0.f;
#pragma unroll
    for (int j=0;j<8;j++){ run += lf[base+j]; csl[j] = run; }
    tot[tid] = run; __syncthreads();
    for (int off=1; off<256; off<<=1){
        float v = (tid >= off) ? tot[tid-off] : 0.f;
        __syncthreads();
        tot[tid] += v;
        __syncthreads();
    }
    float excl = tot[tid] - run;
    float cs[8], cml[8];
    float rmax = -INFINITY;
#pragma unroll
    for (int j=0;j<8;j++){
        cs[j] = csl[j] + excl;                       // cs[m+1]
        float col = g_ig[h*SEQ + base + j] - cs[j];  // ig[m]-cs[m+1]
        g_colt[h*SEQ + base + j] = col;
        rmax = fmaxf(rmax, col);
        cml[j] = rmax;
    }
    tot[tid] = rmax; __syncthreads();
    for (int off=1; off<256; off<<=1){
        float v = (tid >= off) ? tot[tid-off] : -INFINITY;
        __syncthreads();
        tot[tid] = fmaxf(tot[tid], v);
        __syncthreads();
    }
    float em = (tid > 0) ? tot[tid-1] : -INFINITY;
#pragma unroll
    for (int j=0;j<8;j++){
        float rm = fmaxf(em, cml[j]);                // prefix max up to l
        g_rowt[h*SEQ + base + j] = -rm;              // cs[l+1]-max_log_D[l] = -rm
        g_expn[h*SEQ + base + j] = expf(-(cs[j] + rm));  // exp(-max_log_D[l])
    }
}

__global__ void norm_kernel()
{
    int l = blockIdx.x, h = blockIdx.y, tid = threadIdx.x;
    const float* row = g_C + ((size_t)h*SEQ + l)*SEQ;
    float s = 0.f;
    for (int m = tid; m <= l; m += 256) s += row[m];
    __shared__ float sh[256];
    sh[tid] = s; __syncthreads();
    for (int off=128; off>0; off>>=1){
        if (tid < off) sh[tid] += sh[tid+off];
        __syncthreads();
    }
    if (tid == 0){
        float n = fmaxf(fabsf(sh[0]), g_expn[h*SEQ + l]) + 1e-6f;
        g_inrm[h*SEQ + l] = 1.0f / n;
    }
}

__global__ __launch_bounds__(256) void gn_kernel(const float* __restrict__ gnw,
    const float* __restrict__ gnb, const float* __restrict__ skip)
{
    int l = blockIdx.x, tid = threadIdx.x, w = tid >> 5, lane = tid & 31;
    const float* hrow = g_hfl + (size_t)l*DIN + w*DHEAD;
    float vals[8]; float s = 0.f, ss = 0.f;
#pragma unroll
    for (int k2=0;k2<8;k2++){ float v = hrow[lane + k2*32]; vals[k2]=v; s+=v; ss+=v*v; }
#pragma unroll
    for (int off=16; off>0; off>>=1){
        s  += __shfl_xor_sync(0xffffffffu, s,  off);
        ss += __shfl_xor_sync(0xffffffffu, ss, off);
    }
    float mean = s * (1.f/DHEAD);
    float var  = ss * (1.f/DHEAD) - mean*mean;
    float rstd = rsqrtf(var + 1e-5f);
#pragma unroll
    for (int k2=0;k2<8;k2++){
        int c = w*DHEAD + lane + k2*32;
        float hn = (vals[k2] - mean) * rstd;
        float h2 = hn*gnw[c] + gnb[c] + skip[c]*g_xc[(size_t)l*DIN + c];
        float r  = g_proj[(size_t)l*(2*DIN) + DIN + c];
        float sl = r / (1.f + expf(-r));
        g_yin[(size_t)l*DIN + c] = h2 * sl;
    }
}

__global__ void gelu_kernel()
{
    int idx = blockIdx.x*256 + threadIdx.x;
    if (idx >= SEQ*DHID) return;
    int l = idx / DHID, j = idx % DHID;
    float a = g_p[(size_t)l*(2*DHID) + j];
    float z = g_p[(size_t)l*(2*DHID) + DHID + j];
    float t = tanhf(0.7978845608028654f * (a + 0.044715f*a*a*a));
    g_g2[idx] = 0.5f * a * (1.f + t) * z;
}

// ---------------- launch ----------------
extern "C" void kernel_launch(void* const* d_in, const int* in_sizes, int n_in,
                              void* d_out, int out_size)
{
    (void)in_sizes; (void)n_in; (void)out_size;
    const float* x    = (const float*)d_in[0];
    // d_in[1] = mask (tril, implicit)
    const float* ln1w = (const float*)d_in[2];
    const float* winw = (const float*)d_in[3];
    const float* winb = (const float*)d_in[4];
    const float* woutw= (const float*)d_in[5];
    const float* ck   = (const float*)d_in[6];
    const float* cb   = (const float*)d_in[7];
    const float* wq   = (const float*)d_in[8];
    const float* wk   = (const float*)d_in[9];
    const float* wv   = (const float*)d_in[10];
    const float* igw  = (const float*)d_in[11];
    const float* igb  = (const float*)d_in[12];
    const float* fgw  = (const float*)d_in[13];
    const float* fgb  = (const float*)d_in[14];
    const float* gnw  = (const float*)d_in[15];
    const float* gnb  = (const float*)d_in[16];
    const float* skip = (const float*)d_in[17];
    const float* ln2w = (const float*)d_in[18];
    const float* ffnw = (const float*)d_in[19];
    const float* ffnow= (const float*)d_in[20];
    float* out = (float*)d_out;

    float *hln,*proj,*xc,*q,*k,*v,*yin,*x2,*hf,*p,*g2;
    cudaGetSymbolAddress((void**)&hln,  g_hln);
    cudaGetSymbolAddress((void**)&proj, g_proj);
    cudaGetSymbolAddress((void**)&xc,   g_xc);
    cudaGetSymbolAddress((void**)&q,    g_q);
    cudaGetSymbolAddress((void**)&k,    g_k);
    cudaGetSymbolAddress((void**)&v,    g_v);
    cudaGetSymbolAddress((void**)&yin,  g_yin);
    cudaGetSymbolAddress((void**)&x2,   g_x2);
    cudaGetSymbolAddress((void**)&hf,   g_hf);
    cudaGetSymbolAddress((void**)&p,    g_p);
    cudaGetSymbolAddress((void**)&g2,   g_g2);

    // 1. h = LN(x)
    layernorm_kernel<<<SEQ, 256>>>(x, ln1w, hln, DMOD);
    // 2. proj = h @ win_w^T + win_b     [2048,4096]
    mma_nt<<<dim3(4096/BN, SEQ/BM), 256>>>(hln, winw, winb, 0, proj, DMOD, DMOD, DMOD, 2*DIN, 0);
    // 3. xc = silu(causal_conv(xi))
    conv_silu_kernel<<<SEQ*DIN/256, 256>>>(ck, cb);
    // 4. q/k from xc, v from xi (per-head 256x256 linear)
    mma_nn_b<<<dim3(DHEAD/BN, SEQ/BM, NHEAD), 256>>>(xc,   wq, q, DHEAD, DIN,   DHEAD, DIN, DHEAD, (long long)DHEAD*DHEAD, DHEAD);
    mma_nn_b<<<dim3(DHEAD/BN, SEQ/BM, NHEAD), 256>>>(xc,   wk, k, DHEAD, DIN,   DHEAD, DIN, DHEAD, (long long)DHEAD*DHEAD, DHEAD);
    mma_nn_b<<<dim3(DHEAD/BN, SEQ/BM, NHEAD), 256>>>(proj, wv, v, DHEAD, 2*DIN, DHEAD, DIN, DHEAD, (long long)DHEAD*DHEAD, DHEAD);
    // 5. input/forget gates
    gates_kernel<<<SEQ/2, 256>>>(igw, igb, fgw, fgb);
    // 6. per-head scans: colterm / rowterm / exp(-max_log_D)
    scan_kernel<<<NHEAD, 256>>>();
    // 7. C = (QK^T/16) * D   (causal, tile-skipped)
    mma_score<<<dim3(SEQ/BN, SEQ/BM, NHEAD), 256>>>();
    // 8. row sums -> 1/(norm+1e-6)
    norm_kernel<<<dim3(SEQ, NHEAD), 256>>>();
    // 9. hflat = (C * invnorm) @ V
    mma_pav<<<dim3(DHEAD/BN, SEQ/BM, NHEAD), 256>>>();
    // 10. group norm + skip*xc, then * silu(res)
    gn_kernel<<<SEQ, 256>>>(gnw, gnb, skip);
    // 11. x2 = x + yin @ wout_w^T
    mma_nt<<<dim3(DMOD/BN, SEQ/BM), 256>>>(yin, woutw, 0, x, x2, DIN, DIN, DIN, DMOD, DMOD);
    // 12. hf = LN(x2)
    layernorm_kernel<<<SEQ, 256>>>(x2, ln2w, hf, DMOD);
    // 13. p = hf @ ffn_win_w^T   [2048,4096]
    mma_nt<<<dim3(4096/BN, SEQ/BM), 256>>>(hf, ffnw, 0, 0, p, DMOD, DMOD, DMOD, 2*DHID, 0);
    // 14. g2 = gelu(a)*z
    gelu_kernel<<<SEQ*DHID/256, 256>>>();
    // 15. out = x2 + g2 @ ffn_wout_w^T
    mma_nt<<<dim3(DMOD/BN, SEQ/BM), 256>>>(g2, ffnow, 0, x2, out, DHID, DHID, DHID, DMOD, DMOD);
}

// round 3
// speedup vs baseline: 3.1439x; 1.2370x over previous
#include <cuda_runtime.h>
#include <math.h>

#define SEQ   2048
#define DMOD  1024
#define DIN   2048
#define NHEAD 8
#define DHEAD 256
#define DHID  2048

// ---------------- scratch (allocation-free: __device__ globals) ----------------
__device__ float g_hln [SEQ*DMOD];
__device__ float g_proj[SEQ*2*DIN];
__device__ float g_xc  [SEQ*DIN];
__device__ float g_q   [SEQ*DIN];
__device__ float g_k   [SEQ*DIN];
__device__ float g_v   [SEQ*DIN];
__device__ float g_vt  [(size_t)NHEAD*DHEAD*SEQ];
__device__ float g_wqt [NHEAD*DHEAD*DHEAD];
__device__ float g_wkt [NHEAD*DHEAD*DHEAD];
__device__ float g_wvt [NHEAD*DHEAD*DHEAD];
__device__ float g_ig  [NHEAD*SEQ];
__device__ float g_fg  [NHEAD*SEQ];
__device__ float g_rowt[NHEAD*SEQ];
__device__ float g_colt[NHEAD*SEQ];
__device__ float g_expn[NHEAD*SEQ];
__device__ float g_inrm[NHEAD*SEQ];
__device__ float g_C   [(size_t)NHEAD*SEQ*SEQ];
__device__ float g_hfl [SEQ*DIN];
__device__ float g_yin [SEQ*DIN];
__device__ float g_x2  [SEQ*DMOD];
__device__ float g_hf  [SEQ*DMOD];
__device__ float g_p   [SEQ*2*DHID];
__device__ float g_g2  [SEQ*DHID];

// ---------------- TF32 MMA tile config ----------------
#define BM 128
#define BN 128
#define BK 32
#define LDS_PAD 36
#define TILE_W (BM*LDS_PAD)        // words per staged tile (4608)
#define SMEM_BYTES (4*TILE_W*4)    // 2 buffers x (A+B) = 73728 B

#define MMA_TF32(d, a, b) \
  asm volatile("mma.sync.aligned.m16n8k8.row.col.f32.tf32.tf32.f32 " \
    "{%0,%1,%2,%3},{%4,%5,%6,%7},{%8,%9},{%0,%1,%2,%3};" \
    : "+f"((d)[0]),"+f"((d)[1]),"+f"((d)[2]),"+f"((d)[3]) \
    : "r"((a)[0]),"r"((a)[1]),"r"((a)[2]),"r"((a)[3]),"r"((b)[0]),"r"((b)[1]))

__device__ __forceinline__ void cp16(unsigned* smem_dst, const float* gsrc){
    unsigned s = (unsigned)__cvta_generic_to_shared(smem_dst);
    asm volatile("cp.async.cg.shared.global [%0], [%1], 16;\n" :: "r"(s), "l"(gsrc));
}
#define CP_COMMIT() asm volatile("cp.async.commit_group;\n")
#define CP_WAIT(n)  asm volatile("cp.async.wait_group %0;\n" :: "n"(n))

// stage a 128x32 fp32 tile (row-major, raw bits -> TF32-truncated) via cp.async
__device__ __forceinline__ void stage_async(const float* __restrict__ src, int ld,
      int row0, int k0, unsigned* S, int tid)
{
#pragma unroll
    for (int it=0; it<4; it++){
        int idx = it*256 + tid;
        int r = idx>>3, cc = (idx&7)*4;
        cp16(S + r*LDS_PAD + cc, src + (size_t)(row0+r)*ld + k0 + cc);
    }
}

__device__ __forceinline__ void compute_tile(const unsigned* __restrict__ As,
    const unsigned* __restrict__ Bs, float acc[4][4][4], int lane, int wm, int wn)
{
    const int gr = lane>>2, gc = lane&3;
#pragma unroll
    for (int kk=0;kk<4;kk++){
        const int k8 = kk*8;
        unsigned a[4][4], b[4][2];
#pragma unroll
        for (int mt=0;mt<4;mt++){
            const unsigned* p = As + (wm + mt*16 + gr)*LDS_PAD + k8 + gc;
            a[mt][0]=p[0]; a[mt][1]=p[8*LDS_PAD]; a[mt][2]=p[4]; a[mt][3]=p[8*LDS_PAD+4];
        }
#pragma unroll
        for (int nt=0;nt<4;nt++){
            const unsigned* p = Bs + (wn + nt*8 + gr)*LDS_PAD + k8 + gc;
            b[nt][0]=p[0]; b[nt][1]=p[4];
        }
#pragma unroll
        for (int mt=0;mt<4;mt++)
#pragma unroll
            for (int nt=0;nt<4;nt++)
                MMA_TF32(acc[mt][nt], a[mt], b[nt]);
    }
}

// double-buffered NT mainloop: acc += A[m0: ,k]*B[n0: ,k]^T over k<K
__device__ __forceinline__ void gemm_loop(const float* __restrict__ A, int lda,
    const float* __restrict__ B, int ldb, int m0, int n0, int K,
    unsigned* As, unsigned* Bs, float acc[4][4][4], int tid, int lane, int wm, int wn)
{
    stage_async(A, lda, m0, 0, As, tid);
    stage_async(B, ldb, n0, 0, Bs, tid);
    CP_COMMIT();
    int nsteps = K / BK;
    for (int s=0; s<nsteps; s++){
        if (s+1 < nsteps){
            CP_WAIT(0); __syncthreads();
            int buf = (s+1)&1;
            stage_async(A, lda, m0, (s+1)*BK, As + buf*TILE_W, tid);
            stage_async(B, ldb, n0, (s+1)*BK, Bs + buf*TILE_W, tid);
            CP_COMMIT();
        } else {
            CP_WAIT(0); __syncthreads();
        }
        int buf = s&1;
        compute_tile(As + buf*TILE_W, Bs + buf*TILE_W, acc, lane, wm, wn);
        __syncthreads();
    }
}

// ---------------- GEMM kernels ----------------

// C[m,n] = sum_k A[m,k]*B[n,k] (+bias[n]) (+resid[m,n])
__global__ __launch_bounds__(256, 2) void mma_nt(
    const float* __restrict__ A, const float* __restrict__ B,
    const float* __restrict__ bias, const float* __restrict__ resid,
    float* __restrict__ C, int K, int lda, int ldb, int ldc, int ldr)
{
    extern __shared__ unsigned smem[];
    unsigned* As = smem; unsigned* Bs = smem + 2*TILE_W;
    const int tid=threadIdx.x, lane=tid&31, wid=tid>>5;
    const int wm=(wid>>2)*64, wn=(wid&3)*32;
    const int m0=blockIdx.y*BM, n0=blockIdx.x*BN;
    float acc[4][4][4] = {};
    gemm_loop(A, lda, B, ldb, m0, n0, K, As, Bs, acc, tid, lane, wm, wn);
    const int gr=lane>>2, gc=lane&3;
#pragma unroll
    for (int mt=0;mt<4;mt++){
#pragma unroll
        for (int nt=0;nt<4;nt++){
            int row = m0+wm+mt*16+gr;
            int col = n0+wn+nt*8+gc*2;
            float b0=0.f,b1=0.f;
            if (bias){ b0=bias[col]; b1=bias[col+1]; }
            float r00=0,r01=0,r10=0,r11=0;
            if (resid){
                const float* rp  = resid + (size_t)row*ldr + col;
                const float* rp2 = resid + (size_t)(row+8)*ldr + col;
                r00=rp[0]; r01=rp[1]; r10=rp2[0]; r11=rp2[1];
            }
            *(float2*)(C + (size_t)row*ldc + col)     = make_float2(acc[mt][nt][0]+b0+r00, acc[mt][nt][1]+b1+r01);
            *(float2*)(C + (size_t)(row+8)*ldc + col) = make_float2(acc[mt][nt][2]+b0+r10, acc[mt][nt][3]+b1+r11);
        }
    }
}

// batched NT: C[b][m,n] = sum_k A[b][m,k]*B[b][n,k]
__global__ __launch_bounds__(256, 2) void mma_nt_b(
    const float* __restrict__ A, const float* __restrict__ B, float* __restrict__ C,
    int K, int lda, int ldb, int ldc, long long sA, long long sB, long long sC)
{
    A += (long long)blockIdx.z * sA;
    B += (long long)blockIdx.z * sB;
    C += (long long)blockIdx.z * sC;
    extern __shared__ unsigned smem[];
    unsigned* As = smem; unsigned* Bs = smem + 2*TILE_W;
    const int tid=threadIdx.x, lane=tid&31, wid=tid>>5;
    const int wm=(wid>>2)*64, wn=(wid&3)*32;
    const int m0=blockIdx.y*BM, n0=blockIdx.x*BN;
    float acc[4][4][4] = {};
    gemm_loop(A, lda, B, ldb, m0, n0, K, As, Bs, acc, tid, lane, wm, wn);
    const int gr=lane>>2, gc=lane&3;
#pragma unroll
    for (int mt=0;mt<4;mt++){
#pragma unroll
        for (int nt=0;nt<4;nt++){
            int row = m0+wm+mt*16+gr;
            int col = n0+wn+nt*8+gc*2;
            *(float2*)(C + (size_t)row*ldc + col)     = make_float2(acc[mt][nt][0], acc[mt][nt][1]);
            *(float2*)(C + (size_t)(row+8)*ldc + col) = make_float2(acc[mt][nt][2], acc[mt][nt][3]);
        }
    }
}

// scores: C[h][l,m] = (q_h[l]·k_h[m])/16 * exp(rowt[l]+colt[m]) for m<=l else 0
__global__ __launch_bounds__(256, 2) void mma_score()
{
    const int h  = blockIdx.z;
    const int l0 = blockIdx.y * BM;
    const int m0 = blockIdx.x * BN;
    if (m0 >= l0 + BM) return;   // fully-masked tile: skipped (never read downstream)
    extern __shared__ unsigned smem[];
    unsigned* As = smem; unsigned* Bs = smem + 2*TILE_W;
    const float* A = g_q + h*DHEAD;
    const float* B = g_k + h*DHEAD;
    const int tid=threadIdx.x, lane=tid&31, wid=tid>>5;
    const int wm=(wid>>2)*64, wn=(wid&3)*32;
    float acc[4][4][4] = {};
    gemm_loop(A, DIN, B, DIN, l0, m0, DHEAD, As, Bs, acc, tid, lane, wm, wn);
    const float* rt = g_rowt + h*SEQ;
    const float* ct = g_colt + h*SEQ;
    float* Cb = g_C + (size_t)h*SEQ*SEQ;
    const int gr=lane>>2, gc=lane&3;
#pragma unroll
    for (int mt=0;mt<4;mt++){
#pragma unroll
        for (int nt=0;nt<4;nt++){
            int l = l0+wm+mt*16+gr;
            int m = m0+wn+nt*8+gc*2;
            float rl0 = rt[l], rl1 = rt[l+8];
            float cm0 = ct[m], cm1 = ct[m+1];
            float v00 = (m   <= l  ) ? acc[mt][nt][0]*0.0625f*expf(rl0+cm0) : 0.f;
            float v01 = (m+1 <= l  ) ? acc[mt][nt][1]*0.0625f*expf(rl0+cm1) : 0.f;
            float v10 = (m   <= l+8) ? acc[mt][nt][2]*0.0625f*expf(rl1+cm0) : 0.f;
            float v11 = (m+1 <= l+8) ? acc[mt][nt][3]*0.0625f*expf(rl1+cm1) : 0.f;
            *(float2*)(Cb + (size_t)l*SEQ + m)     = make_float2(v00, v01);
            *(float2*)(Cb + (size_t)(l+8)*SEQ + m) = make_float2(v10, v11);
        }
    }
}

// hflat[l, h*256+d] = invnorm[h,l] * sum_{m<=l} C[h][l,m]*vt[h][d][m]
__global__ __launch_bounds__(256, 2) void mma_pav()
{
    const int h  = blockIdx.z;
    const int l0 = blockIdx.y * BM;
    const int n0 = blockIdx.x * BN;
    extern __shared__ unsigned smem[];
    unsigned* As = smem; unsigned* Bs = smem + 2*TILE_W;
    const float* A = g_C + (size_t)h*SEQ*SEQ;
    const float* B = g_vt + (size_t)h*DHEAD*SEQ;
    const int Kmax = l0 + BM;   // causal bound
    const int tid=threadIdx.x, lane=tid&31, wid=tid>>5;
    const int wm=(wid>>2)*64, wn=(wid&3)*32;
    float acc[4][4][4] = {};
    gemm_loop(A, SEQ, B, SEQ, l0, n0, Kmax, As, Bs, acc, tid, lane, wm, wn);
    const int gr=lane>>2, gc=lane&3;
#pragma unroll
    for (int mt=0;mt<4;mt++){
#pragma unroll
        for (int nt=0;nt<4;nt++){
            int l = l0+wm+mt*16+gr;
            int col = n0+wn+nt*8+gc*2;
            float s0 = g_inrm[h*SEQ + l];
            float s1 = g_inrm[h*SEQ + l + 8];
            float* c0 = g_hfl + (size_t)l*DIN + h*DHEAD + col;
            float* c1 = g_hfl + (size_t)(l+8)*DIN + h*DHEAD + col;
            *(float2*)c0 = make_float2(acc[mt][nt][0]*s0, acc[mt][nt][1]*s0);
            *(float2*)c1 = make_float2(acc[mt][nt][2]*s1, acc[mt][nt][3]*s1);
        }
    }
}

// ---------------- transposes ----------------
// per-head 256x256: out[h][d][k] = in[h][k][d]
__global__ void transpose_w(const float* __restrict__ in, float* __restrict__ out)
{
    __shared__ float t[32][33];
    int h = blockIdx.z;
    const float* I = in  + (size_t)h*DHEAD*DHEAD;
    float*       O = out + (size_t)h*DHEAD*DHEAD;
    int k0 = blockIdx.y*32, d0 = blockIdx.x*32;
    int x = threadIdx.x, y = threadIdx.y;
#pragma unroll
    for (int i=0;i<32;i+=8) t[y+i][x] = I[(size_t)(k0+y+i)*DHEAD + d0 + x];
    __syncthreads();
#pragma unroll
    for (int i=0;i<32;i+=8) O[(size_t)(d0+y+i)*DHEAD + k0 + x] = t[x][y+i];
}

// vt[h][d][m] = v[m][h*256+d]
__global__ void transpose_v()
{
    __shared__ float t[32][33];
    int h = blockIdx.z;
    int m0 = blockIdx.x*32, d0 = blockIdx.y*32;
    int x = threadIdx.x, y = threadIdx.y;
#pragma unroll
    for (int i=0;i<32;i+=8) t[y+i][x] = g_v[(size_t)(m0+y+i)*DIN + h*DHEAD + d0 + x];
    __syncthreads();
#pragma unroll
    for (int i=0;i<32;i+=8)
        g_vt[((size_t)h*DHEAD + d0+y+i)*SEQ + m0 + x] = t[x][y+i];
}

// ---------------- elementwise / reduction kernels ----------------
__global__ void layernorm_kernel(const float* __restrict__ x, const float* __restrict__ w,
                                 float* __restrict__ out, int cols)
{
    int row = blockIdx.x, tid = threadIdx.x;
    const float* xr = x + (size_t)row*cols;
    float s = 0.f, ss = 0.f;
    for (int c = tid; c < cols; c += 256){ float v = xr[c]; s += v; ss += v*v; }
    __shared__ float sh1[256], sh2[256];
    sh1[tid]=s; sh2[tid]=ss; __syncthreads();
    for (int off=128; off>0; off>>=1){
        if (tid < off){ sh1[tid]+=sh1[tid+off]; sh2[tid]+=sh2[tid+off]; }
        __syncthreads();
    }
    float mean = sh1[0] / cols;
    float var  = sh2[0] / cols - mean*mean;
    float rstd = rsqrtf(var + 1e-5f);
    for (int c = tid; c < cols; c += 256)
        out[(size_t)row*cols + c] = (xr[c] - mean) * rstd * w[c];
}

__global__ void conv_silu_kernel(const float* __restrict__ ck, const float* __restrict__ cb)
{
    int idx = blockIdx.x*256 + threadIdx.x;
    if (idx >= SEQ*DIN) return;
    int l = idx / DIN, c = idx % DIN;
    float s = cb[c];
#pragma unroll
    for (int t=0;t<4;t++){
        int ls = l - t;
        if (ls >= 0) s = fmaf(g_proj[(size_t)ls*(2*DIN) + c], ck[c*4 + t], s);
    }
    g_xc[idx] = s / (1.f + expf(-s));
}

__global__ __launch_bounds__(256) void gates_kernel(
    const float* __restrict__ igw, const float* __restrict__ igb,
    const float* __restrict__ fgw, const float* __restrict__ fgb)
{
    __shared__ float buf[2*3*DIN];
    int l0 = blockIdx.x*2, tid = threadIdx.x;
    for (int c = tid; c < DIN; c += 256){
#pragma unroll
        for (int rr=0; rr<2; rr++){
            buf[rr*3*DIN + c]         = g_q[(size_t)(l0+rr)*DIN + c];
            buf[rr*3*DIN + DIN + c]   = g_k[(size_t)(l0+rr)*DIN + c];
            buf[rr*3*DIN + 2*DIN + c] = g_v[(size_t)(l0+rr)*DIN + c];
        }
    }
    __syncthreads();
    int w = tid >> 5, lane = tid & 31;
    const float* iw = igw + (size_t)w*3*DIN;
    const float* fw = fgw + (size_t)w*3*DIN;
    float si0=0.f, sf0=0.f, si1=0.f, sf1=0.f;
    for (int j = lane; j < 3*DIN; j += 32){
        float wi = iw[j], wf = fw[j];
        float g0 = buf[j], g1 = buf[3*DIN + j];
        si0 = fmaf(g0, wi, si0); si1 = fmaf(g1, wi, si1);
        sf0 = fmaf(g0, wf, sf0); sf1 = fmaf(g1, wf, sf1);
    }
#pragma unroll
    for (int off=16; off>0; off>>=1){
        si0 += __shfl_xor_sync(0xffffffffu, si0, off);
        sf0 += __shfl_xor_sync(0xffffffffu, sf0, off);
        si1 += __shfl_xor_sync(0xffffffffu, si1, off);
        sf1 += __shfl_xor_sync(0xffffffffu, sf1, off);
    }
    if (lane == 0){
        g_ig[w*SEQ + l0]   = si0 + igb[w];
        g_fg[w*SEQ + l0]   = sf0 + fgb[w];
        g_ig[w*SEQ + l0+1] = si1 + igb[w];
        g_fg[w*SEQ + l0+1] = sf1 + fgb[w];
    }
}

__global__ __launch_bounds__(256) void scan_kernel()
{
    __shared__ float lf[SEQ];
    __shared__ float tot[256];
    int h = blockIdx.x, tid = threadIdx.x;
    for (int m = tid; m < SEQ; m += 256){
        float f = g_fg[h*SEQ + m];
        lf[m] = fminf(f, 0.f) - log1pf(expf(-fabsf(f)));   // log_sigmoid
    }
    __syncthreads();
    int base = tid * 8;
    float csl[8];
    float run = 0.f;
#pragma unroll
    for (int j=0;j<8;j++){ run += lf[base+j]; csl[j] = run; }
    tot[tid] = run; __syncthreads();
    for (int off=1; off<256; off<<=1){
        float v = (tid >= off) ? tot[tid-off] : 0.f;
        __syncthreads();
        tot[tid] += v;
        __syncthreads();
    }
    float excl = tot[tid] - run;
    float cs[8], cml[8];
    float rmax = -INFINITY;
#pragma unroll
    for (int j=0;j<8;j++){
        cs[j] = csl[j] + excl;
        float col = g_ig[h*SEQ + base + j] - cs[j];
        g_colt[h*SEQ + base + j] = col;
        rmax = fmaxf(rmax, col);
        cml[j] = rmax;
    }
    tot[tid] = rmax; __syncthreads();
    for (int off=1; off<256; off<<=1){
        float v = (tid >= off) ? tot[tid-off] : -INFINITY;
        __syncthreads();
        tot[tid] = fmaxf(tot[tid], v);
        __syncthreads();
    }
    float em = (tid > 0) ? tot[tid-1] : -INFINITY;
#pragma unroll
    for (int j=0;j<8;j++){
        float rm = fmaxf(em, cml[j]);
        g_rowt[h*SEQ + base + j] = -rm;
        g_expn[h*SEQ + base + j] = expf(-(cs[j] + rm));
    }
}

__global__ void norm_kernel()
{
    int l = blockIdx.x, h = blockIdx.y, tid = threadIdx.x;
    const float* row = g_C + ((size_t)h*SEQ + l)*SEQ;
    float s = 0.f;
    for (int m = tid; m <= l; m += 256) s += row[m];
    __shared__ float sh[256];
    sh[tid] = s; __syncthreads();
    for (int off=128; off>0; off>>=1){
        if (tid < off) sh[tid] += sh[tid+off];
        __syncthreads();
    }
    if (tid == 0){
        float n = fmaxf(fabsf(sh[0]), g_expn[h*SEQ + l]) + 1e-6f;
        g_inrm[h*SEQ + l] = 1.0f / n;
    }
}

__global__ __launch_bounds__(256) void gn_kernel(const float* __restrict__ gnw,
    const float* __restrict__ gnb, const float* __restrict__ skip)
{
    int l = blockIdx.x, tid = threadIdx.x, w = tid >> 5, lane = tid & 31;
    const float* hrow = g_hfl + (size_t)l*DIN + w*DHEAD;
    float vals[8]; float s = 0.f, ss = 0.f;
#pragma unroll
    for (int k2=0;k2<8;k2++){ float v = hrow[lane + k2*32]; vals[k2]=v; s+=v; ss+=v*v; }
#pragma unroll
    for (int off=16; off>0; off>>=1){
        s  += __shfl_xor_sync(0xffffffffu, s,  off);
        ss += __shfl_xor_sync(0xffffffffu, ss, off);
    }
    float mean = s * (1.f/DHEAD);
    float var  = ss * (1.f/DHEAD) - mean*mean;
    float rstd = rsqrtf(var + 1e-5f);
#pragma unroll
    for (int k2=0;k2<8;k2++){
        int c = w*DHEAD + lane + k2*32;
        float hn = (vals[k2] - mean) * rstd;
        float h2 = hn*gnw[c] + gnb[c] + skip[c]*g_xc[(size_t)l*DIN + c];
        float r  = g_proj[(size_t)l*(2*DIN) + DIN + c];
        float sl = r / (1.f + expf(-r));
        g_yin[(size_t)l*DIN + c] = h2 * sl;
    }
}

__global__ void gelu_kernel()
{
    int idx = blockIdx.x*256 + threadIdx.x;
    if (idx >= SEQ*DHID) return;
    int l = idx / DHID, j = idx % DHID;
    float a = g_p[(size_t)l*(2*DHID) + j];
    float z = g_p[(size_t)l*(2*DHID) + DHID + j];
    float t = tanhf(0.7978845608028654f * (a + 0.044715f*a*a*a));
    g_g2[idx] = 0.5f * a * (1.f + t) * z;
}

// ---------------- launch ----------------
extern "C" void kernel_launch(void* const* d_in, const int* in_sizes, int n_in,
                              void* d_out, int out_size)
{
    (void)in_sizes; (void)n_in; (void)out_size;
    const float* x    = (const float*)d_in[0];
    const float* ln1w = (const float*)d_in[2];
    const float* winw = (const float*)d_in[3];
    const float* winb = (const float*)d_in[4];
    const float* woutw= (const float*)d_in[5];
    const float* ck   = (const float*)d_in[6];
    const float* cb   = (const float*)d_in[7];
    const float* wq   = (const float*)d_in[8];
    const float* wk   = (const float*)d_in[9];
    const float* wv   = (const float*)d_in[10];
    const float* igw  = (const float*)d_in[11];
    const float* igb  = (const float*)d_in[12];
    const float* fgw  = (const float*)d_in[13];
    const float* fgb  = (const float*)d_in[14];
    const float* gnw  = (const float*)d_in[15];
    const float* gnb  = (const float*)d_in[16];
    const float* skip = (const float*)d_in[17];
    const float* ln2w = (const float*)d_in[18];
    const float* ffnw = (const float*)d_in[19];
    const float* ffnow= (const float*)d_in[20];
    float* out = (float*)d_out;

    static int smem_set = 0;
    if (!smem_set){
        cudaFuncSetAttribute(mma_nt,    cudaFuncAttributeMaxDynamicSharedMemorySize, SMEM_BYTES);
        cudaFuncSetAttribute(mma_nt_b,  cudaFuncAttributeMaxDynamicSharedMemorySize, SMEM_BYTES);
        cudaFuncSetAttribute(mma_score, cudaFuncAttributeMaxDynamicSharedMemorySize, SMEM_BYTES);
        cudaFuncSetAttribute(mma_pav,   cudaFuncAttributeMaxDynamicSharedMemorySize, SMEM_BYTES);
        smem_set = 1;
    }

    float *hln,*proj,*xc,*q,*k,*v,*yin,*x2,*hf,*p,*g2,*wqt,*wkt,*wvt;
    cudaGetSymbolAddress((void**)&hln,  g_hln);
    cudaGetSymbolAddress((void**)&proj, g_proj);
    cudaGetSymbolAddress((void**)&xc,   g_xc);
    cudaGetSymbolAddress((void**)&q,    g_q);
    cudaGetSymbolAddress((void**)&k,    g_k);
    cudaGetSymbolAddress((void**)&v,    g_v);
    cudaGetSymbolAddress((void**)&yin,  g_yin);
    cudaGetSymbolAddress((void**)&x2,   g_x2);
    cudaGetSymbolAddress((void**)&hf,   g_hf);
    cudaGetSymbolAddress((void**)&p,    g_p);
    cudaGetSymbolAddress((void**)&g2,   g_g2);
    cudaGetSymbolAddress((void**)&wqt,  g_wqt);
    cudaGetSymbolAddress((void**)&wkt,  g_wkt);
    cudaGetSymbolAddress((void**)&wvt,  g_wvt);

    dim3 tb(32, 8);
    // weight transposes (independent of data path order)
    transpose_w<<<dim3(8,8,NHEAD), tb>>>(wq, wqt);
    transpose_w<<<dim3(8,8,NHEAD), tb>>>(wk, wkt);
    transpose_w<<<dim3(8,8,NHEAD), tb>>>(wv, wvt);

    // 1. h = LN(x)
    layernorm_kernel<<<SEQ, 256>>>(x, ln1w, hln, DMOD);
    // 2. proj = h @ win_w^T + win_b
    mma_nt<<<dim3(4096/BN, SEQ/BM), 256, SMEM_BYTES>>>(hln, winw, winb, 0, proj, DMOD, DMOD, DMOD, 2*DIN, 0);
    // 3. xc = silu(causal_conv(xi))
    conv_silu_kernel<<<SEQ*DIN/256, 256>>>(ck, cb);
    // 4. q/k from xc, v from xi
    mma_nt_b<<<dim3(DHEAD/BN, SEQ/BM, NHEAD), 256, SMEM_BYTES>>>(xc,   wqt, q, DHEAD, DIN,   DHEAD, DIN, DHEAD, (long long)DHEAD*DHEAD, DHEAD);
    mma_nt_b<<<dim3(DHEAD/BN, SEQ/BM, NHEAD), 256, SMEM_BYTES>>>(xc,   wkt, k, DHEAD, DIN,   DHEAD, DIN, DHEAD, (long long)DHEAD*DHEAD, DHEAD);
    mma_nt_b<<<dim3(DHEAD/BN, SEQ/BM, NHEAD), 256, SMEM_BYTES>>>(proj, wvt, v, DHEAD, 2*DIN, DHEAD, DIN, DHEAD, (long long)DHEAD*DHEAD, DHEAD);
    // 4b. vt[h][d][m]
    transpose_v<<<dim3(SEQ/32, DHEAD/32, NHEAD), tb>>>();
    // 5. gates
    gates_kernel<<<SEQ/2, 256>>>(igw, igb, fgw, fgb);
    // 6. per-head scans
    scan_kernel<<<NHEAD, 256>>>();
    // 7. C = (QK^T/16) * D (causal, tile-skipped)
    mma_score<<<dim3(SEQ/BN, SEQ/BM, NHEAD), 256, SMEM_BYTES>>>();
    // 8. row sums -> 1/(norm+1e-6)
    norm_kernel<<<dim3(SEQ, NHEAD), 256>>>();
    // 9. hflat = (C*invnorm) @ V
    mma_pav<<<dim3(DHEAD/BN, SEQ/BM, NHEAD), 256, SMEM_BYTES>>>();
    // 10. group norm + skip*xc, * silu(res)
    gn_kernel<<<SEQ, 256>>>(gnw, gnb, skip);
    // 11. x2 = x + yin @ wout_w^T
    mma_nt<<<dim3(DMOD/BN, SEQ/BM), 256, SMEM_BYTES>>>(yin, woutw, 0, x, x2, DIN, DIN, DIN, DMOD, DMOD);
    // 12. hf = LN(x2)
    layernorm_kernel<<<SEQ, 256>>>(x2, ln2w, hf, DMOD);
    // 13. p = hf @ ffn_win_w^T
    mma_nt<<<dim3(4096/BN, SEQ/BM), 256, SMEM_BYTES>>>(hf, ffnw, 0, 0, p, DMOD, DMOD, DMOD, 2*DHID, 0);
    // 14. g2 = gelu(a)*z
    gelu_kernel<<<SEQ*DHID/256, 256>>>();
    // 15. out = x2 + g2 @ ffn_wout_w^T
    mma_nt<<<dim3(DMOD/BN, SEQ/BM), 256, SMEM_BYTES>>>(g2, ffnow, 0, x2, out, DHID, DHID, DHID, DMOD, DMOD);
}

// round 4
// speedup vs baseline: 4.8537x; 1.5438x over previous
#include <cuda_runtime.h>
#include <cuda_bf16.h>
#include <math.h>

#define SEQ   2048
#define DMOD  1024
#define DIN   2048
#define NHEAD 8
#define DHEAD 256
#define DHID  2048

typedef __nv_bfloat16 bf16;

// ---------------- scratch (allocation-free: __device__ globals) ----------------
__device__ float g_proj[SEQ*2*DIN];
__device__ float g_xc  [SEQ*DIN];
__device__ float g_q   [SEQ*DIN];
__device__ float g_k   [SEQ*DIN];
__device__ float g_v   [SEQ*DIN];
__device__ float g_ig  [NHEAD*SEQ];
__device__ float g_fg  [NHEAD*SEQ];
__device__ float g_rowt[NHEAD*SEQ];
__device__ float g_colt[NHEAD*SEQ];
__device__ float g_expn[NHEAD*SEQ];
__device__ float g_inrm[NHEAD*SEQ];
__device__ float g_psum[NHEAD*16*SEQ];
__device__ float g_hfl [SEQ*DIN];
__device__ float g_x2  [SEQ*DMOD];
__device__ float g_p   [SEQ*2*DHID];

__device__ bf16 g_hln_bf [SEQ*DMOD];
__device__ bf16 g_xi_bf  [SEQ*DIN];
__device__ bf16 g_xc_bf  [SEQ*DIN];
__device__ bf16 g_q_bf   [SEQ*DIN];
__device__ bf16 g_k_bf   [SEQ*DIN];
__device__ bf16 g_vt_bf  [(size_t)NHEAD*DHEAD*SEQ];
__device__ bf16 g_C_bf   [(size_t)NHEAD*SEQ*SEQ];
__device__ bf16 g_yin_bf [SEQ*DIN];
__device__ bf16 g_hf_bf  [SEQ*DMOD];
__device__ bf16 g_g2_bf  [SEQ*DHID];
__device__ bf16 g_winw_bf[2*DIN*DMOD];
__device__ bf16 g_woutw_bf[DMOD*DIN];
__device__ bf16 g_ffnw_bf[2*DHID*DMOD];
__device__ bf16 g_ffnow_bf[DMOD*DHID];
__device__ bf16 g_wqt_bf[NHEAD*DHEAD*DHEAD];
__device__ bf16 g_wkt_bf[NHEAD*DHEAD*DHEAD];
__device__ bf16 g_wvt_bf[NHEAD*DHEAD*DHEAD];

// ---------------- bf16 MMA tile config ----------------
#define BM 128
#define BN 128
#define BKB 64                   // bf16 elements per stage (128B rows)
#define TILEB 16384              // 128 rows x 128B
#define SMEM_GEMM (4*TILEB)      // double-buffered A+B

__device__ __forceinline__ unsigned sw128(unsigned o){ return o ^ ((o>>3)&0x70); }

__device__ __forceinline__ void cp16(void* smem_dst, const void* gsrc){
    unsigned s = (unsigned)__cvta_generic_to_shared(smem_dst);
    asm volatile("cp.async.cg.shared.global [%0], [%1], 16;" :: "r"(s), "l"(gsrc));
}
#define CP_COMMIT() asm volatile("cp.async.commit_group;")
#define CP_WAIT(n)  asm volatile("cp.async.wait_group %0;" :: "n"(n))

__device__ __forceinline__ void ldsm4(unsigned r[4], const void* p){
    unsigned a = (unsigned)__cvta_generic_to_shared(p);
    asm volatile("ldmatrix.sync.aligned.m8n8.x4.shared.b16 {%0,%1,%2,%3}, [%4];"
        : "=r"(r[0]),"=r"(r[1]),"=r"(r[2]),"=r"(r[3]) : "r"(a));
}

#define MMA_BF16(d, a, b) \
  asm volatile("mma.sync.aligned.m16n8k16.row.col.f32.bf16.bf16.f32 " \
    "{%0,%1,%2,%3},{%4,%5,%6,%7},{%8,%9},{%0,%1,%2,%3};" \
    : "+f"((d)[0]),"+f"((d)[1]),"+f"((d)[2]),"+f"((d)[3]) \
    : "r"((a)[0]),"r"((a)[1]),"r"((a)[2]),"r"((a)[3]),"r"((b)[0]),"r"((b)[1]))

// stage 128 rows x 64 bf16 (row-major, swizzled SW128) via cp.async
__device__ __forceinline__ void stage_bf(const bf16* __restrict__ src, int ld,
      int row0, int k0, char* S, int tid)
{
#pragma unroll
    for (int it=0; it<4; it++){
        int idx = it*256 + tid;
        int r = idx>>3, ch = idx&7;
        cp16(S + sw128(r*128 + ch*16), src + (size_t)(row0+r)*ld + k0 + ch*8);
    }
}

__device__ __forceinline__ void compute_bf(const char* __restrict__ As,
    const char* __restrict__ Bs, float acc[4][4][4], int lane, int wm, int wn)
{
    const int l15 = lane&15, lh = lane>>4, l7 = lane&7, lb3 = (lane>>3)&1;
#pragma unroll
    for (int kk=0;kk<4;kk++){
        unsigned a[4][4];
#pragma unroll
        for (int mt=0;mt<4;mt++)
            ldsm4(a[mt], As + sw128((wm + mt*16 + l15)*128 + (kk*2 + lh)*16));
        unsigned b[2][4];
#pragma unroll
        for (int bp=0;bp<2;bp++){
            unsigned row = wn + bp*16 + lh*8 + l7;
            ldsm4(b[bp], Bs + sw128(row*128 + (kk*2 + lb3)*16));
        }
#pragma unroll
        for (int mt=0;mt<4;mt++)
#pragma unroll
            for (int nt=0;nt<4;nt++)
                MMA_BF16(acc[mt][nt], a[mt], b[nt>>1] + (nt&1)*2);
    }
}

// double-buffered NT mainloop: acc += A[m0:,k]*B[n0:,k]^T, k<K
__device__ __forceinline__ void gemm_loop_bf(const bf16* __restrict__ A, int lda,
    const bf16* __restrict__ B, int ldb, int m0, int n0, int K,
    char* SA, char* SB, float acc[4][4][4], int tid, int lane, int wm, int wn)
{
    stage_bf(A, lda, m0, 0, SA, tid);
    stage_bf(B, ldb, n0, 0, SB, tid);
    CP_COMMIT();
    int nsteps = K >> 6;
    for (int s=0; s<nsteps; s++){
        int cur = s&1;
        if (s+1 < nsteps){
            int nb = (s+1)&1;
            stage_bf(A, lda, m0, (s+1)*BKB, SA + nb*TILEB, tid);
            stage_bf(B, ldb, n0, (s+1)*BKB, SB + nb*TILEB, tid);
            CP_COMMIT();
            CP_WAIT(1);
        } else {
            CP_WAIT(0);
        }
        __syncthreads();
        compute_bf(SA + cur*TILEB, SB + cur*TILEB, acc, lane, wm, wn);
        __syncthreads();
    }
}

// ---------------- GEMM kernels ----------------

// C[m,n] = sum_k A[m,k]*B[n,k] (+bias) (+resid); fp32 out + optional bf16 shadow
__global__ __launch_bounds__(256, 2) void mma_nt_bf(
    const bf16* __restrict__ A, const bf16* __restrict__ B,
    const float* __restrict__ bias, const float* __restrict__ resid,
    float* __restrict__ Cf, bf16* __restrict__ Cb,
    int K, int lda, int ldb, int ldc, int ldr, int ldcb, int bfcols)
{
    extern __shared__ char smem[];
    char* SA = smem; char* SB = smem + 2*TILEB;
    const int tid=threadIdx.x, lane=tid&31, wid=tid>>5;
    const int wm=(wid>>2)*64, wn=(wid&3)*32;
    const int m0=blockIdx.y*BM, n0=blockIdx.x*BN;
    float acc[4][4][4] = {};
    gemm_loop_bf(A, lda, B, ldb, m0, n0, K, SA, SB, acc, tid, lane, wm, wn);
    const int gr=lane>>2, gc=lane&3;
#pragma unroll
    for (int mt=0;mt<4;mt++){
#pragma unroll
        for (int nt=0;nt<4;nt++){
            int row = m0+wm+mt*16+gr;
            int col = n0+wn+nt*8+gc*2;
            float b0=0.f,b1=0.f;
            if (bias){ b0=bias[col]; b1=bias[col+1]; }
            float r00=0,r01=0,r10=0,r11=0;
            if (resid){
                const float* rp  = resid + (size_t)row*ldr + col;
                const float* rp2 = resid + (size_t)(row+8)*ldr + col;
                r00=rp[0]; r01=rp[1]; r10=rp2[0]; r11=rp2[1];
            }
            float v00=acc[mt][nt][0]+b0+r00, v01=acc[mt][nt][1]+b1+r01;
            float v10=acc[mt][nt][2]+b0+r10, v11=acc[mt][nt][3]+b1+r11;
            if (Cf){
                *(float2*)(Cf + (size_t)row*ldc + col)     = make_float2(v00,v01);
                *(float2*)(Cf + (size_t)(row+8)*ldc + col) = make_float2(v10,v11);
            }
            if (Cb && col < bfcols){
                *(__nv_bfloat162*)(Cb + (size_t)row*ldcb + col)     = __floats2bfloat162_rn(v00,v01);
                *(__nv_bfloat162*)(Cb + (size_t)(row+8)*ldcb + col) = __floats2bfloat162_rn(v10,v11);
            }
        }
    }
}

// batched NT (per-head q/k/v): fp32 out + optional bf16 shadow
__global__ __launch_bounds__(256, 2) void mma_nt_b_bf(
    const bf16* __restrict__ A, const bf16* __restrict__ B,
    float* __restrict__ Cf, bf16* __restrict__ Cb,
    int K, int lda, int ldb, int ldc,
    long long sA, long long sB, long long sC)
{
    A  += (long long)blockIdx.z * sA;
    B  += (long long)blockIdx.z * sB;
    Cf += (long long)blockIdx.z * sC;
    if (Cb) Cb += (long long)blockIdx.z * sC;
    extern __shared__ char smem[];
    char* SA = smem; char* SB = smem + 2*TILEB;
    const int tid=threadIdx.x, lane=tid&31, wid=tid>>5;
    const int wm=(wid>>2)*64, wn=(wid&3)*32;
    const int m0=blockIdx.y*BM, n0=blockIdx.x*BN;
    float acc[4][4][4] = {};
    gemm_loop_bf(A, lda, B, ldb, m0, n0, K, SA, SB, acc, tid, lane, wm, wn);
    const int gr=lane>>2, gc=lane&3;
#pragma unroll
    for (int mt=0;mt<4;mt++){
#pragma unroll
        for (int nt=0;nt<4;nt++){
            int row = m0+wm+mt*16+gr;
            int col = n0+wn+nt*8+gc*2;
            *(float2*)(Cf + (size_t)row*ldc + col)     = make_float2(acc[mt][nt][0],acc[mt][nt][1]);
            *(float2*)(Cf + (size_t)(row+8)*ldc + col) = make_float2(acc[mt][nt][2],acc[mt][nt][3]);
            if (Cb){
                *(__nv_bfloat162*)(Cb + (size_t)row*ldc + col)     = __floats2bfloat162_rn(acc[mt][nt][0],acc[mt][nt][1]);
                *(__nv_bfloat162*)(Cb + (size_t)(row+8)*ldc + col) = __floats2bfloat162_rn(acc[mt][nt][2],acc[mt][nt][3]);
            }
        }
    }
}

// scores: C[h][l,m] = (q·k)/16 * exp(rowt[l]+colt[m]) masked; bf16 out + fp32 tile row-sums
__global__ __launch_bounds__(256, 2) void mma_score_bf()
{
    const int h  = blockIdx.z;
    const int l0 = blockIdx.y * BM;
    const int m0 = blockIdx.x * BN;
    if (m0 >= l0 + BM) return;   // fully-masked tile: skipped (never read downstream)
    extern __shared__ char smem[];
    char* SA = smem; char* SB = smem + 2*TILEB;
    const bf16* A = g_q_bf + h*DHEAD;
    const bf16* B = g_k_bf + h*DHEAD;
    const int tid=threadIdx.x, lane=tid&31, wid=tid>>5;
    const int wm=(wid>>2)*64, wn=(wid&3)*32;
    float acc[4][4][4] = {};
    gemm_loop_bf(A, DIN, B, DIN, l0, m0, DHEAD, SA, SB, acc, tid, lane, wm, wn);

    float* sred = (float*)smem;   // reuse (post-loop, after final syncthreads)
    const float* rt = g_rowt + h*SEQ;
    const float* ct = g_colt + h*SEQ;
    bf16* Cb = g_C_bf + (size_t)h*SEQ*SEQ;
    const int gr=lane>>2, gc=lane&3;
#pragma unroll
    for (int mt=0;mt<4;mt++){
        int l = l0+wm+mt*16+gr;
        float rl0 = rt[l], rl1 = rt[l+8];
        float rs0 = 0.f, rs1 = 0.f;
#pragma unroll
        for (int nt=0;nt<4;nt++){
            int m = m0+wn+nt*8+gc*2;
            float cm0 = ct[m], cm1 = ct[m+1];
            float v00 = (m   <= l  ) ? acc[mt][nt][0]*0.0625f*expf(rl0+cm0) : 0.f;
            float v01 = (m+1 <= l  ) ? acc[mt][nt][1]*0.0625f*expf(rl0+cm1) : 0.f;
            float v10 = (m   <= l+8) ? acc[mt][nt][2]*0.0625f*expf(rl1+cm0) : 0.f;
            float v11 = (m+1 <= l+8) ? acc[mt][nt][3]*0.0625f*expf(rl1+cm1) : 0.f;
            rs0 += v00 + v01;
            rs1 += v10 + v11;
            *(__nv_bfloat162*)(Cb + (size_t)l*SEQ + m)     = __floats2bfloat162_rn(v00,v01);
            *(__nv_bfloat162*)(Cb + (size_t)(l+8)*SEQ + m) = __floats2bfloat162_rn(v10,v11);
        }
        // reduce across the 4 quad lanes (same row)
        rs0 += __shfl_xor_sync(0xffffffffu, rs0, 1);
        rs0 += __shfl_xor_sync(0xffffffffu, rs0, 2);
        rs1 += __shfl_xor_sync(0xffffffffu, rs1, 1);
        rs1 += __shfl_xor_sync(0xffffffffu, rs1, 2);
        if (gc == 0){
            sred[(wm+mt*16+gr)*4   + (wid&3)] = rs0;
            sred[(wm+mt*16+gr+8)*4 + (wid&3)] = rs1;
        }
    }
    __syncthreads();
    if (tid < 128){
        float s = sred[tid*4] + sred[tid*4+1] + sred[tid*4+2] + sred[tid*4+3];
        g_psum[((size_t)h*16 + blockIdx.x)*SEQ + l0 + tid] = s;
    }
}

// hflat[l, h*256+d] = invnorm[h,l] * sum_{m<=l} C[h][l,m]*vt[h][d][m]
__global__ __launch_bounds__(256, 2) void mma_pav_bf()
{
    const int h  = blockIdx.z;
    const int l0 = blockIdx.y * BM;
    const int n0 = blockIdx.x * BN;
    extern __shared__ char smem[];
    char* SA = smem; char* SB = smem + 2*TILEB;
    const bf16* A = g_C_bf + (size_t)h*SEQ*SEQ;
    const bf16* B = g_vt_bf + (size_t)h*DHEAD*SEQ;
    const int Kmax = l0 + BM;   // causal bound
    const int tid=threadIdx.x, lane=tid&31, wid=tid>>5;
    const int wm=(wid>>2)*64, wn=(wid&3)*32;
    float acc[4][4][4] = {};
    gemm_loop_bf(A, SEQ, B, SEQ, l0, n0, Kmax, SA, SB, acc, tid, lane, wm, wn);
    const int gr=lane>>2, gc=lane&3;
#pragma unroll
    for (int mt=0;mt<4;mt++){
#pragma unroll
        for (int nt=0;nt<4;nt++){
            int l = l0+wm+mt*16+gr;
            int col = n0+wn+nt*8+gc*2;
            float s0 = g_inrm[h*SEQ + l];
            float s1 = g_inrm[h*SEQ + l + 8];
            float* c0 = g_hfl + (size_t)l*DIN + h*DHEAD + col;
            float* c1 = g_hfl + (size_t)(l+8)*DIN + h*DHEAD + col;
            *(float2*)c0 = make_float2(acc[mt][nt][0]*s0, acc[mt][nt][1]*s0);
            *(float2*)c1 = make_float2(acc[mt][nt][2]*s1, acc[mt][nt][3]*s1);
        }
    }
}

// ---------------- converts / transposes ----------------
__global__ void convert_f2bf(const float* __restrict__ src, bf16* __restrict__ dst, int n)
{
    int i = blockIdx.x*256 + threadIdx.x;
    if (i < n) dst[i] = __float2bfloat16_rn(src[i]);
}

// per-head 256x256: out[h][d][k] = in[h][k][d], bf16 out
__global__ void transpose_w_bf(const float* __restrict__ in, bf16* __restrict__ out)
{
    __shared__ float t[32][33];
    int h = blockIdx.z;
    const float* I = in  + (size_t)h*DHEAD*DHEAD;
    bf16*        O = out + (size_t)h*DHEAD*DHEAD;
    int k0 = blockIdx.y*32, d0 = blockIdx.x*32;
    int x = threadIdx.x, y = threadIdx.y;
#pragma unroll
    for (int i=0;i<32;i+=8) t[y+i][x] = I[(size_t)(k0+y+i)*DHEAD + d0 + x];
    __syncthreads();
#pragma unroll
    for (int i=0;i<32;i+=8) O[(size_t)(d0+y+i)*DHEAD + k0 + x] = __float2bfloat16_rn(t[x][y+i]);
}

// vt_bf[h][d][m] = v[m][h*256+d]
__global__ void transpose_v_bf()
{
    __shared__ float t[32][33];
    int h = blockIdx.z;
    int m0 = blockIdx.x*32, d0 = blockIdx.y*32;
    int x = threadIdx.x, y = threadIdx.y;
#pragma unroll
    for (int i=0;i<32;i+=8) t[y+i][x] = g_v[(size_t)(m0+y+i)*DIN + h*DHEAD + d0 + x];
    __syncthreads();
#pragma unroll
    for (int i=0;i<32;i+=8)
        g_vt_bf[((size_t)h*DHEAD + d0+y+i)*SEQ + m0 + x] = __float2bfloat16_rn(t[x][y+i]);
}

// ---------------- elementwise / reduction kernels ----------------
__global__ void layernorm_bf(const float* __restrict__ x, const float* __restrict__ w,
                             bf16* __restrict__ out, int cols)
{
    int row = blockIdx.x, tid = threadIdx.x;
    const float* xr = x + (size_t)row*cols;
    float s = 0.f, ss = 0.f;
    for (int c = tid; c < cols; c += 256){ float v = xr[c]; s += v; ss += v*v; }
    __shared__ float sh1[256], sh2[256];
    sh1[tid]=s; sh2[tid]=ss; __syncthreads();
    for (int off=128; off>0; off>>=1){
        if (tid < off){ sh1[tid]+=sh1[tid+off]; sh2[tid]+=sh2[tid+off]; }
        __syncthreads();
    }
    float mean = sh1[0] / cols;
    float var  = sh2[0] / cols - mean*mean;
    float rstd = rsqrtf(var + 1e-5f);
    for (int c = tid; c < cols; c += 256)
        out[(size_t)row*cols + c] = __float2bfloat16_rn((xr[c] - mean) * rstd * w[c]);
}

__global__ void conv_silu_kernel(const float* __restrict__ ck, const float* __restrict__ cb)
{
    int idx = blockIdx.x*256 + threadIdx.x;
    if (idx >= SEQ*DIN) return;
    int l = idx / DIN, c = idx % DIN;
    float s = cb[c];
#pragma unroll
    for (int t=0;t<4;t++){
        int ls = l - t;
        if (ls >= 0) s = fmaf(g_proj[(size_t)ls*(2*DIN) + c], ck[c*4 + t], s);
    }
    float r = s / (1.f + expf(-s));
    g_xc[idx] = r;
    g_xc_bf[idx] = __float2bfloat16_rn(r);
}

// 8 rows per block (dynamic smem); each warp = one head
__global__ __launch_bounds__(256) void gates_kernel(
    const float* __restrict__ igw, const float* __restrict__ igb,
    const float* __restrict__ fgw, const float* __restrict__ fgb)
{
    extern __shared__ float buf[];   // 8*3*DIN floats
    int l0 = blockIdx.x*8, tid = threadIdx.x;
#pragma unroll
    for (int rr=0; rr<8; rr++){
        for (int c = tid; c < DIN; c += 256){
            buf[rr*3*DIN + c]         = g_q[(size_t)(l0+rr)*DIN + c];
            buf[rr*3*DIN + DIN + c]   = g_k[(size_t)(l0+rr)*DIN + c];
            buf[rr*3*DIN + 2*DIN + c] = g_v[(size_t)(l0+rr)*DIN + c];
        }
    }
    __syncthreads();
    int w = tid >> 5, lane = tid & 31;
    const float* iw = igw + (size_t)w*3*DIN;
    const float* fw = fgw + (size_t)w*3*DIN;
    float si[8] = {}, sf[8] = {};
    for (int j = lane; j < 3*DIN; j += 32){
        float wi = iw[j], wf = fw[j];
#pragma unroll
        for (int rr=0;rr<8;rr++){
            float g = buf[rr*3*DIN + j];
            si[rr] = fmaf(g, wi, si[rr]);
            sf[rr] = fmaf(g, wf, sf[rr]);
        }
    }
#pragma unroll
    for (int off=16; off>0; off>>=1){
#pragma unroll
        for (int rr=0;rr<8;rr++){
            si[rr] += __shfl_xor_sync(0xffffffffu, si[rr], off);
            sf[rr] += __shfl_xor_sync(0xffffffffu, sf[rr], off);
        }
    }
    if (lane == 0){
#pragma unroll
        for (int rr=0;rr<8;rr++){
            g_ig[w*SEQ + l0+rr] = si[rr] + igb[w];
            g_fg[w*SEQ + l0+rr] = sf[rr] + fgb[w];
        }
    }
}

__global__ __launch_bounds__(256) void scan_kernel()
{
    __shared__ float lf[SEQ];
    __shared__ float tot[256];
    int h = blockIdx.x, tid = threadIdx.x;
    for (int m = tid; m < SEQ; m += 256){
        float f = g_fg[h*SEQ + m];
        lf[m] = fminf(f, 0.f) - log1pf(expf(-fabsf(f)));   // log_sigmoid
    }
    __syncthreads();
    int base = tid * 8;
    float csl[8];
    float run = 0.f;
#pragma unroll
    for (int j=0;j<8;j++){ run += lf[base+j]; csl[j] = run; }
    tot[tid] = run; __syncthreads();
    for (int off=1; off<256; off<<=1){
        float v = (tid >= off) ? tot[tid-off] : 0.f;
        __syncthreads();
        tot[tid] += v;
        __syncthreads();
    }
    float excl = tot[tid] - run;
    float cs[8], cml[8];
    float rmax = -INFINITY;
#pragma unroll
    for (int j=0;j<8;j++){
        cs[j] = csl[j] + excl;
        float col = g_ig[h*SEQ + base + j] - cs[j];
        g_colt[h*SEQ + base + j] = col;
        rmax = fmaxf(rmax, col);
        cml[j] = rmax;
    }
    tot[tid] = rmax; __syncthreads();
    for (int off=1; off<256; off<<=1){
        float v = (tid >= off) ? tot[tid-off] : -INFINITY;
        __syncthreads();
        tot[tid] = fmaxf(tot[tid], v);
        __syncthreads();
    }
    float em = (tid > 0) ? tot[tid-1] : -INFINITY;
#pragma unroll
    for (int j=0;j<8;j++){
        float rm = fmaxf(em, cml[j]);
        g_rowt[h*SEQ + base + j] = -rm;
        g_expn[h*SEQ + base + j] = expf(-(cs[j] + rm));
    }
}

__global__ void normreduce_kernel()
{
    int idx = blockIdx.x*256 + threadIdx.x;   // h*SEQ + l
    if (idx >= NHEAD*SEQ) return;
    int h = idx >> 11, l = idx & (SEQ-1);
    int nt = (l >> 7) + 1;
    float s = 0.f;
    for (int t=0; t<nt; t++) s += g_psum[((size_t)h*16 + t)*SEQ + l];
    float n = fmaxf(fabsf(s), g_expn[idx]) + 1e-6f;
    g_inrm[idx] = 1.0f / n;
}

__global__ __launch_bounds__(256) void gn_kernel(const float* __restrict__ gnw,
    const float* __restrict__ gnb, const float* __restrict__ skip)
{
    int l = blockIdx.x, tid = threadIdx.x, w = tid >> 5, lane = tid & 31;
    const float* hrow = g_hfl + (size_t)l*DIN + w*DHEAD;
    float vals[8]; float s = 0.f, ss = 0.f;
#pragma unroll
    for (int k2=0;k2<8;k2++){ float v = hrow[lane + k2*32]; vals[k2]=v; s+=v; ss+=v*v; }
#pragma unroll
    for (int off=16; off>0; off>>=1){
        s  += __shfl_xor_sync(0xffffffffu, s,  off);
        ss += __shfl_xor_sync(0xffffffffu, ss, off);
    }
    float mean = s * (1.f/DHEAD);
    float var  = ss * (1.f/DHEAD) - mean*mean;
    float rstd = rsqrtf(var + 1e-5f);
#pragma unroll
    for (int k2=0;k2<8;k2++){
        int c = w*DHEAD + lane + k2*32;
        float hn = (vals[k2] - mean) * rstd;
        float h2 = hn*gnw[c] + gnb[c] + skip[c]*g_xc[(size_t)l*DIN + c];
        float r  = g_proj[(size_t)l*(2*DIN) + DIN + c];
        float sl = r / (1.f + expf(-r));
        g_yin_bf[(size_t)l*DIN + c] = __float2bfloat16_rn(h2 * sl);
    }
}

__global__ void gelu_kernel()
{
    int idx = blockIdx.x*256 + threadIdx.x;
    if (idx >= SEQ*DHID) return;
    int l = idx / DHID, j = idx % DHID;
    float a = g_p[(size_t)l*(2*DHID) + j];
    float z = g_p[(size_t)l*(2*DHID) + DHID + j];
    float t = tanhf(0.7978845608028654f * (a + 0.044715f*a*a*a));
    g_g2_bf[idx] = __float2bfloat16_rn(0.5f * a * (1.f + t) * z);
}

// ---------------- launch ----------------
extern "C" void kernel_launch(void* const* d_in, const int* in_sizes, int n_in,
                              void* d_out, int out_size)
{
    (void)in_sizes; (void)n_in; (void)out_size;
    const float* x    = (const float*)d_in[0];
    const float* ln1w = (const float*)d_in[2];
    const float* winw = (const float*)d_in[3];
    const float* winb = (const float*)d_in[4];
    const float* woutw= (const float*)d_in[5];
    const float* ck   = (const float*)d_in[6];
    const float* cb   = (const float*)d_in[7];
    const float* wq   = (const float*)d_in[8];
    const float* wk   = (const float*)d_in[9];
    const float* wv   = (const float*)d_in[10];
    const float* igw  = (const float*)d_in[11];
    const float* igb  = (const float*)d_in[12];
    const float* fgw  = (const float*)d_in[13];
    const float* fgb  = (const float*)d_in[14];
    const float* gnw  = (const float*)d_in[15];
    const float* gnb  = (const float*)d_in[16];
    const float* skip = (const float*)d_in[17];
    const float* ln2w = (const float*)d_in[18];
    const float* ffnw = (const float*)d_in[19];
    const float* ffnow= (const float*)d_in[20];
    float* out = (float*)d_out;

    static int attr_set = 0;
    if (!attr_set){
        cudaFuncSetAttribute(mma_nt_bf,    cudaFuncAttributeMaxDynamicSharedMemorySize, SMEM_GEMM);
        cudaFuncSetAttribute(mma_nt_b_bf,  cudaFuncAttributeMaxDynamicSharedMemorySize, SMEM_GEMM);
        cudaFuncSetAttribute(mma_score_bf, cudaFuncAttributeMaxDynamicSharedMemorySize, SMEM_GEMM);
        cudaFuncSetAttribute(mma_pav_bf,   cudaFuncAttributeMaxDynamicSharedMemorySize, SMEM_GEMM);
        cudaFuncSetAttribute(gates_kernel, cudaFuncAttributeMaxDynamicSharedMemorySize, 8*3*DIN*4);
        attr_set = 1;
    }

    float *proj,*x2,*p;
    bf16 *hln,*xi,*winwb,*woutwb,*ffnwb,*ffnowb,*wqt,*wkt,*wvt,*xcb,*qb,*kb,*yinb,*hfb,*g2b;
    cudaGetSymbolAddress((void**)&proj,  g_proj);
    cudaGetSymbolAddress((void**)&x2,    g_x2);
    cudaGetSymbolAddress((void**)&p,     g_p);
    cudaGetSymbolAddress((void**)&hln,   g_hln_bf);
    cudaGetSymbolAddress((void**)&xi,    g_xi_bf);
    cudaGetSymbolAddress((void**)&winwb, g_winw_bf);
    cudaGetSymbolAddress((void**)&woutwb,g_woutw_bf);
    cudaGetSymbolAddress((void**)&ffnwb, g_ffnw_bf);
    cudaGetSymbolAddress((void**)&ffnowb,g_ffnow_bf);
    cudaGetSymbolAddress((void**)&wqt,   g_wqt_bf);
    cudaGetSymbolAddress((void**)&wkt,   g_wkt_bf);
    cudaGetSymbolAddress((void**)&wvt,   g_wvt_bf);
    cudaGetSymbolAddress((void**)&xcb,   g_xc_bf);
    cudaGetSymbolAddress((void**)&qb,    g_q_bf);
    cudaGetSymbolAddress((void**)&kb,    g_k_bf);
    cudaGetSymbolAddress((void**)&yinb,  g_yin_bf);
    cudaGetSymbolAddress((void**)&hfb,   g_hf_bf);
    cudaGetSymbolAddress((void**)&g2b,   g_g2_bf);
    float *qf,*kf,*vf,*hfl;
    cudaGetSymbolAddress((void**)&qf, g_q);
    cudaGetSymbolAddress((void**)&kf, g_k);
    cudaGetSymbolAddress((void**)&vf, g_v);
    cudaGetSymbolAddress((void**)&hfl, g_hfl);

    dim3 tb(32, 8);
    // one-time-per-call weight conversions / transposes
    convert_f2bf<<<(2*DIN*DMOD+255)/256, 256>>>(winw,  winwb,  2*DIN*DMOD);
    convert_f2bf<<<(DMOD*DIN+255)/256,   256>>>(woutw, woutwb, DMOD*DIN);
    convert_f2bf<<<(2*DHID*DMOD+255)/256,256>>>(ffnw,  ffnwb,  2*DHID*DMOD);
    convert_f2bf<<<(DMOD*DHID+255)/256,  256>>>(ffnow, ffnowb, DMOD*DHID);
    transpose_w_bf<<<dim3(8,8,NHEAD), tb>>>(wq, wqt);
    transpose_w_bf<<<dim3(8,8,NHEAD), tb>>>(wk, wkt);
    transpose_w_bf<<<dim3(8,8,NHEAD), tb>>>(wv, wvt);

    // 1. hln = LN(x) -> bf16
    layernorm_bf<<<SEQ, 256>>>(x, ln1w, hln, DMOD);
    // 2. proj = hln @ win^T + b  (fp32 full + bf16 xi half)
    mma_nt_bf<<<dim3(4096/BN, SEQ/BM), 256, SMEM_GEMM>>>(hln, winwb, winb, 0,
        proj, xi, DMOD, DMOD, DMOD, 2*DIN, 0, DIN, DIN);
    // 3. xc = silu(conv(xi))  (fp32 + bf16)
    conv_silu_kernel<<<SEQ*DIN/256, 256>>>(ck, cb);
    // 4. q/k from xc, v from xi
    mma_nt_b_bf<<<dim3(2, SEQ/BM, NHEAD), 256, SMEM_GEMM>>>(xcb, wqt, qf, qb,
        DHEAD, DIN, DHEAD, DIN, DHEAD, (long long)DHEAD*DHEAD, DHEAD);
    mma_nt_b_bf<<<dim3(2, SEQ/BM, NHEAD), 256, SMEM_GEMM>>>(xcb, wkt, kf, kb,
        DHEAD, DIN, DHEAD, DIN, DHEAD, (long long)DHEAD*DHEAD, DHEAD);
    mma_nt_b_bf<<<dim3(2, SEQ/BM, NHEAD), 256, SMEM_GEMM>>>(xi,  wvt, vf, (bf16*)0,
        DHEAD, DIN, DHEAD, DIN, DHEAD, (long long)DHEAD*DHEAD, DHEAD);
    // 4b. vt_bf[h][d][m]
    transpose_v_bf<<<dim3(SEQ/32, DHEAD/32, NHEAD), tb>>>();
    // 5. gates (fp32 q,k,v)
    gates_kernel<<<SEQ/8, 256, 8*3*DIN*4>>>(igw, igb, fgw, fgb);
    // 6. per-head scans
    scan_kernel<<<NHEAD, 256>>>();
    // 7. C = (QK^T/16)*D (bf16) + fused tile row-sums
    mma_score_bf<<<dim3(SEQ/BN, SEQ/BM, NHEAD), 256, SMEM_GEMM>>>();
    // 8. reduce partials -> 1/(norm+1e-6)
    normreduce_kernel<<<NHEAD*SEQ/256, 256>>>();
    // 9. hflat = (C*invnorm) @ V
    mma_pav_bf<<<dim3(2, SEQ/BM, NHEAD), 256, SMEM_GEMM>>>();
    // 10. group norm + skip*xc, * silu(res) -> bf16
    gn_kernel<<<SEQ, 256>>>(gnw, gnb, skip);
    // 11. x2 = x + yin @ wout^T
    mma_nt_bf<<<dim3(DMOD/BN, SEQ/BM), 256, SMEM_GEMM>>>(yinb, woutwb, 0, x,
        x2, (bf16*)0, DIN, DIN, DIN, DMOD, DMOD, 0, 0);
    // 12. hf = LN(x2) -> bf16
    layernorm_bf<<<SEQ, 256>>>(x2, ln2w, hfb, DMOD);
    // 13. p = hf @ ffn_win^T
    mma_nt_bf<<<dim3(4096/BN, SEQ/BM), 256, SMEM_GEMM>>>(hfb, ffnwb, 0, 0,
        p, (bf16*)0, DMOD, DMOD, DMOD, 2*DHID, 0, 0, 0);
    // 14. g2 = gelu(a)*z -> bf16
    gelu_kernel<<<SEQ*DHID/256, 256>>>();
    // 15. out = x2 + g2 @ ffn_wout^T
    mma_nt_bf<<<dim3(DMOD/BN, SEQ/BM), 256, SMEM_GEMM>>>(g2b, ffnowb, 0, x2,
        out, (bf16*)0, DHID, DHID, DHID, DMOD, DMOD, 0, 0);
}

// round 5
// speedup vs baseline: 5.9171x; 1.2191x over previous
#include <cuda_runtime.h>
#include <cuda_bf16.h>
#include <math.h>

#define SEQ   2048
#define DMOD  1024
#define DIN   2048
#define NHEAD 8
#define DHEAD 256
#define DHID  2048

typedef __nv_bfloat16 bf16;

// ---------------- scratch (allocation-free: __device__ globals) ----------------
__device__ float g_ig  [NHEAD*SEQ];
__device__ float g_fg  [NHEAD*SEQ];
__device__ float g_rowt[NHEAD*SEQ];
__device__ float g_colt[NHEAD*SEQ];
__device__ float g_expn[NHEAD*SEQ];
__device__ float g_inrm[NHEAD*SEQ];
__device__ float g_psum[NHEAD*16*SEQ];
__device__ float g_hfl [SEQ*DIN];
__device__ float g_x2  [SEQ*DMOD];

__device__ bf16 g_hln_bf [SEQ*DMOD];
__device__ bf16 g_proj_bf[SEQ*2*DIN];
__device__ bf16 g_xc_bf  [SEQ*DIN];
__device__ bf16 g_q_bf   [SEQ*DIN];
__device__ bf16 g_k_bf   [SEQ*DIN];
__device__ bf16 g_v_bf   [SEQ*DIN];
__device__ bf16 g_vt_bf  [(size_t)NHEAD*DHEAD*SEQ];
__device__ bf16 g_C_bf   [(size_t)NHEAD*SEQ*SEQ];
__device__ bf16 g_yin_bf [SEQ*DIN];
__device__ bf16 g_hf_bf  [SEQ*DMOD];
__device__ bf16 g_p_bf   [SEQ*2*DHID];
__device__ bf16 g_g2_bf  [SEQ*DHID];
__device__ bf16 g_winw_bf[2*DIN*DMOD];
__device__ bf16 g_woutw_bf[DMOD*DIN];
__device__ bf16 g_ffnw_bf[2*DHID*DMOD];
__device__ bf16 g_ffnow_bf[DMOD*DHID];
__device__ bf16 g_wqt_bf[NHEAD*DHEAD*DHEAD];
__device__ bf16 g_wkt_bf[NHEAD*DHEAD*DHEAD];
__device__ bf16 g_wvt_bf[NHEAD*DHEAD*DHEAD];

// ---------------- bf16 MMA tile config ----------------
#define BM 128
#define BN 128
#define BKB 64                   // bf16 elements per stage (128B rows)
#define TILEB 16384              // 128 rows x 128B
#define SMEM_GEMM (4*TILEB)      // double-buffered A+B

__device__ __forceinline__ unsigned sw128(unsigned o){ return o ^ ((o>>3)&0x70); }

__device__ __forceinline__ void cp16(void* smem_dst, const void* gsrc){
    unsigned s = (unsigned)__cvta_generic_to_shared(smem_dst);
    asm volatile("cp.async.cg.shared.global [%0], [%1], 16;" :: "r"(s), "l"(gsrc));
}
#define CP_COMMIT() asm volatile("cp.async.commit_group;")
#define CP_WAIT(n)  asm volatile("cp.async.wait_group %0;" :: "n"(n))

__device__ __forceinline__ void ldsm4(unsigned r[4], const void* p){
    unsigned a = (unsigned)__cvta_generic_to_shared(p);
    asm volatile("ldmatrix.sync.aligned.m8n8.x4.shared.b16 {%0,%1,%2,%3}, [%4];"
        : "=r"(r[0]),"=r"(r[1]),"=r"(r[2]),"=r"(r[3]) : "r"(a));
}

#define MMA_BF16(d, a, b) \
  asm volatile("mma.sync.aligned.m16n8k16.row.col.f32.bf16.bf16.f32 " \
    "{%0,%1,%2,%3},{%4,%5,%6,%7},{%8,%9},{%0,%1,%2,%3};" \
    : "+f"((d)[0]),"+f"((d)[1]),"+f"((d)[2]),"+f"((d)[3]) \
    : "r"((a)[0]),"r"((a)[1]),"r"((a)[2]),"r"((a)[3]),"r"((b)[0]),"r"((b)[1]))

__device__ __forceinline__ void stage_bf(const bf16* __restrict__ src, int ld,
      int row0, int k0, char* S, int tid)
{
#pragma unroll
    for (int it=0; it<4; it++){
        int idx = it*256 + tid;
        int r = idx>>3, ch = idx&7;
        cp16(S + sw128(r*128 + ch*16), src + (size_t)(row0+r)*ld + k0 + ch*8);
    }
}

__device__ __forceinline__ void compute_bf(const char* __restrict__ As,
    const char* __restrict__ Bs, float acc[4][4][4], int lane, int wm, int wn)
{
    const int l15 = lane&15, lh = lane>>4, l7 = lane&7, lb3 = (lane>>3)&1;
#pragma unroll
    for (int kk=0;kk<4;kk++){
        unsigned a[4][4];
#pragma unroll
        for (int mt=0;mt<4;mt++)
            ldsm4(a[mt], As + sw128((wm + mt*16 + l15)*128 + (kk*2 + lh)*16));
        unsigned b[2][4];
#pragma unroll
        for (int bp=0;bp<2;bp++){
            unsigned row = wn + bp*16 + lh*8 + l7;
            ldsm4(b[bp], Bs + sw128(row*128 + (kk*2 + lb3)*16));
        }
#pragma unroll
        for (int mt=0;mt<4;mt++)
#pragma unroll
            for (int nt=0;nt<4;nt++)
                MMA_BF16(acc[mt][nt], a[mt], b[nt>>1] + (nt&1)*2);
    }
}

__device__ __forceinline__ void gemm_loop_bf(const bf16* __restrict__ A, int lda,
    const bf16* __restrict__ B, int ldb, int m0, int n0, int K,
    char* SA, char* SB, float acc[4][4][4], int tid, int lane, int wm, int wn)
{
    stage_bf(A, lda, m0, 0, SA, tid);
    stage_bf(B, ldb, n0, 0, SB, tid);
    CP_COMMIT();
    int nsteps = K >> 6;
    for (int s=0; s<nsteps; s++){
        int cur = s&1;
        if (s+1 < nsteps){
            int nb = (s+1)&1;
            stage_bf(A, lda, m0, (s+1)*BKB, SA + nb*TILEB, tid);
            stage_bf(B, ldb, n0, (s+1)*BKB, SB + nb*TILEB, tid);
            CP_COMMIT();
            CP_WAIT(1);
        } else {
            CP_WAIT(0);
        }
        __syncthreads();
        compute_bf(SA + cur*TILEB, SB + cur*TILEB, acc, lane, wm, wn);
        __syncthreads();
    }
}

// ---------------- GEMM kernels ----------------

// C[m,n] = sum_k A[m,k]*B[n,k] (+bias) (+resid); optional fp32 out, optional bf16 out
__global__ __launch_bounds__(256, 2) void mma_nt_bf(
    const bf16* __restrict__ A, const bf16* __restrict__ B,
    const float* __restrict__ bias, const float* __restrict__ resid,
    float* __restrict__ Cf, bf16* __restrict__ Cb,
    int K, int lda, int ldb, int ldc, int ldr, int ldcb)
{
    extern __shared__ char smem[];
    char* SA = smem; char* SB = smem + 2*TILEB;
    const int tid=threadIdx.x, lane=tid&31, wid=tid>>5;
    const int wm=(wid>>2)*64, wn=(wid&3)*32;
    const int m0=blockIdx.y*BM, n0=blockIdx.x*BN;
    float acc[4][4][4] = {};
    gemm_loop_bf(A, lda, B, ldb, m0, n0, K, SA, SB, acc, tid, lane, wm, wn);
    const int gr=lane>>2, gc=lane&3;
#pragma unroll
    for (int mt=0;mt<4;mt++){
#pragma unroll
        for (int nt=0;nt<4;nt++){
            int row = m0+wm+mt*16+gr;
            int col = n0+wn+nt*8+gc*2;
            float b0=0.f,b1=0.f;
            if (bias){ b0=bias[col]; b1=bias[col+1]; }
            float r00=0,r01=0,r10=0,r11=0;
            if (resid){
                const float* rp  = resid + (size_t)row*ldr + col;
                const float* rp2 = resid + (size_t)(row+8)*ldr + col;
                r00=rp[0]; r01=rp[1]; r10=rp2[0]; r11=rp2[1];
            }
            float v00=acc[mt][nt][0]+b0+r00, v01=acc[mt][nt][1]+b1+r01;
            float v10=acc[mt][nt][2]+b0+r10, v11=acc[mt][nt][3]+b1+r11;
            if (Cf){
                *(float2*)(Cf + (size_t)row*ldc + col)     = make_float2(v00,v01);
                *(float2*)(Cf + (size_t)(row+8)*ldc + col) = make_float2(v10,v11);
            }
            if (Cb){
                *(__nv_bfloat162*)(Cb + (size_t)row*ldcb + col)     = __floats2bfloat162_rn(v00,v01);
                *(__nv_bfloat162*)(Cb + (size_t)(row+8)*ldcb + col) = __floats2bfloat162_rn(v10,v11);
            }
        }
    }
}

// batched NT (per-head q/k/v): bf16 out
__global__ __launch_bounds__(256, 2) void mma_nt_b_bf(
    const bf16* __restrict__ A, const bf16* __restrict__ B,
    bf16* __restrict__ Cb,
    int K, int lda, int ldb, int ldc,
    long long sA, long long sB, long long sC)
{
    A  += (long long)blockIdx.z * sA;
    B  += (long long)blockIdx.z * sB;
    Cb += (long long)blockIdx.z * sC;
    extern __shared__ char smem[];
    char* SA = smem; char* SB = smem + 2*TILEB;
    const int tid=threadIdx.x, lane=tid&31, wid=tid>>5;
    const int wm=(wid>>2)*64, wn=(wid&3)*32;
    const int m0=blockIdx.y*BM, n0=blockIdx.x*BN;
    float acc[4][4][4] = {};
    gemm_loop_bf(A, lda, B, ldb, m0, n0, K, SA, SB, acc, tid, lane, wm, wn);
    const int gr=lane>>2, gc=lane&3;
#pragma unroll
    for (int mt=0;mt<4;mt++){
#pragma unroll
        for (int nt=0;nt<4;nt++){
            int row = m0+wm+mt*16+gr;
            int col = n0+wn+nt*8+gc*2;
            *(__nv_bfloat162*)(Cb + (size_t)row*ldc + col)     = __floats2bfloat162_rn(acc[mt][nt][0],acc[mt][nt][1]);
            *(__nv_bfloat162*)(Cb + (size_t)(row+8)*ldc + col) = __floats2bfloat162_rn(acc[mt][nt][2],acc[mt][nt][3]);
        }
    }
}

// scores: C[h][l,m] = (q·k)/16 * exp(rowt[l]+colt[m]) masked; bf16 out + fp32 tile row-sums
__global__ __launch_bounds__(256, 2) void mma_score_bf()
{
    const int h  = blockIdx.z;
    const int l0 = blockIdx.y * BM;
    const int m0 = blockIdx.x * BN;
    if (m0 >= l0 + BM) return;   // fully-masked tile: skipped (never read downstream)
    extern __shared__ char smem[];
    char* SA = smem; char* SB = smem + 2*TILEB;
    const bf16* A = g_q_bf + h*DHEAD;
    const bf16* B = g_k_bf + h*DHEAD;
    const int tid=threadIdx.x, lane=tid&31, wid=tid>>5;
    const int wm=(wid>>2)*64, wn=(wid&3)*32;
    float acc[4][4][4] = {};
    gemm_loop_bf(A, DIN, B, DIN, l0, m0, DHEAD, SA, SB, acc, tid, lane, wm, wn);

    float* sred = (float*)smem;   // reuse after final syncthreads
    const float* rt = g_rowt + h*SEQ;
    const float* ct = g_colt + h*SEQ;
    bf16* Cb = g_C_bf + (size_t)h*SEQ*SEQ;
    const int gr=lane>>2, gc=lane&3;
#pragma unroll
    for (int mt=0;mt<4;mt++){
        int l = l0+wm+mt*16+gr;
        float rl0 = rt[l], rl1 = rt[l+8];
        float rs0 = 0.f, rs1 = 0.f;
#pragma unroll
        for (int nt=0;nt<4;nt++){
            int m = m0+wn+nt*8+gc*2;
            float cm0 = ct[m], cm1 = ct[m+1];
            float v00 = (m   <= l  ) ? acc[mt][nt][0]*0.0625f*expf(rl0+cm0) : 0.f;
            float v01 = (m+1 <= l  ) ? acc[mt][nt][1]*0.0625f*expf(rl0+cm1) : 0.f;
            float v10 = (m   <= l+8) ? acc[mt][nt][2]*0.0625f*expf(rl1+cm0) : 0.f;
            float v11 = (m+1 <= l+8) ? acc[mt][nt][3]*0.0625f*expf(rl1+cm1) : 0.f;
            rs0 += v00 + v01;
            rs1 += v10 + v11;
            *(__nv_bfloat162*)(Cb + (size_t)l*SEQ + m)     = __floats2bfloat162_rn(v00,v01);
            *(__nv_bfloat162*)(Cb + (size_t)(l+8)*SEQ + m) = __floats2bfloat162_rn(v10,v11);
        }
        rs0 += __shfl_xor_sync(0xffffffffu, rs0, 1);
        rs0 += __shfl_xor_sync(0xffffffffu, rs0, 2);
        rs1 += __shfl_xor_sync(0xffffffffu, rs1, 1);
        rs1 += __shfl_xor_sync(0xffffffffu, rs1, 2);
        if (gc == 0){
            sred[(wm+mt*16+gr)*4   + (wid&3)] = rs0;
            sred[(wm+mt*16+gr+8)*4 + (wid&3)] = rs1;
        }
    }
    __syncthreads();
    if (tid < 128){
        float s = sred[tid*4] + sred[tid*4+1] + sred[tid*4+2] + sred[tid*4+3];
        g_psum[((size_t)h*16 + blockIdx.x)*SEQ + l0 + tid] = s;
    }
}

// hflat[l, h*256+d] = invnorm[h,l] * sum_{m<=l} C[h][l,m]*vt[h][d][m]
__global__ __launch_bounds__(256, 2) void mma_pav_bf()
{
    const int h  = blockIdx.z;
    const int l0 = blockIdx.y * BM;
    const int n0 = blockIdx.x * BN;
    extern __shared__ char smem[];
    char* SA = smem; char* SB = smem + 2*TILEB;
    const bf16* A = g_C_bf + (size_t)h*SEQ*SEQ;
    const bf16* B = g_vt_bf + (size_t)h*DHEAD*SEQ;
    const int Kmax = l0 + BM;   // causal bound
    const int tid=threadIdx.x, lane=tid&31, wid=tid>>5;
    const int wm=(wid>>2)*64, wn=(wid&3)*32;
    float acc[4][4][4] = {};
    gemm_loop_bf(A, SEQ, B, SEQ, l0, n0, Kmax, SA, SB, acc, tid, lane, wm, wn);
    const int gr=lane>>2, gc=lane&3;
#pragma unroll
    for (int mt=0;mt<4;mt++){
#pragma unroll
        for (int nt=0;nt<4;nt++){
            int l = l0+wm+mt*16+gr;
            int col = n0+wn+nt*8+gc*2;
            float s0 = g_inrm[h*SEQ + l];
            float s1 = g_inrm[h*SEQ + l + 8];
            float* c0 = g_hfl + (size_t)l*DIN + h*DHEAD + col;
            float* c1 = g_hfl + (size_t)(l+8)*DIN + h*DHEAD + col;
            *(float2*)c0 = make_float2(acc[mt][nt][0]*s0, acc[mt][nt][1]*s0);
            *(float2*)c1 = make_float2(acc[mt][nt][2]*s1, acc[mt][nt][3]*s1);
        }
    }
}

// ---------------- converts / transposes ----------------
// vectorized: 8 elements per thread
__global__ void convert_f2bf8(const float* __restrict__ src, bf16* __restrict__ dst, int n8)
{
    int i = blockIdx.x*256 + threadIdx.x;
    if (i >= n8) return;
    const float4* s = (const float4*)(src + (size_t)i*8);
    float4 a = s[0], b = s[1];
    __nv_bfloat162 o[4] = { __floats2bfloat162_rn(a.x,a.y), __floats2bfloat162_rn(a.z,a.w),
                            __floats2bfloat162_rn(b.x,b.y), __floats2bfloat162_rn(b.z,b.w) };
    *(uint4*)(dst + (size_t)i*8) = *(uint4*)o;
}

// per-head 256x256: out[h][d][k] = in[h][k][d], bf16 out
__global__ void transpose_w_bf(const float* __restrict__ in, bf16* __restrict__ out)
{
    __shared__ float t[32][33];
    int h = blockIdx.z;
    const float* I = in  + (size_t)h*DHEAD*DHEAD;
    bf16*        O = out + (size_t)h*DHEAD*DHEAD;
    int k0 = blockIdx.y*32, d0 = blockIdx.x*32;
    int x = threadIdx.x, y = threadIdx.y;
#pragma unroll
    for (int i=0;i<32;i+=8) t[y+i][x] = I[(size_t)(k0+y+i)*DHEAD + d0 + x];
    __syncthreads();
#pragma unroll
    for (int i=0;i<32;i+=8) O[(size_t)(d0+y+i)*DHEAD + k0 + x] = __float2bfloat16_rn(t[x][y+i]);
}

// vt_bf[h][d][m] = v_bf[m][h*256+d]
__global__ void transpose_v_bf()
{
    __shared__ float t[32][33];
    int h = blockIdx.z;
    int m0 = blockIdx.x*32, d0 = blockIdx.y*32;
    int x = threadIdx.x, y = threadIdx.y;
#pragma unroll
    for (int i=0;i<32;i+=8) t[y+i][x] = __bfloat162float(g_v_bf[(size_t)(m0+y+i)*DIN + h*DHEAD + d0 + x]);
    __syncthreads();
#pragma unroll
    for (int i=0;i<32;i+=8)
        g_vt_bf[((size_t)h*DHEAD + d0+y+i)*SEQ + m0 + x] = __float2bfloat16_rn(t[x][y+i]);
}

// ---------------- elementwise / reduction kernels ----------------
__global__ void layernorm_bf(const float* __restrict__ x, const float* __restrict__ w,
                             bf16* __restrict__ out, int cols)
{
    int row = blockIdx.x, tid = threadIdx.x;
    const float* xr = x + (size_t)row*cols;
    float s = 0.f, ss = 0.f;
    for (int c = tid*4; c < cols; c += 1024){
        float4 v = *(const float4*)(xr + c);
        s += v.x+v.y+v.z+v.w;
        ss += v.x*v.x+v.y*v.y+v.z*v.z+v.w*v.w;
    }
    __shared__ float sh1[256], sh2[256];
    sh1[tid]=s; sh2[tid]=ss; __syncthreads();
    for (int off=128; off>0; off>>=1){
        if (tid < off){ sh1[tid]+=sh1[tid+off]; sh2[tid]+=sh2[tid+off]; }
        __syncthreads();
    }
    float mean = sh1[0] / cols;
    float var  = sh2[0] / cols - mean*mean;
    float rstd = rsqrtf(var + 1e-5f);
    for (int c = tid*4; c < cols; c += 1024){
        float4 v = *(const float4*)(xr + c);
        float4 wv = *(const float4*)(w + c);
        __nv_bfloat162 o0 = __floats2bfloat162_rn((v.x-mean)*rstd*wv.x, (v.y-mean)*rstd*wv.y);
        __nv_bfloat162 o1 = __floats2bfloat162_rn((v.z-mean)*rstd*wv.z, (v.w-mean)*rstd*wv.w);
        *(__nv_bfloat162*)(out + (size_t)row*cols + c)     = o0;
        *(__nv_bfloat162*)(out + (size_t)row*cols + c + 2) = o1;
    }
}

// 8 channels per thread; one block per sequence row
__global__ __launch_bounds__(256) void conv_silu_kernel(const float* __restrict__ ck, const float* __restrict__ cb)
{
    int l = blockIdx.x;
    int c8 = threadIdx.x * 8;
    float acc[8];
    {
        float4 b0 = *(const float4*)(cb + c8);
        float4 b1 = *(const float4*)(cb + c8 + 4);
        acc[0]=b0.x; acc[1]=b0.y; acc[2]=b0.z; acc[3]=b0.w;
        acc[4]=b1.x; acc[5]=b1.y; acc[6]=b1.z; acc[7]=b1.w;
    }
    float4 kt[8];
#pragma unroll
    for (int j=0;j<8;j++) kt[j] = *(const float4*)(ck + (c8+j)*4);   // taps 0..3 for channel
#pragma unroll
    for (int t=0;t<4;t++){
        int ls = l - t;
        if (ls < 0) break;
        uint4 u = *(const uint4*)(g_proj_bf + (size_t)ls*(2*DIN) + c8);
        __nv_bfloat162* bp = (__nv_bfloat162*)&u;
        float tap[8];
#pragma unroll
        for (int j=0;j<4;j++){ float2 f = __bfloat1622float2(bp[j]); tap[2*j]=f.x; tap[2*j+1]=f.y; }
        acc[0] = fmaf(tap[0], ((float*)&kt[0])[t], acc[0]);
        acc[1] = fmaf(tap[1], ((float*)&kt[1])[t], acc[1]);
        acc[2] = fmaf(tap[2], ((float*)&kt[2])[t], acc[2]);
        acc[3] = fmaf(tap[3], ((float*)&kt[3])[t], acc[3]);
        acc[4] = fmaf(tap[4], ((float*)&kt[4])[t], acc[4]);
        acc[5] = fmaf(tap[5], ((float*)&kt[5])[t], acc[5]);
        acc[6] = fmaf(tap[6], ((float*)&kt[6])[t], acc[6]);
        acc[7] = fmaf(tap[7], ((float*)&kt[7])[t], acc[7]);
    }
    __nv_bfloat162 o[4];
#pragma unroll
    for (int j=0;j<4;j++){
        float a0 = acc[2*j],   r0 = a0 / (1.f + expf(-a0));
        float a1 = acc[2*j+1], r1 = a1 / (1.f + expf(-a1));
        o[j] = __floats2bfloat162_rn(r0, r1);
    }
    *(uint4*)(g_xc_bf + (size_t)l*DIN + c8) = *(uint4*)o;
}

// 16 rows per block; each warp = one head; bf16 smem staging
#define GROWS 16
__global__ __launch_bounds__(256) void gates_kernel(
    const float* __restrict__ igw, const float* __restrict__ igb,
    const float* __restrict__ fgw, const float* __restrict__ fgb)
{
    extern __shared__ bf16 gbuf[];   // GROWS * 3*DIN bf16 = 192KB
    int l0 = blockIdx.x*GROWS, tid = threadIdx.x;
    const int CH = DIN/8;   // uint4 chunks per array-row
    for (int i = tid; i < GROWS*3*CH; i += 256){
        int rr = i / (3*CH); int rem = i - rr*3*CH;
        int a = rem / CH;    int ch = rem - a*CH;
        const bf16* src = (a==0 ? g_q_bf : a==1 ? g_k_bf : g_v_bf) + (size_t)(l0+rr)*DIN + ch*8;
        *(uint4*)&gbuf[(size_t)rr*3*DIN + a*DIN + ch*8] = *(const uint4*)src;
    }
    __syncthreads();
    int w = tid >> 5, lane = tid & 31;
    const float* iw = igw + (size_t)w*3*DIN;
    const float* fw = fgw + (size_t)w*3*DIN;
    float si[GROWS] = {}, sf[GROWS] = {};
    for (int j = lane*8; j < 3*DIN; j += 256){
        float4 wi0 = *(const float4*)(iw + j), wi1 = *(const float4*)(iw + j + 4);
        float4 wf0 = *(const float4*)(fw + j), wf1 = *(const float4*)(fw + j + 4);
#pragma unroll
        for (int rr=0; rr<GROWS; rr++){
            uint4 u = *(uint4*)&gbuf[(size_t)rr*3*DIN + j];
            __nv_bfloat162* bp = (__nv_bfloat162*)&u;
            float2 g0 = __bfloat1622float2(bp[0]);
            float2 g1 = __bfloat1622float2(bp[1]);
            float2 g2 = __bfloat1622float2(bp[2]);
            float2 g3 = __bfloat1622float2(bp[3]);
            si[rr] = fmaf(g0.x, wi0.x, si[rr]); si[rr] = fmaf(g0.y, wi0.y, si[rr]);
            si[rr] = fmaf(g1.x, wi0.z, si[rr]); si[rr] = fmaf(g1.y, wi0.w, si[rr]);
            si[rr] = fmaf(g2.x, wi1.x, si[rr]); si[rr] = fmaf(g2.y, wi1.y, si[rr]);
            si[rr] = fmaf(g3.x, wi1.z, si[rr]); si[rr] = fmaf(g3.y, wi1.w, si[rr]);
            sf[rr] = fmaf(g0.x, wf0.x, sf[rr]); sf[rr] = fmaf(g0.y, wf0.y, sf[rr]);
            sf[rr] = fmaf(g1.x, wf0.z, sf[rr]); sf[rr] = fmaf(g1.y, wf0.w, sf[rr]);
            sf[rr] = fmaf(g2.x, wf1.x, sf[rr]); sf[rr] = fmaf(g2.y, wf1.y, sf[rr]);
            sf[rr] = fmaf(g3.x, wf1.z, sf[rr]); sf[rr] = fmaf(g3.y, wf1.w, sf[rr]);
        }
    }
#pragma unroll
    for (int off=16; off>0; off>>=1){
#pragma unroll
        for (int rr=0;rr<GROWS;rr++){
            si[rr] += __shfl_xor_sync(0xffffffffu, si[rr], off);
            sf[rr] += __shfl_xor_sync(0xffffffffu, sf[rr], off);
        }
    }
    if (lane == 0){
#pragma unroll
        for (int rr=0;rr<GROWS;rr++){
            g_ig[w*SEQ + l0+rr] = si[rr] + igb[w];
            g_fg[w*SEQ + l0+rr] = sf[rr] + fgb[w];
        }
    }
}

__global__ __launch_bounds__(256) void scan_kernel()
{
    __shared__ float lf[SEQ];
    __shared__ float tot[256];
    int h = blockIdx.x, tid = threadIdx.x;
    for (int m = tid; m < SEQ; m += 256){
        float f = g_fg[h*SEQ + m];
        lf[m] = fminf(f, 0.f) - log1pf(expf(-fabsf(f)));   // log_sigmoid
    }
    __syncthreads();
    int base = tid * 8;
    float csl[8];
    float run = 0.f;
#pragma unroll
    for (int j=0;j<8;j++){ run += lf[base+j]; csl[j] = run; }
    tot[tid] = run; __syncthreads();
    for (int off=1; off<256; off<<=1){
        float v = (tid >= off) ? tot[tid-off] : 0.f;
        __syncthreads();
        tot[tid] += v;
        __syncthreads();
    }
    float excl = tot[tid] - run;
    float cs[8], cml[8];
    float rmax = -INFINITY;
#pragma unroll
    for (int j=0;j<8;j++){
        cs[j] = csl[j] + excl;
        float col = g_ig[h*SEQ + base + j] - cs[j];
        g_colt[h*SEQ + base + j] = col;
        rmax = fmaxf(rmax, col);
        cml[j] = rmax;
    }
    tot[tid] = rmax; __syncthreads();
    for (int off=1; off<256; off<<=1){
        float v = (tid >= off) ? tot[tid-off] : -INFINITY;
        __syncthreads();
        tot[tid] = fmaxf(tot[tid], v);
        __syncthreads();
    }
    float em = (tid > 0) ? tot[tid-1] : -INFINITY;
#pragma unroll
    for (int j=0;j<8;j++){
        float rm = fmaxf(em, cml[j]);
        g_rowt[h*SEQ + base + j] = -rm;
        g_expn[h*SEQ + base + j] = expf(-(cs[j] + rm));
    }
}

__global__ void normreduce_kernel()
{
    int idx = blockIdx.x*256 + threadIdx.x;   // h*SEQ + l
    if (idx >= NHEAD*SEQ) return;
    int h = idx >> 11, l = idx & (SEQ-1);
    int nt = (l >> 7) + 1;
    float s = 0.f;
    for (int t=0; t<nt; t++) s += g_psum[((size_t)h*16 + t)*SEQ + l];
    float n = fmaxf(fabsf(s), g_expn[idx]) + 1e-6f;
    g_inrm[idx] = 1.0f / n;
}

__global__ __launch_bounds__(256) void gn_kernel(const float* __restrict__ gnw,
    const float* __restrict__ gnb, const float* __restrict__ skip)
{
    int l = blockIdx.x, tid = threadIdx.x, w = tid >> 5, lane = tid & 31;
    int c0 = w*DHEAD + lane*8;
    float4 h0 = *(const float4*)(g_hfl + (size_t)l*DIN + c0);
    float4 h1 = *(const float4*)(g_hfl + (size_t)l*DIN + c0 + 4);
    float vals[8] = {h0.x,h0.y,h0.z,h0.w,h1.x,h1.y,h1.z,h1.w};
    float s = 0.f, ss = 0.f;
#pragma unroll
    for (int j=0;j<8;j++){ s += vals[j]; ss += vals[j]*vals[j]; }
#pragma unroll
    for (int off=16; off>0; off>>=1){
        s  += __shfl_xor_sync(0xffffffffu, s,  off);
        ss += __shfl_xor_sync(0xffffffffu, ss, off);
    }
    float mean = s * (1.f/DHEAD);
    float var  = ss * (1.f/DHEAD) - mean*mean;
    float rstd = rsqrtf(var + 1e-5f);
    float4 gw0 = *(const float4*)(gnw + c0), gw1 = *(const float4*)(gnw + c0 + 4);
    float4 gb0 = *(const float4*)(gnb + c0), gb1 = *(const float4*)(gnb + c0 + 4);
    float4 sk0 = *(const float4*)(skip + c0), sk1 = *(const float4*)(skip + c0 + 4);
    uint4 uxc = *(const uint4*)(g_xc_bf + (size_t)l*DIN + c0);
    uint4 urs = *(const uint4*)(g_proj_bf + (size_t)l*(2*DIN) + DIN + c0);
    float gwv[8] = {gw0.x,gw0.y,gw0.z,gw0.w,gw1.x,gw1.y,gw1.z,gw1.w};
    float gbv[8] = {gb0.x,gb0.y,gb0.z,gb0.w,gb1.x,gb1.y,gb1.z,gb1.w};
    float skv[8] = {sk0.x,sk0.y,sk0.z,sk0.w,sk1.x,sk1.y,sk1.z,sk1.w};
    float xcv[8], rsv[8];
    {
        __nv_bfloat162* bx = (__nv_bfloat162*)&uxc;
        __nv_bfloat162* br = (__nv_bfloat162*)&urs;
#pragma unroll
        for (int j=0;j<4;j++){
            float2 fx = __bfloat1622float2(bx[j]); xcv[2*j]=fx.x; xcv[2*j+1]=fx.y;
            float2 fr = __bfloat1622float2(br[j]); rsv[2*j]=fr.x; rsv[2*j+1]=fr.y;
        }
    }
    __nv_bfloat162 o[4];
#pragma unroll
    for (int j=0;j<4;j++){
        float y0, y1;
        {
            float hn = (vals[2*j] - mean) * rstd;
            float h2 = hn*gwv[2*j] + gbv[2*j] + skv[2*j]*xcv[2*j];
            float r  = rsv[2*j];
            y0 = h2 * (r / (1.f + expf(-r)));
        }
        {
            float hn = (vals[2*j+1] - mean) * rstd;
            float h2 = hn*gwv[2*j+1] + gbv[2*j+1] + skv[2*j+1]*xcv[2*j+1];
            float r  = rsv[2*j+1];
            y1 = h2 * (r / (1.f + expf(-r)));
        }
        o[j] = __floats2bfloat162_rn(y0, y1);
    }
    *(uint4*)(g_yin_bf + (size_t)l*DIN + c0) = *(uint4*)o;
}

__global__ void gelu_kernel()
{
    int idx = blockIdx.x*256 + threadIdx.x;    // 8 elements each
    int l = idx >> 8, j8 = (idx & 255) * 8;
    uint4 ua = *(const uint4*)(g_p_bf + (size_t)l*(2*DHID) + j8);
    uint4 uz = *(const uint4*)(g_p_bf + (size_t)l*(2*DHID) + DHID + j8);
    __nv_bfloat162* ba = (__nv_bfloat162*)&ua;
    __nv_bfloat162* bz = (__nv_bfloat162*)&uz;
    __nv_bfloat162 o[4];
#pragma unroll
    for (int q=0;q<4;q++){
        float2 fa = __bfloat1622float2(ba[q]);
        float2 fz = __bfloat1622float2(bz[q]);
        float t0 = tanhf(0.7978845608028654f * (fa.x + 0.044715f*fa.x*fa.x*fa.x));
        float t1 = tanhf(0.7978845608028654f * (fa.y + 0.044715f*fa.y*fa.y*fa.y));
        o[q] = __floats2bfloat162_rn(0.5f*fa.x*(1.f+t0)*fz.x, 0.5f*fa.y*(1.f+t1)*fz.y);
    }
    *(uint4*)(g_g2_bf + (size_t)l*DHID + j8) = *(uint4*)o;
}

// ---------------- launch ----------------
extern "C" void kernel_launch(void* const* d_in, const int* in_sizes, int n_in,
                              void* d_out, int out_size)
{
    (void)in_sizes; (void)n_in; (void)out_size;
    const float* x    = (const float*)d_in[0];
    const float* ln1w = (const float*)d_in[2];
    const float* winw = (const float*)d_in[3];
    const float* winb = (const float*)d_in[4];
    const float* woutw= (const float*)d_in[5];
    const float* ck   = (const float*)d_in[6];
    const float* cb   = (const float*)d_in[7];
    const float* wq   = (const float*)d_in[8];
    const float* wk   = (const float*)d_in[9];
    const float* wv   = (const float*)d_in[10];
    const float* igw  = (const float*)d_in[11];
    const float* igb  = (const float*)d_in[12];
    const float* fgw  = (const float*)d_in[13];
    const float* fgb  = (const float*)d_in[14];
    const float* gnw  = (const float*)d_in[15];
    const float* gnb  = (const float*)d_in[16];
    const float* skip = (const float*)d_in[17];
    const float* ln2w = (const float*)d_in[18];
    const float* ffnw = (const float*)d_in[19];
    const float* ffnow= (const float*)d_in[20];
    float* out = (float*)d_out;

    static int attr_set = 0;
    if (!attr_set){
        cudaFuncSetAttribute(mma_nt_bf,    cudaFuncAttributeMaxDynamicSharedMemorySize, SMEM_GEMM);
        cudaFuncSetAttribute(mma_nt_b_bf,  cudaFuncAttributeMaxDynamicSharedMemorySize, SMEM_GEMM);
        cudaFuncSetAttribute(mma_score_bf, cudaFuncAttributeMaxDynamicSharedMemorySize, SMEM_GEMM);
        cudaFuncSetAttribute(mma_pav_bf,   cudaFuncAttributeMaxDynamicSharedMemorySize, SMEM_GEMM);
        cudaFuncSetAttribute(gates_kernel, cudaFuncAttributeMaxDynamicSharedMemorySize, GROWS*3*DIN*2);
        attr_set = 1;
    }

    float *x2, *hfl;
    bf16 *hln,*projb,*winwb,*woutwb,*ffnwb,*ffnowb,*wqt,*wkt,*wvt,*xcb,*qb,*kb,*vb,*yinb,*hfb,*pb,*g2b;
    cudaGetSymbolAddress((void**)&x2,    g_x2);
    cudaGetSymbolAddress((void**)&hfl,   g_hfl);
    cudaGetSymbolAddress((void**)&hln,   g_hln_bf);
    cudaGetSymbolAddress((void**)&projb, g_proj_bf);
    cudaGetSymbolAddress((void**)&winwb, g_winw_bf);
    cudaGetSymbolAddress((void**)&woutwb,g_woutw_bf);
    cudaGetSymbolAddress((void**)&ffnwb, g_ffnw_bf);
    cudaGetSymbolAddress((void**)&ffnowb,g_ffnow_bf);
    cudaGetSymbolAddress((void**)&wqt,   g_wqt_bf);
    cudaGetSymbolAddress((void**)&wkt,   g_wkt_bf);
    cudaGetSymbolAddress((void**)&wvt,   g_wvt_bf);
    cudaGetSymbolAddress((void**)&xcb,   g_xc_bf);
    cudaGetSymbolAddress((void**)&qb,    g_q_bf);
    cudaGetSymbolAddress((void**)&kb,    g_k_bf);
    cudaGetSymbolAddress((void**)&vb,    g_v_bf);
    cudaGetSymbolAddress((void**)&yinb,  g_yin_bf);
    cudaGetSymbolAddress((void**)&hfb,   g_hf_bf);
    cudaGetSymbolAddress((void**)&pb,    g_p_bf);
    cudaGetSymbolAddress((void**)&g2b,   g_g2_bf);

    dim3 tb(32, 8);
    // one-time-per-call weight conversions / transposes (vectorized)
    convert_f2bf8<<<(2*DIN*DMOD/8+255)/256, 256>>>(winw,  winwb,  2*DIN*DMOD/8);
    convert_f2bf8<<<(DMOD*DIN/8+255)/256,   256>>>(woutw, woutwb, DMOD*DIN/8);
    convert_f2bf8<<<(2*DHID*DMOD/8+255)/256,256>>>(ffnw,  ffnwb,  2*DHID*DMOD/8);
    convert_f2bf8<<<(DMOD*DHID/8+255)/256,  256>>>(ffnow, ffnowb, DMOD*DHID/8);
    transpose_w_bf<<<dim3(8,8,NHEAD), tb>>>(wq, wqt);
    transpose_w_bf<<<dim3(8,8,NHEAD), tb>>>(wk, wkt);
    transpose_w_bf<<<dim3(8,8,NHEAD), tb>>>(wv, wvt);

    // 1. hln = LN(x) -> bf16
    layernorm_bf<<<SEQ, 256>>>(x, ln1w, hln, DMOD);
    // 2. proj = hln @ win^T + b  -> bf16 only
    mma_nt_bf<<<dim3(4096/BN, SEQ/BM), 256, SMEM_GEMM>>>(hln, winwb, winb, 0,
        (float*)0, projb, DMOD, DMOD, DMOD, 0, 0, 2*DIN);
    // 3. xc = silu(conv(xi)) -> bf16
    conv_silu_kernel<<<SEQ, 256>>>(ck, cb);
    // 4. q/k from xc, v from xi (bf16 out only)
    mma_nt_b_bf<<<dim3(2, SEQ/BM, NHEAD), 256, SMEM_GEMM>>>(xcb, wqt, qb,
        DHEAD, DIN, DHEAD, DIN, DHEAD, (long long)DHEAD*DHEAD, DHEAD);
    mma_nt_b_bf<<<dim3(2, SEQ/BM, NHEAD), 256, SMEM_GEMM>>>(xcb, wkt, kb,
        DHEAD, DIN, DHEAD, DIN, DHEAD, (long long)DHEAD*DHEAD, DHEAD);
    mma_nt_b_bf<<<dim3(2, SEQ/BM, NHEAD), 256, SMEM_GEMM>>>(projb, wvt, vb,
        DHEAD, 2*DIN, DHEAD, DIN, DHEAD, (long long)DHEAD*DHEAD, DHEAD);
    // 4b. vt_bf[h][d][m]
    transpose_v_bf<<<dim3(SEQ/32, DHEAD/32, NHEAD), tb>>>();
    // 5. gates (bf16 q,k,v)
    gates_kernel<<<SEQ/GROWS, 256, GROWS*3*DIN*2>>>(igw, igb, fgw, fgb);
    // 6. per-head scans
    scan_kernel<<<NHEAD, 256>>>();
    // 7. C = (QK^T/16)*D (bf16) + fused tile row-sums
    mma_score_bf<<<dim3(SEQ/BN, SEQ/BM, NHEAD), 256, SMEM_GEMM>>>();
    // 8. reduce partials -> 1/(norm+1e-6)
    normreduce_kernel<<<NHEAD*SEQ/256, 256>>>();
    // 9. hflat = (C*invnorm) @ V
    mma_pav_bf<<<dim3(2, SEQ/BM, NHEAD), 256, SMEM_GEMM>>>();
    // 10. group norm + skip*xc, * silu(res) -> bf16
    gn_kernel<<<SEQ, 256>>>(gnw, gnb, skip);
    // 11. x2 = x + yin @ wout^T  (fp32)
    mma_nt_bf<<<dim3(DMOD/BN, SEQ/BM), 256, SMEM_GEMM>>>(yinb, woutwb, 0, x,
        x2, (bf16*)0, DIN, DIN, DIN, DMOD, DMOD, 0);
    // 12. hf = LN(x2) -> bf16
    layernorm_bf<<<SEQ, 256>>>(x2, ln2w, hfb, DMOD);
    // 13. p = hf @ ffn_win^T -> bf16 only
    mma_nt_bf<<<dim3(4096/BN, SEQ/BM), 256, SMEM_GEMM>>>(hfb, ffnwb, 0, 0,
        (float*)0, pb, DMOD, DMOD, DMOD, 0, 0, 2*DHID);
    // 14. g2 = gelu(a)*z -> bf16
    gelu_kernel<<<SEQ*DHID/8/256, 256>>>();
    // 15. out = x2 + g2 @ ffn_wout^T (fp32)
    mma_nt_bf<<<dim3(DMOD/BN, SEQ/BM), 256, SMEM_GEMM>>>(g2b, ffnowb, 0, x2,
        out, (bf16*)0, DHID, DHID, DHID, DMOD, DMOD, 0);
}

// round 9
// speedup vs baseline: 5.9335x; 1.0028x over previous
#include <cuda_runtime.h>
#include <cuda_bf16.h>
#include <math.h>

#define SEQ   2048
#define DMOD  1024
#define DIN   2048
#define NHEAD 8
#define DHEAD 256
#define DHID  2048

typedef __nv_bfloat16 bf16;

// ---------------- scratch (allocation-free: __device__ globals) ----------------
__device__ float g_ig  [NHEAD*SEQ];
__device__ float g_fg  [NHEAD*SEQ];
__device__ float g_rowt[NHEAD*SEQ];
__device__ float g_colt[NHEAD*SEQ];
__device__ float g_expn[NHEAD*SEQ];
__device__ float g_inrm[NHEAD*SEQ];
__device__ float g_psum[NHEAD*16*SEQ];
__device__ float g_hfl [SEQ*DIN];
__device__ float g_x2  [SEQ*DMOD];

__device__ bf16 g_hln_bf [SEQ*DMOD];
__device__ bf16 g_proj_bf[SEQ*2*DIN];
__device__ bf16 g_xc_bf  [SEQ*DIN];
__device__ bf16 g_q_bf   [SEQ*DIN];
__device__ bf16 g_k_bf   [SEQ*DIN];
__device__ bf16 g_v_bf   [SEQ*DIN];
__device__ bf16 g_vt_bf  [(size_t)NHEAD*DHEAD*SEQ];
__device__ bf16 g_C_bf   [(size_t)NHEAD*SEQ*SEQ];
__device__ bf16 g_yin_bf [SEQ*DIN];
__device__ bf16 g_hf_bf  [SEQ*DMOD];
__device__ bf16 g_p_bf   [SEQ*2*DHID];
__device__ bf16 g_g2_bf  [SEQ*DHID];
__device__ bf16 g_winw_bf[2*DIN*DMOD];
__device__ bf16 g_woutw_bf[DMOD*DIN];
__device__ bf16 g_ffnw_bf[2*DHID*DMOD];
__device__ bf16 g_ffnow_bf[DMOD*DHID];
__device__ bf16 g_wqt_bf[NHEAD*DHEAD*DHEAD];
__device__ bf16 g_wkt_bf[NHEAD*DHEAD*DHEAD];
__device__ bf16 g_wvt_bf[NHEAD*DHEAD*DHEAD];

// ---------------- tile config ----------------
#define BM 128
#define BN 128
#define BKB 64                   // bf16 elements per stage (128B rows)
#define TILEB 16384              // 128 rows x 128B
#define SMEM_GEMM (6*TILEB)      // triple-buffered A+B = 96KB

__device__ __forceinline__ unsigned sw128(unsigned o){ return o ^ ((o>>3)&0x70); }

__device__ __forceinline__ void cp16(void* smem_dst, const void* gsrc){
    unsigned s = (unsigned)__cvta_generic_to_shared(smem_dst);
    asm volatile("cp.async.cg.shared.global [%0], [%1], 16;" :: "r"(s), "l"(gsrc));
}
#define CP_COMMIT() asm volatile("cp.async.commit_group;")
#define CP_WAIT(n)  asm volatile("cp.async.wait_group %0;" :: "n"(n))

__device__ __forceinline__ void ldsm4(unsigned r[4], const void* p){
    unsigned a = (unsigned)__cvta_generic_to_shared(p);
    asm volatile("ldmatrix.sync.aligned.m8n8.x4.shared.b16 {%0,%1,%2,%3}, [%4];"
        : "=r"(r[0]),"=r"(r[1]),"=r"(r[2]),"=r"(r[3]) : "r"(a));
}

#define MMA_BF16(d, a, b) \
  asm volatile("mma.sync.aligned.m16n8k16.row.col.f32.bf16.bf16.f32 " \
    "{%0,%1,%2,%3},{%4,%5,%6,%7},{%8,%9},{%0,%1,%2,%3};" \
    : "+f"((d)[0]),"+f"((d)[1]),"+f"((d)[2]),"+f"((d)[3]) \
    : "r"((a)[0]),"r"((a)[1]),"r"((a)[2]),"r"((a)[3]),"r"((b)[0]),"r"((b)[1]))

// fast-math helpers (bit-invisible under bf16 output quantization — verified R7==R8)
__device__ __forceinline__ float ftanh(float x){
    float y; asm("tanh.approx.f32 %0, %1;" : "=f"(y) : "f"(x)); return y;
}
__device__ __forceinline__ float fsigmoid(float x){ return 1.f / (1.f + __expf(-x)); }

__device__ __forceinline__ void stage_bf(const bf16* __restrict__ src, int ld,
      int row0, int k0, char* S, int tid)
{
#pragma unroll
    for (int it=0; it<4; it++){
        int idx = it*256 + tid;
        int r = idx>>3, ch = idx&7;
        cp16(S + sw128(r*128 + ch*16), src + (size_t)(row0+r)*ld + k0 + ch*8);
    }
}

__device__ __forceinline__ void compute_bf(const char* __restrict__ As,
    const char* __restrict__ Bs, float acc[4][4][4], int lane, int wm, int wn)
{
    const int l15 = lane&15, lh = lane>>4, l7 = lane&7, lb3 = (lane>>3)&1;
#pragma unroll
    for (int kk=0;kk<4;kk++){
        unsigned a[4][4];
#pragma unroll
        for (int mt=0;mt<4;mt++)
            ldsm4(a[mt], As + sw128((wm + mt*16 + l15)*128 + (kk*2 + lh)*16));
        unsigned b[2][4];
#pragma unroll
        for (int bp=0;bp<2;bp++){
            unsigned row = wn + bp*16 + lh*8 + l7;
            ldsm4(b[bp], Bs + sw128(row*128 + (kk*2 + lb3)*16));
        }
#pragma unroll
        for (int mt=0;mt<4;mt++)
#pragma unroll
            for (int nt=0;nt<4;nt++)
                MMA_BF16(acc[mt][nt], a[mt], b[nt>>1] + (nt&1)*2);
    }
}

// 3-stage cp.async pipeline, one barrier per K-step (bit-exact vs 2-stage)
__device__ __forceinline__ void gemm_loop_bf(const bf16* __restrict__ A, int lda,
    const bf16* __restrict__ B, int ldb, int m0, int n0, int K,
    char* smem, float acc[4][4][4], int tid, int lane, int wm, int wn)
{
    const int nsteps = K >> 6;
    stage_bf(A, lda, m0, 0, smem, tid);
    stage_bf(B, ldb, n0, 0, smem + TILEB, tid);
    CP_COMMIT();
    if (nsteps > 1){
        stage_bf(A, lda, m0, BKB, smem + 2*TILEB, tid);
        stage_bf(B, ldb, n0, BKB, smem + 3*TILEB, tid);
        CP_COMMIT();
    }
    for (int s=0; s<nsteps; s++){
        if (s+1 < nsteps) { CP_WAIT(1); } else { CP_WAIT(0); }
        __syncthreads();
        if (s+2 < nsteps){
            char* T = smem + ((s+2)%3)*2*TILEB;
            stage_bf(A, lda, m0, (s+2)*BKB, T, tid);
            stage_bf(B, ldb, n0, (s+2)*BKB, T + TILEB, tid);
            CP_COMMIT();
        }
        char* Cur = smem + (s%3)*2*TILEB;
        compute_bf(Cur, Cur + TILEB, acc, lane, wm, wn);
    }
    __syncthreads();   // smem safe for reuse after loop
}

// ---------------- GEMM kernels ----------------

// C[m,n] = sum_k A[m,k]*B[n,k] (+bias) (+resid); optional fp32 out, optional bf16 out
__global__ __launch_bounds__(256, 2) void mma_nt_bf(
    const bf16* __restrict__ A, const bf16* __restrict__ B,
    const float* __restrict__ bias, const float* __restrict__ resid,
    float* __restrict__ Cf, bf16* __restrict__ Cb,
    int K, int lda, int ldb, int ldc, int ldr, int ldcb)
{
    extern __shared__ char smem[];
    const int tid=threadIdx.x, lane=tid&31, wid=tid>>5;
    const int wm=(wid>>2)*64, wn=(wid&3)*32;
    const int m0=blockIdx.y*BM, n0=blockIdx.x*BN;
    float acc[4][4][4] = {};
    gemm_loop_bf(A, lda, B, ldb, m0, n0, K, smem, acc, tid, lane, wm, wn);
    const int gr=lane>>2, gc=lane&3;
#pragma unroll
    for (int mt=0;mt<4;mt++){
#pragma unroll
        for (int nt=0;nt<4;nt++){
            int row = m0+wm+mt*16+gr;
            int col = n0+wn+nt*8+gc*2;
            float b0=0.f,b1=0.f;
            if (bias){ b0=bias[col]; b1=bias[col+1]; }
            float r00=0,r01=0,r10=0,r11=0;
            if (resid){
                const float* rp  = resid + (size_t)row*ldr + col;
                const float* rp2 = resid + (size_t)(row+8)*ldr + col;
                r00=rp[0]; r01=rp[1]; r10=rp2[0]; r11=rp2[1];
            }
            float v00=acc[mt][nt][0]+b0+r00, v01=acc[mt][nt][1]+b1+r01;
            float v10=acc[mt][nt][2]+b0+r10, v11=acc[mt][nt][3]+b1+r11;
            if (Cf){
                *(float2*)(Cf + (size_t)row*ldc + col)     = make_float2(v00,v01);
                *(float2*)(Cf + (size_t)(row+8)*ldc + col) = make_float2(v10,v11);
            }
            if (Cb){
                *(__nv_bfloat162*)(Cb + (size_t)row*ldcb + col)     = __floats2bfloat162_rn(v00,v01);
                *(__nv_bfloat162*)(Cb + (size_t)(row+8)*ldcb + col) = __floats2bfloat162_rn(v10,v11);
            }
        }
    }
}

// fused q/k/v: grid.z = which*NHEAD + h.
// NOTE: per-head input slice — A is offset by h*DHEAD columns (head_lin semantics).
__global__ __launch_bounds__(256, 2) void mma_qkv()
{
    const int z = blockIdx.z;
    const int which = z >> 3;      // 0=q, 1=k, 2=v
    const int h = z & 7;
    const bf16* A; int lda; const bf16* B; bf16* C;
    if (which == 0){ A = g_xc_bf   + h*DHEAD; lda = DIN;   B = g_wqt_bf + h*DHEAD*DHEAD; C = g_q_bf + h*DHEAD; }
    else if (which == 1){ A = g_xc_bf + h*DHEAD; lda = DIN; B = g_wkt_bf + h*DHEAD*DHEAD; C = g_k_bf + h*DHEAD; }
    else { A = g_proj_bf + h*DHEAD; lda = 2*DIN; B = g_wvt_bf + h*DHEAD*DHEAD; C = g_v_bf + h*DHEAD; }
    extern __shared__ char smem[];
    const int tid=threadIdx.x, lane=tid&31, wid=tid>>5;
    const int wm=(wid>>2)*64, wn=(wid&3)*32;
    const int m0=blockIdx.y*BM, n0=blockIdx.x*BN;
    float acc[4][4][4] = {};
    gemm_loop_bf(A, lda, B, DHEAD, m0, n0, DHEAD, smem, acc, tid, lane, wm, wn);
    const int gr=lane>>2, gc=lane&3;
#pragma unroll
    for (int mt=0;mt<4;mt++){
#pragma unroll
        for (int nt=0;nt<4;nt++){
            int row = m0+wm+mt*16+gr;
            int col = n0+wn+nt*8+gc*2;
            *(__nv_bfloat162*)(C + (size_t)row*DIN + col)     = __floats2bfloat162_rn(acc[mt][nt][0],acc[mt][nt][1]);
            *(__nv_bfloat162*)(C + (size_t)(row+8)*DIN + col) = __floats2bfloat162_rn(acc[mt][nt][2],acc[mt][nt][3]);
        }
    }
}

// scores: C[h][l,m] = (q·k)/16 * exp(rowt[l]+colt[m]) masked; bf16 out + fp32 tile row-sums
__global__ __launch_bounds__(256, 2) void mma_score_bf()
{
    const int h  = blockIdx.z;
    const int l0 = blockIdx.y * BM;
    const int m0 = blockIdx.x * BN;
    if (m0 >= l0 + BM) return;   // fully-masked tile: skipped (never read downstream)
    extern __shared__ char smem[];
    const bf16* A = g_q_bf + h*DHEAD;
    const bf16* B = g_k_bf + h*DHEAD;
    const int tid=threadIdx.x, lane=tid&31, wid=tid>>5;
    const int wm=(wid>>2)*64, wn=(wid&3)*32;
    float acc[4][4][4] = {};
    gemm_loop_bf(A, DIN, B, DIN, l0, m0, DHEAD, smem, acc, tid, lane, wm, wn);

    float* sred = (float*)smem;   // safe: gemm_loop ends with syncthreads
    const float* rt = g_rowt + h*SEQ;
    const float* ct = g_colt + h*SEQ;
    bf16* Cb = g_C_bf + (size_t)h*SEQ*SEQ;
    const int gr=lane>>2, gc=lane&3;
#pragma unroll
    for (int mt=0;mt<4;mt++){
        int l = l0+wm+mt*16+gr;
        float rl0 = rt[l], rl1 = rt[l+8];
        float rs0 = 0.f, rs1 = 0.f;
#pragma unroll
        for (int nt=0;nt<4;nt++){
            int m = m0+wn+nt*8+gc*2;
            float cm0 = ct[m], cm1 = ct[m+1];
            float v00 = (m   <= l  ) ? acc[mt][nt][0]*0.0625f*__expf(rl0+cm0) : 0.f;
            float v01 = (m+1 <= l  ) ? acc[mt][nt][1]*0.0625f*__expf(rl0+cm1) : 0.f;
            float v10 = (m   <= l+8) ? acc[mt][nt][2]*0.0625f*__expf(rl1+cm0) : 0.f;
            float v11 = (m+1 <= l+8) ? acc[mt][nt][3]*0.0625f*__expf(rl1+cm1) : 0.f;
            rs0 += v00 + v01;
            rs1 += v10 + v11;
            *(__nv_bfloat162*)(Cb + (size_t)l*SEQ + m)     = __floats2bfloat162_rn(v00,v01);
            *(__nv_bfloat162*)(Cb + (size_t)(l+8)*SEQ + m) = __floats2bfloat162_rn(v10,v11);
        }
        rs0 += __shfl_xor_sync(0xffffffffu, rs0, 1);
        rs0 += __shfl_xor_sync(0xffffffffu, rs0, 2);
        rs1 += __shfl_xor_sync(0xffffffffu, rs1, 1);
        rs1 += __shfl_xor_sync(0xffffffffu, rs1, 2);
        if (gc == 0){
            sred[(wm+mt*16+gr)*4   + (wid&3)] = rs0;
            sred[(wm+mt*16+gr+8)*4 + (wid&3)] = rs1;
        }
    }
    __syncthreads();
    if (tid < 128){
        float s = sred[tid*4] + sred[tid*4+1] + sred[tid*4+2] + sred[tid*4+3];
        g_psum[((size_t)h*16 + blockIdx.x)*SEQ + l0 + tid] = s;
    }
}

// hflat[l, h*256+d] = invnorm[h,l] * sum_{m<=l} C[h][l,m]*vt[h][d][m]
__global__ __launch_bounds__(256, 2) void mma_pav_bf()
{
    const int h  = blockIdx.z;
    const int l0 = blockIdx.y * BM;
    const int n0 = blockIdx.x * BN;
    extern __shared__ char smem[];
    const bf16* A = g_C_bf + (size_t)h*SEQ*SEQ;
    const bf16* B = g_vt_bf + (size_t)h*DHEAD*SEQ;
    const int Kmax = l0 + BM;   // causal bound
    const int tid=threadIdx.x, lane=tid&31, wid=tid>>5;
    const int wm=(wid>>2)*64, wn=(wid&3)*32;
    float acc[4][4][4] = {};
    gemm_loop_bf(A, SEQ, B, SEQ, l0, n0, Kmax, smem, acc, tid, lane, wm, wn);
    const int gr=lane>>2, gc=lane&3;
#pragma unroll
    for (int mt=0;mt<4;mt++){
#pragma unroll
        for (int nt=0;nt<4;nt++){
            int l = l0+wm+mt*16+gr;
            int col = n0+wn+nt*8+gc*2;
            float s0 = g_inrm[h*SEQ + l];
            float s1 = g_inrm[h*SEQ + l + 8];
            float* c0 = g_hfl + (size_t)l*DIN + h*DHEAD + col;
            float* c1 = g_hfl + (size_t)(l+8)*DIN + h*DHEAD + col;
            *(float2*)c0 = make_float2(acc[mt][nt][0]*s0, acc[mt][nt][1]*s0);
            *(float2*)c1 = make_float2(acc[mt][nt][2]*s1, acc[mt][nt][3]*s1);
        }
    }
}

// ---------------- converts / transposes ----------------
__global__ void convert_f2bf8(const float* __restrict__ src, bf16* __restrict__ dst, int n8)
{
    int i = blockIdx.x*256 + threadIdx.x;
    if (i >= n8) return;
    const float4* s = (const float4*)(src + (size_t)i*8);
    float4 a = s[0], b = s[1];
    __nv_bfloat162 o[4] = { __floats2bfloat162_rn(a.x,a.y), __floats2bfloat162_rn(a.z,a.w),
                            __floats2bfloat162_rn(b.x,b.y), __floats2bfloat162_rn(b.z,b.w) };
    *(uint4*)(dst + (size_t)i*8) = *(uint4*)o;
}

__global__ void transpose_w_bf(const float* __restrict__ in, bf16* __restrict__ out)
{
    __shared__ float t[32][33];
    int h = blockIdx.z;
    const float* I = in  + (size_t)h*DHEAD*DHEAD;
    bf16*        O = out + (size_t)h*DHEAD*DHEAD;
    int k0 = blockIdx.y*32, d0 = blockIdx.x*32;
    int x = threadIdx.x, y = threadIdx.y;
#pragma unroll
    for (int i=0;i<32;i+=8) t[y+i][x] = I[(size_t)(k0+y+i)*DHEAD + d0 + x];
    __syncthreads();
#pragma unroll
    for (int i=0;i<32;i+=8) O[(size_t)(d0+y+i)*DHEAD + k0 + x] = __float2bfloat16_rn(t[x][y+i]);
}

__global__ void transpose_v_bf()
{
    __shared__ float t[32][33];
    int h = blockIdx.z;
    int m0 = blockIdx.x*32, d0 = blockIdx.y*32;
    int x = threadIdx.x, y = threadIdx.y;
#pragma unroll
    for (int i=0;i<32;i+=8) t[y+i][x] = __bfloat162float(g_v_bf[(size_t)(m0+y+i)*DIN + h*DHEAD + d0 + x]);
    __syncthreads();
#pragma unroll
    for (int i=0;i<32;i+=8)
        g_vt_bf[((size_t)h*DHEAD + d0+y+i)*SEQ + m0 + x] = __float2bfloat16_rn(t[x][y+i]);
}

// ---------------- elementwise / reduction kernels ----------------
__global__ void layernorm_bf(const float* __restrict__ x, const float* __restrict__ w,
                             bf16* __restrict__ out, int cols)
{
    int row = blockIdx.x, tid = threadIdx.x;
    const float* xr = x + (size_t)row*cols;
    float s = 0.f, ss = 0.f;
    for (int c = tid*4; c < cols; c += 1024){
        float4 v = *(const float4*)(xr + c);
        s += v.x+v.y+v.z+v.w;
        ss += v.x*v.x+v.y*v.y+v.z*v.z+v.w*v.w;
    }
    __shared__ float sh1[256], sh2[256];
    sh1[tid]=s; sh2[tid]=ss; __syncthreads();
    for (int off=128; off>0; off>>=1){
        if (tid < off){ sh1[tid]+=sh1[tid+off]; sh2[tid]+=sh2[tid+off]; }
        __syncthreads();
    }
    float mean = sh1[0] / cols;
    float var  = sh2[0] / cols - mean*mean;
    float rstd = rsqrtf(var + 1e-5f);
    for (int c = tid*4; c < cols; c += 1024){
        float4 v = *(const float4*)(xr + c);
        float4 wv = *(const float4*)(w + c);
        __nv_bfloat162 o0 = __floats2bfloat162_rn((v.x-mean)*rstd*wv.x, (v.y-mean)*rstd*wv.y);
        __nv_bfloat162 o1 = __floats2bfloat162_rn((v.z-mean)*rstd*wv.z, (v.w-mean)*rstd*wv.w);
        *(__nv_bfloat162*)(out + (size_t)row*cols + c)     = o0;
        *(__nv_bfloat162*)(out + (size_t)row*cols + c + 2) = o1;
    }
}

__global__ __launch_bounds__(256) void conv_silu_kernel(const float* __restrict__ ck, const float* __restrict__ cb)
{
    int l = blockIdx.x;
    int c8 = threadIdx.x * 8;
    float acc[8];
    {
        float4 b0 = *(const float4*)(cb + c8);
        float4 b1 = *(const float4*)(cb + c8 + 4);
        acc[0]=b0.x; acc[1]=b0.y; acc[2]=b0.z; acc[3]=b0.w;
        acc[4]=b1.x; acc[5]=b1.y; acc[6]=b1.z; acc[7]=b1.w;
    }
    float4 kt[8];
#pragma unroll
    for (int j=0;j<8;j++) kt[j] = *(const float4*)(ck + (c8+j)*4);
#pragma unroll
    for (int t=0;t<4;t++){
        int ls = l - t;
        if (ls < 0) break;
        uint4 u = *(const uint4*)(g_proj_bf + (size_t)ls*(2*DIN) + c8);
        __nv_bfloat162* bp = (__nv_bfloat162*)&u;
        float tap[8];
#pragma unroll
        for (int j=0;j<4;j++){ float2 f = __bfloat1622float2(bp[j]); tap[2*j]=f.x; tap[2*j+1]=f.y; }
#pragma unroll
        for (int j=0;j<8;j++)
            acc[j] = fmaf(tap[j], ((float*)&kt[j])[t], acc[j]);
    }
    __nv_bfloat162 o[4];
#pragma unroll
    for (int j=0;j<4;j++){
        float a0 = acc[2*j],   r0 = a0 * fsigmoid(a0);
        float a1 = acc[2*j+1], r1 = a1 * fsigmoid(a1);
        o[j] = __floats2bfloat162_rn(r0, r1);
    }
    *(uint4*)(g_xc_bf + (size_t)l*DIN + c8) = *(uint4*)o;
}

#define GROWS 16
__global__ __launch_bounds__(256) void gates_kernel(
    const float* __restrict__ igw, const float* __restrict__ igb,
    const float* __restrict__ fgw, const float* __restrict__ fgb)
{
    extern __shared__ bf16 gbuf[];
    int l0 = blockIdx.x*GROWS, tid = threadIdx.x;
    const int CH = DIN/8;
    for (int i = tid; i < GROWS*3*CH; i += 256){
        int rr = i / (3*CH); int rem = i - rr*3*CH;
        int a = rem / CH;    int ch = rem - a*CH;
        const bf16* src = (a==0 ? g_q_bf : a==1 ? g_k_bf : g_v_bf) + (size_t)(l0+rr)*DIN + ch*8;
        *(uint4*)&gbuf[(size_t)rr*3*DIN + a*DIN + ch*8] = *(const uint4*)src;
    }
    __syncthreads();
    int w = tid >> 5, lane = tid & 31;
    const float* iw = igw + (size_t)w*3*DIN;
    const float* fw = fgw + (size_t)w*3*DIN;
    float si[GROWS] = {}, sf[GROWS] = {};
    for (int j = lane*8; j < 3*DIN; j += 256){
        float4 wi0 = *(const float4*)(iw + j), wi1 = *(const float4*)(iw + j + 4);
        float4 wf0 = *(const float4*)(fw + j), wf1 = *(const float4*)(fw + j + 4);
#pragma unroll
        for (int rr=0; rr<GROWS; rr++){
            uint4 u = *(uint4*)&gbuf[(size_t)rr*3*DIN + j];
            __nv_bfloat162* bp = (__nv_bfloat162*)&u;
            float2 g0 = __bfloat1622float2(bp[0]);
            float2 g1 = __bfloat1622float2(bp[1]);
            float2 g2 = __bfloat1622float2(bp[2]);
            float2 g3 = __bfloat1622float2(bp[3]);
            si[rr] = fmaf(g0.x, wi0.x, si[rr]); si[rr] = fmaf(g0.y, wi0.y, si[rr]);
            si[rr] = fmaf(g1.x, wi0.z, si[rr]); si[rr] = fmaf(g1.y, wi0.w, si[rr]);
            si[rr] = fmaf(g2.x, wi1.x, si[rr]); si[rr] = fmaf(g2.y, wi1.y, si[rr]);
            si[rr] = fmaf(g3.x, wi1.z, si[rr]); si[rr] = fmaf(g3.y, wi1.w, si[rr]);
            sf[rr] = fmaf(g0.x, wf0.x, sf[rr]); sf[rr] = fmaf(g0.y, wf0.y, sf[rr]);
            sf[rr] = fmaf(g1.x, wf0.z, sf[rr]); sf[rr] = fmaf(g1.y, wf0.w, sf[rr]);
            sf[rr] = fmaf(g2.x, wf1.x, sf[rr]); sf[rr] = fmaf(g2.y, wf1.y, sf[rr]);
            sf[rr] = fmaf(g3.x, wf1.z, sf[rr]); sf[rr] = fmaf(g3.y, wf1.w, sf[rr]);
        }
    }
#pragma unroll
    for (int off=16; off>0; off>>=1){
#pragma unroll
        for (int rr=0;rr<GROWS;rr++){
            si[rr] += __shfl_xor_sync(0xffffffffu, si[rr], off);
            sf[rr] += __shfl_xor_sync(0xffffffffu, sf[rr], off);
        }
    }
    if (lane == 0){
#pragma unroll
        for (int rr=0;rr<GROWS;rr++){
            g_ig[w*SEQ + l0+rr] = si[rr] + igb[w];
            g_fg[w*SEQ + l0+rr] = sf[rr] + fgb[w];
        }
    }
}

__global__ __launch_bounds__(256) void scan_kernel()
{
    __shared__ float lf[SEQ];
    __shared__ float tot[256];
    int h = blockIdx.x, tid = threadIdx.x;
    for (int m = tid; m < SEQ; m += 256){
        float f = g_fg[h*SEQ + m];
        lf[m] = fminf(f, 0.f) - log1pf(expf(-fabsf(f)));
    }
    __syncthreads();
    int base = tid * 8;
    float csl[8];
    float run = 0.f;
#pragma unroll
    for (int j=0;j<8;j++){ run += lf[base+j]; csl[j] = run; }
    tot[tid] = run; __syncthreads();
    for (int off=1; off<256; off<<=1){
        float v = (tid >= off) ? tot[tid-off] : 0.f;
        __syncthreads();
        tot[tid] += v;
        __syncthreads();
    }
    float excl = tot[tid] - run;
    float cs[8], cml[8];
    float rmax = -INFINITY;
#pragma unroll
    for (int j=0;j<8;j++){
        cs[j] = csl[j] + excl;
        float col = g_ig[h*SEQ + base + j] - cs[j];
        g_colt[h*SEQ + base + j] = col;
        rmax = fmaxf(rmax, col);
        cml[j] = rmax;
    }
    tot[tid] = rmax; __syncthreads();
    for (int off=1; off<256; off<<=1){
        float v = (tid >= off) ? tot[tid-off] : -INFINITY;
        __syncthreads();
        tot[tid] = fmaxf(tot[tid], v);
        __syncthreads();
    }
    float em = (tid > 0) ? tot[tid-1] : -INFINITY;
#pragma unroll
    for (int j=0;j<8;j++){
        float rm = fmaxf(em, cml[j]);
        g_rowt[h*SEQ + base + j] = -rm;
        g_expn[h*SEQ + base + j] = expf(-(cs[j] + rm));
    }
}

__global__ void normreduce_kernel()
{
    int idx = blockIdx.x*256 + threadIdx.x;
    if (idx >= NHEAD*SEQ) return;
    int h = idx >> 11, l = idx & (SEQ-1);
    int nt = (l >> 7) + 1;
    float s = 0.f;
    for (int t=0; t<nt; t++) s += g_psum[((size_t)h*16 + t)*SEQ + l];
    float n = fmaxf(fabsf(s), g_expn[idx]) + 1e-6f;
    g_inrm[idx] = 1.0f / n;
}

__global__ __launch_bounds__(256) void gn_kernel(const float* __restrict__ gnw,
    const float* __restrict__ gnb, const float* __restrict__ skip)
{
    int l = blockIdx.x, tid = threadIdx.x, w = tid >> 5, lane = tid & 31;
    int c0 = w*DHEAD + lane*8;
    float4 h0 = *(const float4*)(g_hfl + (size_t)l*DIN + c0);
    float4 h1 = *(const float4*)(g_hfl + (size_t)l*DIN + c0 + 4);
    float vals[8] = {h0.x,h0.y,h0.z,h0.w,h1.x,h1.y,h1.z,h1.w};
    float s = 0.f, ss = 0.f;
#pragma unroll
    for (int j=0;j<8;j++){ s += vals[j]; ss += vals[j]*vals[j]; }
#pragma unroll
    for (int off=16; off>0; off>>=1){
        s  += __shfl_xor_sync(0xffffffffu, s,  off);
        ss += __shfl_xor_sync(0xffffffffu, ss, off);
    }
    float mean = s * (1.f/DHEAD);
    float var  = ss * (1.f/DHEAD) - mean*mean;
    float rstd = rsqrtf(var + 1e-5f);
    float4 gw0 = *(const float4*)(gnw + c0), gw1 = *(const float4*)(gnw + c0 + 4);
    float4 gb0 = *(const float4*)(gnb + c0), gb1 = *(const float4*)(gnb + c0 + 4);
    float4 sk0 = *(const float4*)(skip + c0), sk1 = *(const float4*)(skip + c0 + 4);
    uint4 uxc = *(const uint4*)(g_xc_bf + (size_t)l*DIN + c0);
    uint4 urs = *(const uint4*)(g_proj_bf + (size_t)l*(2*DIN) + DIN + c0);
    float gwv[8] = {gw0.x,gw0.y,gw0.z,gw0.w,gw1.x,gw1.y,gw1.z,gw1.w};
    float gbv[8] = {gb0.x,gb0.y,gb0.z,gb0.w,gb1.x,gb1.y,gb1.z,gb1.w};
    float skv[8] = {sk0.x,sk0.y,sk0.z,sk0.w,sk1.x,sk1.y,sk1.z,sk1.w};
    float xcv[8], rsv[8];
    {
        __nv_bfloat162* bx = (__nv_bfloat162*)&uxc;
        __nv_bfloat162* br = (__nv_bfloat162*)&urs;
#pragma unroll
        for (int j=0;j<4;j++){
            float2 fx = __bfloat1622float2(bx[j]); xcv[2*j]=fx.x; xcv[2*j+1]=fx.y;
            float2 fr = __bfloat1622float2(br[j]); rsv[2*j]=fr.x; rsv[2*j+1]=fr.y;
        }
    }
    __nv_bfloat162 o[4];
#pragma unroll
    for (int j=0;j<4;j++){
        float y0, y1;
        {
            float hn = (vals[2*j] - mean) * rstd;
            float h2 = hn*gwv[2*j] + gbv[2*j] + skv[2*j]*xcv[2*j];
            float r  = rsv[2*j];
            y0 = h2 * (r * fsigmoid(r));
        }
        {
            float hn = (vals[2*j+1] - mean) * rstd;
            float h2 = hn*gwv[2*j+1] + gbv[2*j+1] + skv[2*j+1]*xcv[2*j+1];
            float r  = rsv[2*j+1];
            y1 = h2 * (r * fsigmoid(r));
        }
        o[j] = __floats2bfloat162_rn(y0, y1);
    }
    *(uint4*)(g_yin_bf + (size_t)l*DIN + c0) = *(uint4*)o;
}

__global__ void gelu_kernel()
{
    int idx = blockIdx.x*256 + threadIdx.x;
    int l = idx >> 8, j8 = (idx & 255) * 8;
    uint4 ua = *(const uint4*)(g_p_bf + (size_t)l*(2*DHID) + j8);
    uint4 uz = *(const uint4*)(g_p_bf + (size_t)l*(2*DHID) + DHID + j8);
    __nv_bfloat162* ba = (__nv_bfloat162*)&ua;
    __nv_bfloat162* bz = (__nv_bfloat162*)&uz;
    __nv_bfloat162 o[4];
#pragma unroll
    for (int q=0;q<4;q++){
        float2 fa = __bfloat1622float2(ba[q]);
        float2 fz = __bfloat1622float2(bz[q]);
        float t0 = ftanh(0.7978845608028654f * (fa.x + 0.044715f*fa.x*fa.x*fa.x));
        float t1 = ftanh(0.7978845608028654f * (fa.y + 0.044715f*fa.y*fa.y*fa.y));
        o[q] = __floats2bfloat162_rn(0.5f*fa.x*(1.f+t0)*fz.x, 0.5f*fa.y*(1.f+t1)*fz.y);
    }
    *(uint4*)(g_g2_bf + (size_t)l*DHID + j8) = *(uint4*)o;
}

// ---------------- launch ----------------
extern "C" void kernel_launch(void* const* d_in, const int* in_sizes, int n_in,
                              void* d_out, int out_size)
{
    (void)in_sizes; (void)n_in; (void)out_size;
    const float* x    = (const float*)d_in[0];
    const float* ln1w = (const float*)d_in[2];
    const float* winw = (const float*)d_in[3];
    const float* winb = (const float*)d_in[4];
    const float* woutw= (const float*)d_in[5];
    const float* ck   = (const float*)d_in[6];
    const float* cb   = (const float*)d_in[7];
    const float* wq   = (const float*)d_in[8];
    const float* wk   = (const float*)d_in[9];
    const float* wv   = (const float*)d_in[10];
    const float* igw  = (const float*)d_in[11];
    const float* igb  = (const float*)d_in[12];
    const float* fgw  = (const float*)d_in[13];
    const float* fgb  = (const float*)d_in[14];
    const float* gnw  = (const float*)d_in[15];
    const float* gnb  = (const float*)d_in[16];
    const float* skip = (const float*)d_in[17];
    const float* ln2w = (const float*)d_in[18];
    const float* ffnw = (const float*)d_in[19];
    const float* ffnow= (const float*)d_in[20];
    float* out = (float*)d_out;

    static int attr_set = 0;
    if (!attr_set){
        cudaFuncSetAttribute(mma_nt_bf,    cudaFuncAttributeMaxDynamicSharedMemorySize, SMEM_GEMM);
        cudaFuncSetAttribute(mma_qkv,      cudaFuncAttributeMaxDynamicSharedMemorySize, SMEM_GEMM);
        cudaFuncSetAttribute(mma_score_bf, cudaFuncAttributeMaxDynamicSharedMemorySize, SMEM_GEMM);
        cudaFuncSetAttribute(mma_pav_bf,   cudaFuncAttributeMaxDynamicSharedMemorySize, SMEM_GEMM);
        cudaFuncSetAttribute(gates_kernel, cudaFuncAttributeMaxDynamicSharedMemorySize, GROWS*3*DIN*2);
        attr_set = 1;
    }

    float *x2;
    bf16 *hln,*projb,*winwb,*woutwb,*ffnwb,*ffnowb,*wqt,*wkt,*wvt,*yinb,*hfb,*pb,*g2b;
    cudaGetSymbolAddress((void**)&x2,    g_x2);
    cudaGetSymbolAddress((void**)&hln,   g_hln_bf);
    cudaGetSymbolAddress((void**)&projb, g_proj_bf);
    cudaGetSymbolAddress((void**)&winwb, g_winw_bf);
    cudaGetSymbolAddress((void**)&woutwb,g_woutw_bf);
    cudaGetSymbolAddress((void**)&ffnwb, g_ffnw_bf);
    cudaGetSymbolAddress((void**)&ffnowb,g_ffnow_bf);
    cudaGetSymbolAddress((void**)&wqt,   g_wqt_bf);
    cudaGetSymbolAddress((void**)&wkt,   g_wkt_bf);
    cudaGetSymbolAddress((void**)&wvt,   g_wvt_bf);
    cudaGetSymbolAddress((void**)&yinb,  g_yin_bf);
    cudaGetSymbolAddress((void**)&hfb,   g_hf_bf);
    cudaGetSymbolAddress((void**)&pb,    g_p_bf);
    cudaGetSymbolAddress((void**)&g2b,   g_g2_bf);

    dim3 tb(32, 8);
    convert_f2bf8<<<(2*DIN*DMOD/8+255)/256, 256>>>(winw,  winwb,  2*DIN*DMOD/8);
    convert_f2bf8<<<(DMOD*DIN/8+255)/256,   256>>>(woutw, woutwb, DMOD*DIN/8);
    convert_f2bf8<<<(2*DHID*DMOD/8+255)/256,256>>>(ffnw,  ffnwb,  2*DHID*DMOD/8);
    convert_f2bf8<<<(DMOD*DHID/8+255)/256,  256>>>(ffnow, ffnowb, DMOD*DHID/8);
    transpose_w_bf<<<dim3(8,8,NHEAD), tb>>>(wq, wqt);
    transpose_w_bf<<<dim3(8,8,NHEAD), tb>>>(wk, wkt);
    transpose_w_bf<<<dim3(8,8,NHEAD), tb>>>(wv, wvt);

    // 1. hln = LN(x) -> bf16
    layernorm_bf<<<SEQ, 256>>>(x, ln1w, hln, DMOD);
    // 2. proj = hln @ win^T + b -> bf16
    mma_nt_bf<<<dim3(4096/BN, SEQ/BM), 256, SMEM_GEMM>>>(hln, winwb, winb, 0,
        (float*)0, projb, DMOD, DMOD, DMOD, 0, 0, 2*DIN);
    // 3. xc = silu(conv(xi)) -> bf16
    conv_silu_kernel<<<SEQ, 256>>>(ck, cb);
    // 4. fused q/k/v (bf16 out, per-head input slices)
    mma_qkv<<<dim3(2, SEQ/BM, 3*NHEAD), 256, SMEM_GEMM>>>();
    transpose_v_bf<<<dim3(SEQ/32, DHEAD/32, NHEAD), tb>>>();
    // 5. gates
    gates_kernel<<<SEQ/GROWS, 256, GROWS*3*DIN*2>>>(igw, igb, fgw, fgb);
    // 6. per-head scans
    scan_kernel<<<NHEAD, 256>>>();
    // 7. C = (QK^T/16)*D (bf16) + fused tile row-sums
    mma_score_bf<<<dim3(SEQ/BN, SEQ/BM, NHEAD), 256, SMEM_GEMM>>>();
    // 8. reduce partials
    normreduce_kernel<<<NHEAD*SEQ/256, 256>>>();
    // 9. hflat = (C*invnorm) @ V
    mma_pav_bf<<<dim3(2, SEQ/BM, NHEAD), 256, SMEM_GEMM>>>();
    // 10. group norm + skip*xc, * silu(res) -> bf16
    gn_kernel<<<SEQ, 256>>>(gnw, gnb, skip);
    // 11. x2 = x + yin @ wout^T (fp32)
    mma_nt_bf<<<dim3(DMOD/BN, SEQ/BM), 256, SMEM_GEMM>>>(yinb, woutwb, 0, x,
        x2, (bf16*)0, DIN, DIN, DIN, DMOD, DMOD, 0);
    // 12. hf = LN(x2) -> bf16
    layernorm_bf<<<SEQ, 256>>>(x2, ln2w, hfb, DMOD);
    // 13. p = hf @ ffn_win^T -> bf16
    mma_nt_bf<<<dim3(4096/BN, SEQ/BM), 256, SMEM_GEMM>>>(hfb, ffnwb, 0, 0,
        (float*)0, pb, DMOD, DMOD, DMOD, 0, 0, 2*DHID);
    // 14. g2 = gelu(a)*z -> bf16
    gelu_kernel<<<SEQ*DHID/8/256, 256>>>();
    // 15. out = x2 + g2 @ ffn_wout^T (fp32)
    mma_nt_bf<<<dim3(DMOD/BN, SEQ/BM), 256, SMEM_GEMM>>>(g2b, ffnowb, 0, x2,
        out, (bf16*)0, DHID, DHID, DHID, DMOD, DMOD, 0);
}

// round 10
// speedup vs baseline: 6.2377x; 1.0513x over previous
#include <cuda_runtime.h>
#include <cuda_bf16.h>
#include <math.h>

#define SEQ   2048
#define DMOD  1024
#define DIN   2048
#define NHEAD 8
#define DHEAD 256
#define DHID  2048

typedef __nv_bfloat16 bf16;

// ---------------- scratch (allocation-free: __device__ globals) ----------------
__device__ float g_ig  [NHEAD*SEQ];
__device__ float g_fg  [NHEAD*SEQ];
__device__ float g_rowt[NHEAD*SEQ];
__device__ float g_colt[NHEAD*SEQ];
__device__ float g_expn[NHEAD*SEQ];
__device__ float g_inrm[NHEAD*SEQ];
__device__ float g_psum[NHEAD*16*SEQ];
__device__ float g_hfl [SEQ*DIN];
__device__ float g_x2  [SEQ*DMOD];

__device__ bf16 g_hln_bf [SEQ*DMOD];
__device__ bf16 g_proj_bf[SEQ*2*DIN];
__device__ bf16 g_xc_bf  [SEQ*DIN];
__device__ bf16 g_q_bf   [SEQ*DIN];
__device__ bf16 g_k_bf   [SEQ*DIN];
__device__ bf16 g_v_bf   [SEQ*DIN];
__device__ bf16 g_vt_bf  [(size_t)NHEAD*DHEAD*SEQ];
__device__ bf16 g_C_bf   [(size_t)NHEAD*SEQ*SEQ];
__device__ bf16 g_yin_bf [SEQ*DIN];
__device__ bf16 g_hf_bf  [SEQ*DMOD];
__device__ bf16 g_g2_bf  [SEQ*DHID];
__device__ bf16 g_winw_bf[2*DIN*DMOD];
__device__ bf16 g_woutw_bf[DMOD*DIN];
__device__ bf16 g_ffnw_bf[2*DHID*DMOD];   // ROW-REORDERED: row 2t = a-row t, row 2t+1 = z-row DHID+t
__device__ bf16 g_ffnow_bf[DMOD*DHID];
__device__ bf16 g_wqt_bf[NHEAD*DHEAD*DHEAD];
__device__ bf16 g_wkt_bf[NHEAD*DHEAD*DHEAD];
__device__ bf16 g_wvt_bf[NHEAD*DHEAD*DHEAD];

// ---------------- tile config ----------------
#define BM 128
#define BN 128
#define BKB 64                   // bf16 elements per stage (128B rows)
#define TILEB 16384              // 128 rows x 128B
#define SMEM_GEMM (6*TILEB)      // triple-buffered A+B = 96KB

__device__ __forceinline__ unsigned sw128(unsigned o){ return o ^ ((o>>3)&0x70); }

__device__ __forceinline__ void cp16(void* smem_dst, const void* gsrc){
    unsigned s = (unsigned)__cvta_generic_to_shared(smem_dst);
    asm volatile("cp.async.cg.shared.global [%0], [%1], 16;" :: "r"(s), "l"(gsrc));
}
#define CP_COMMIT() asm volatile("cp.async.commit_group;")
#define CP_WAIT(n)  asm volatile("cp.async.wait_group %0;" :: "n"(n))

__device__ __forceinline__ void ldsm4(unsigned r[4], const void* p){
    unsigned a = (unsigned)__cvta_generic_to_shared(p);
    asm volatile("ldmatrix.sync.aligned.m8n8.x4.shared.b16 {%0,%1,%2,%3}, [%4];"
        : "=r"(r[0]),"=r"(r[1]),"=r"(r[2]),"=r"(r[3]) : "r"(a));
}

#define MMA_BF16(d, a, b) \
  asm volatile("mma.sync.aligned.m16n8k16.row.col.f32.bf16.bf16.f32 " \
    "{%0,%1,%2,%3},{%4,%5,%6,%7},{%8,%9},{%0,%1,%2,%3};" \
    : "+f"((d)[0]),"+f"((d)[1]),"+f"((d)[2]),"+f"((d)[3]) \
    : "r"((a)[0]),"r"((a)[1]),"r"((a)[2]),"r"((a)[3]),"r"((b)[0]),"r"((b)[1]))

// fast-math helpers (bit-invisible under bf16 output quantization — verified R7==R8)
__device__ __forceinline__ float ftanh(float x){
    float y; asm("tanh.approx.f32 %0, %1;" : "=f"(y) : "f"(x)); return y;
}
__device__ __forceinline__ float fsigmoid(float x){ return 1.f / (1.f + __expf(-x)); }
__device__ __forceinline__ float fgelu(float a){
    float t = ftanh(0.7978845608028654f * (a + 0.044715f*a*a*a));
    return 0.5f * a * (1.f + t);
}

__device__ __forceinline__ void stage_bf(const bf16* __restrict__ src, int ld,
      int row0, int k0, char* S, int tid)
{
#pragma unroll
    for (int it=0; it<4; it++){
        int idx = it*256 + tid;
        int r = idx>>3, ch = idx&7;
        cp16(S + sw128(r*128 + ch*16), src + (size_t)(row0+r)*ld + k0 + ch*8);
    }
}

__device__ __forceinline__ void compute_bf(const char* __restrict__ As,
    const char* __restrict__ Bs, float acc[4][4][4], int lane, int wm, int wn)
{
    const int l15 = lane&15, lh = lane>>4, l7 = lane&7, lb3 = (lane>>3)&1;
#pragma unroll
    for (int kk=0;kk<4;kk++){
        unsigned a[4][4];
#pragma unroll
        for (int mt=0;mt<4;mt++)
            ldsm4(a[mt], As + sw128((wm + mt*16 + l15)*128 + (kk*2 + lh)*16));
        unsigned b[2][4];
#pragma unroll
        for (int bp=0;bp<2;bp++){
            unsigned row = wn + bp*16 + lh*8 + l7;
            ldsm4(b[bp], Bs + sw128(row*128 + (kk*2 + lb3)*16));
        }
#pragma unroll
        for (int mt=0;mt<4;mt++)
#pragma unroll
            for (int nt=0;nt<4;nt++)
                MMA_BF16(acc[mt][nt], a[mt], b[nt>>1] + (nt&1)*2);
    }
}

// 3-stage cp.async pipeline, one barrier per K-step
__device__ __forceinline__ void gemm_loop_bf(const bf16* __restrict__ A, int lda,
    const bf16* __restrict__ B, int ldb, int m0, int n0, int K,
    char* smem, float acc[4][4][4], int tid, int lane, int wm, int wn)
{
    const int nsteps = K >> 6;
    stage_bf(A, lda, m0, 0, smem, tid);
    stage_bf(B, ldb, n0, 0, smem + TILEB, tid);
    CP_COMMIT();
    if (nsteps > 1){
        stage_bf(A, lda, m0, BKB, smem + 2*TILEB, tid);
        stage_bf(B, ldb, n0, BKB, smem + 3*TILEB, tid);
        CP_COMMIT();
    }
    for (int s=0; s<nsteps; s++){
        if (s+1 < nsteps) { CP_WAIT(1); } else { CP_WAIT(0); }
        __syncthreads();
        if (s+2 < nsteps){
            char* T = smem + ((s+2)%3)*2*TILEB;
            stage_bf(A, lda, m0, (s+2)*BKB, T, tid);
            stage_bf(B, ldb, n0, (s+2)*BKB, T + TILEB, tid);
            CP_COMMIT();
        }
        char* Cur = smem + (s%3)*2*TILEB;
        compute_bf(Cur, Cur + TILEB, acc, lane, wm, wn);
    }
    __syncthreads();   // smem safe for reuse after loop
}

// ---------------- GEMM kernels ----------------

// C[m,n] = sum_k A[m,k]*B[n,k] (+bias) (+resid); optional fp32 out, optional bf16 out
__global__ __launch_bounds__(256, 2) void mma_nt_bf(
    const bf16* __restrict__ A, const bf16* __restrict__ B,
    const float* __restrict__ bias, const float* __restrict__ resid,
    float* __restrict__ Cf, bf16* __restrict__ Cb,
    int K, int lda, int ldb, int ldc, int ldr, int ldcb)
{
    extern __shared__ char smem[];
    const int tid=threadIdx.x, lane=tid&31, wid=tid>>5;
    const int wm=(wid>>2)*64, wn=(wid&3)*32;
    const int m0=blockIdx.y*BM, n0=blockIdx.x*BN;
    float acc[4][4][4] = {};
    gemm_loop_bf(A, lda, B, ldb, m0, n0, K, smem, acc, tid, lane, wm, wn);
    const int gr=lane>>2, gc=lane&3;
#pragma unroll
    for (int mt=0;mt<4;mt++){
#pragma unroll
        for (int nt=0;nt<4;nt++){
            int row = m0+wm+mt*16+gr;
            int col = n0+wn+nt*8+gc*2;
            float b0=0.f,b1=0.f;
            if (bias){ b0=bias[col]; b1=bias[col+1]; }
            float r00=0,r01=0,r10=0,r11=0;
            if (resid){
                const float* rp  = resid + (size_t)row*ldr + col;
                const float* rp2 = resid + (size_t)(row+8)*ldr + col;
                r00=rp[0]; r01=rp[1]; r10=rp2[0]; r11=rp2[1];
            }
            float v00=acc[mt][nt][0]+b0+r00, v01=acc[mt][nt][1]+b1+r01;
            float v10=acc[mt][nt][2]+b0+r10, v11=acc[mt][nt][3]+b1+r11;
            if (Cf){
                *(float2*)(Cf + (size_t)row*ldc + col)     = make_float2(v00,v01);
                *(float2*)(Cf + (size_t)(row+8)*ldc + col) = make_float2(v10,v11);
            }
            if (Cb){
                *(__nv_bfloat162*)(Cb + (size_t)row*ldcb + col)     = __floats2bfloat162_rn(v00,v01);
                *(__nv_bfloat162*)(Cb + (size_t)(row+8)*ldcb + col) = __floats2bfloat162_rn(v10,v11);
            }
        }
    }
}

// ffn-in GEMM with fused GELU-pair epilogue.
// B rows are interleaved (2t = a-row t, 2t+1 = z-row t), so each thread's
// (col, col+1) fragment pair is exactly (a_t, z_t); writes g2[row][t] directly.
__global__ __launch_bounds__(256, 2) void mma_ffn1()
{
    extern __shared__ char smem[];
    const int tid=threadIdx.x, lane=tid&31, wid=tid>>5;
    const int wm=(wid>>2)*64, wn=(wid&3)*32;
    const int m0=blockIdx.y*BM, n0=blockIdx.x*BN;
    float acc[4][4][4] = {};
    gemm_loop_bf(g_hf_bf, DMOD, g_ffnw_bf, DMOD, m0, n0, DMOD, smem, acc, tid, lane, wm, wn);
    const int gr=lane>>2, gc=lane&3;
#pragma unroll
    for (int mt=0;mt<4;mt++){
#pragma unroll
        for (int nt=0;nt<4;nt++){
            int row = m0+wm+mt*16+gr;
            int col = n0+wn+nt*8+gc*2;   // even: a, odd: z
            int t = col >> 1;
            g_g2_bf[(size_t)row*DHID + t]     = __float2bfloat16_rn(fgelu(acc[mt][nt][0]) * acc[mt][nt][1]);
            g_g2_bf[(size_t)(row+8)*DHID + t] = __float2bfloat16_rn(fgelu(acc[mt][nt][2]) * acc[mt][nt][3]);
        }
    }
}

// fused q/k/v: grid.z = which*NHEAD + h; per-head input slice (head_lin semantics).
__global__ __launch_bounds__(256, 2) void mma_qkv()
{
    const int z = blockIdx.z;
    const int which = z >> 3;      // 0=q, 1=k, 2=v
    const int h = z & 7;
    const bf16* A; int lda; const bf16* B; bf16* C;
    if (which == 0){ A = g_xc_bf   + h*DHEAD; lda = DIN;   B = g_wqt_bf + h*DHEAD*DHEAD; C = g_q_bf + h*DHEAD; }
    else if (which == 1){ A = g_xc_bf + h*DHEAD; lda = DIN; B = g_wkt_bf + h*DHEAD*DHEAD; C = g_k_bf + h*DHEAD; }
    else { A = g_proj_bf + h*DHEAD; lda = 2*DIN; B = g_wvt_bf + h*DHEAD*DHEAD; C = g_v_bf + h*DHEAD; }
    extern __shared__ char smem[];
    const int tid=threadIdx.x, lane=tid&31, wid=tid>>5;
    const int wm=(wid>>2)*64, wn=(wid&3)*32;
    const int m0=blockIdx.y*BM, n0=blockIdx.x*BN;
    float acc[4][4][4] = {};
    gemm_loop_bf(A, lda, B, DHEAD, m0, n0, DHEAD, smem, acc, tid, lane, wm, wn);
    const int gr=lane>>2, gc=lane&3;
#pragma unroll
    for (int mt=0;mt<4;mt++){
#pragma unroll
        for (int nt=0;nt<4;nt++){
            int row = m0+wm+mt*16+gr;
            int col = n0+wn+nt*8+gc*2;
            *(__nv_bfloat162*)(C + (size_t)row*DIN + col)     = __floats2bfloat162_rn(acc[mt][nt][0],acc[mt][nt][1]);
            *(__nv_bfloat162*)(C + (size_t)(row+8)*DIN + col) = __floats2bfloat162_rn(acc[mt][nt][2],acc[mt][nt][3]);
        }
    }
}

// scores: C[h][l,m] = (q·k)/16 * exp(rowt[l]+colt[m]) masked; bf16 out + fp32 tile row-sums
__global__ __launch_bounds__(256, 2) void mma_score_bf()
{
    const int h  = blockIdx.z;
    const int l0 = blockIdx.y * BM;
    const int m0 = blockIdx.x * BN;
    if (m0 >= l0 + BM) return;   // fully-masked tile: skipped (never read downstream)
    extern __shared__ char smem[];
    const bf16* A = g_q_bf + h*DHEAD;
    const bf16* B = g_k_bf + h*DHEAD;
    const int tid=threadIdx.x, lane=tid&31, wid=tid>>5;
    const int wm=(wid>>2)*64, wn=(wid&3)*32;
    float acc[4][4][4] = {};
    gemm_loop_bf(A, DIN, B, DIN, l0, m0, DHEAD, smem, acc, tid, lane, wm, wn);

    float* sred = (float*)smem;   // safe: gemm_loop ends with syncthreads
    const float* rt = g_rowt + h*SEQ;
    const float* ct = g_colt + h*SEQ;
    bf16* Cb = g_C_bf + (size_t)h*SEQ*SEQ;
    const int gr=lane>>2, gc=lane&3;
#pragma unroll
    for (int mt=0;mt<4;mt++){
        int l = l0+wm+mt*16+gr;
        float rl0 = rt[l], rl1 = rt[l+8];
        float rs0 = 0.f, rs1 = 0.f;
#pragma unroll
        for (int nt=0;nt<4;nt++){
            int m = m0+wn+nt*8+gc*2;
            float cm0 = ct[m], cm1 = ct[m+1];
            float v00 = (m   <= l  ) ? acc[mt][nt][0]*0.0625f*__expf(rl0+cm0) : 0.f;
            float v01 = (m+1 <= l  ) ? acc[mt][nt][1]*0.0625f*__expf(rl0+cm1) : 0.f;
            float v10 = (m   <= l+8) ? acc[mt][nt][2]*0.0625f*__expf(rl1+cm0) : 0.f;
            float v11 = (m+1 <= l+8) ? acc[mt][nt][3]*0.0625f*__expf(rl1+cm1) : 0.f;
            rs0 += v00 + v01;
            rs1 += v10 + v11;
            *(__nv_bfloat162*)(Cb + (size_t)l*SEQ + m)     = __floats2bfloat162_rn(v00,v01);
            *(__nv_bfloat162*)(Cb + (size_t)(l+8)*SEQ + m) = __floats2bfloat162_rn(v10,v11);
        }
        rs0 += __shfl_xor_sync(0xffffffffu, rs0, 1);
        rs0 += __shfl_xor_sync(0xffffffffu, rs0, 2);
        rs1 += __shfl_xor_sync(0xffffffffu, rs1, 1);
        rs1 += __shfl_xor_sync(0xffffffffu, rs1, 2);
        if (gc == 0){
            sred[(wm+mt*16+gr)*4   + (wid&3)] = rs0;
            sred[(wm+mt*16+gr+8)*4 + (wid&3)] = rs1;
        }
    }
    __syncthreads();
    if (tid < 128){
        float s = sred[tid*4] + sred[tid*4+1] + sred[tid*4+2] + sred[tid*4+3];
        g_psum[((size_t)h*16 + blockIdx.x)*SEQ + l0 + tid] = s;
    }
}

// hflat[l, h*256+d] = invnorm[h,l] * sum_{m<=l} C[h][l,m]*vt[h][d][m]
__global__ __launch_bounds__(256, 2) void mma_pav_bf()
{
    const int h  = blockIdx.z;
    const int l0 = blockIdx.y * BM;
    const int n0 = blockIdx.x * BN;
    extern __shared__ char smem[];
    const bf16* A = g_C_bf + (size_t)h*SEQ*SEQ;
    const bf16* B = g_vt_bf + (size_t)h*DHEAD*SEQ;
    const int Kmax = l0 + BM;   // causal bound
    const int tid=threadIdx.x, lane=tid&31, wid=tid>>5;
    const int wm=(wid>>2)*64, wn=(wid&3)*32;
    float acc[4][4][4] = {};
    gemm_loop_bf(A, SEQ, B, SEQ, l0, n0, Kmax, smem, acc, tid, lane, wm, wn);
    const int gr=lane>>2, gc=lane&3;
#pragma unroll
    for (int mt=0;mt<4;mt++){
#pragma unroll
        for (int nt=0;nt<4;nt++){
            int l = l0+wm+mt*16+gr;
            int col = n0+wn+nt*8+gc*2;
            float s0 = g_inrm[h*SEQ + l];
            float s1 = g_inrm[h*SEQ + l + 8];
            float* c0 = g_hfl + (size_t)l*DIN + h*DHEAD + col;
            float* c1 = g_hfl + (size_t)(l+8)*DIN + h*DHEAD + col;
            *(float2*)c0 = make_float2(acc[mt][nt][0]*s0, acc[mt][nt][1]*s0);
            *(float2*)c1 = make_float2(acc[mt][nt][2]*s1, acc[mt][nt][3]*s1);
        }
    }
}

// ---------------- weight prep ----------------
// one launch: winw, woutw, ffnow plain converts + ffnw interleaved-row convert
#define CW_N0 524288   // winw  4M elems / 8
#define CW_N1 262144   // woutw 2M / 8
#define CW_N2 262144   // ffnow 2M / 8
#define CW_N3 524288   // ffnw  4M / 8 (remapped)
__device__ __forceinline__ void cvt8(const float* s, bf16* d){
    float4 a = ((const float4*)s)[0], b = ((const float4*)s)[1];
    __nv_bfloat162 o[4] = { __floats2bfloat162_rn(a.x,a.y), __floats2bfloat162_rn(a.z,a.w),
                            __floats2bfloat162_rn(b.x,b.y), __floats2bfloat162_rn(b.z,b.w) };
    *(uint4*)d = *(uint4*)o;
}
__global__ void convert_weights(const float* __restrict__ winw, const float* __restrict__ woutw,
                                const float* __restrict__ ffnw, const float* __restrict__ ffnow)
{
    int i = blockIdx.x*256 + threadIdx.x;
    if (i < CW_N0){
        cvt8(winw + (size_t)i*8, g_winw_bf + (size_t)i*8);
    } else if (i < CW_N0+CW_N1){
        int j = i - CW_N0;
        cvt8(woutw + (size_t)j*8, g_woutw_bf + (size_t)j*8);
    } else if (i < CW_N0+CW_N1+CW_N2){
        int j = i - CW_N0 - CW_N1;
        cvt8(ffnow + (size_t)j*8, g_ffnow_bf + (size_t)j*8);
    } else {
        int j = i - CW_N0 - CW_N1 - CW_N2;
        if (j < CW_N3){
            int r = j >> 7, c8 = (j & 127) * 8;     // 128 chunks per 1024-col row
            int src = (r & 1) ? (DHID + (r>>1)) : (r>>1);
            cvt8(ffnw + (size_t)src*DMOD + c8, g_ffnw_bf + (size_t)r*DMOD + c8);
        }
    }
}

// all three per-head 256x256 weight transposes in one launch: z = which*8 + h
__global__ void transpose_w_all(const float* __restrict__ wq, const float* __restrict__ wk,
                                const float* __restrict__ wv)
{
    __shared__ float t[32][33];
    int z = blockIdx.z;
    int which = z >> 3, h = z & 7;
    const float* I = (which==0 ? wq : which==1 ? wk : wv) + (size_t)h*DHEAD*DHEAD;
    bf16* O = (which==0 ? g_wqt_bf : which==1 ? g_wkt_bf : g_wvt_bf) + (size_t)h*DHEAD*DHEAD;
    int k0 = blockIdx.y*32, d0 = blockIdx.x*32;
    int x = threadIdx.x, y = threadIdx.y;
#pragma unroll
    for (int i=0;i<32;i+=8) t[y+i][x] = I[(size_t)(k0+y+i)*DHEAD + d0 + x];
    __syncthreads();
#pragma unroll
    for (int i=0;i<32;i+=8) O[(size_t)(d0+y+i)*DHEAD + k0 + x] = __float2bfloat16_rn(t[x][y+i]);
}

__global__ void transpose_v_bf()
{
    __shared__ float t[32][33];
    int h = blockIdx.z;
    int m0 = blockIdx.x*32, d0 = blockIdx.y*32;
    int x = threadIdx.x, y = threadIdx.y;
#pragma unroll
    for (int i=0;i<32;i+=8) t[y+i][x] = __bfloat162float(g_v_bf[(size_t)(m0+y+i)*DIN + h*DHEAD + d0 + x]);
    __syncthreads();
#pragma unroll
    for (int i=0;i<32;i+=8)
        g_vt_bf[((size_t)h*DHEAD + d0+y+i)*SEQ + m0 + x] = __float2bfloat16_rn(t[x][y+i]);
}

// ---------------- elementwise / reduction kernels ----------------
// warp-per-row layernorm (cols = 1024)
__global__ __launch_bounds__(256) void layernorm_bf(const float* __restrict__ x,
    const float* __restrict__ w, bf16* __restrict__ out, int cols)
{
    int wrp = threadIdx.x >> 5, lane = threadIdx.x & 31;
    int row = blockIdx.x*8 + wrp;
    const float* xr = x + (size_t)row*cols;
    float4 v[8];
    float s = 0.f, ss = 0.f;
#pragma unroll
    for (int i=0;i<8;i++){
        v[i] = ((const float4*)xr)[lane + i*32];
        s  += v[i].x + v[i].y + v[i].z + v[i].w;
        ss += v[i].x*v[i].x + v[i].y*v[i].y + v[i].z*v[i].z + v[i].w*v[i].w;
    }
#pragma unroll
    for (int off=16; off>0; off>>=1){
        s  += __shfl_xor_sync(0xffffffffu, s,  off);
        ss += __shfl_xor_sync(0xffffffffu, ss, off);
    }
    float mean = s / cols;
    float var  = ss / cols - mean*mean;
    float rstd = rsqrtf(var + 1e-5f);
    bf16* orow = out + (size_t)row*cols;
#pragma unroll
    for (int i=0;i<8;i++){
        float4 wv = ((const float4*)w)[lane + i*32];
        __nv_bfloat162 o0 = __floats2bfloat162_rn((v[i].x-mean)*rstd*wv.x, (v[i].y-mean)*rstd*wv.y);
        __nv_bfloat162 o1 = __floats2bfloat162_rn((v[i].z-mean)*rstd*wv.z, (v[i].w-mean)*rstd*wv.w);
        uint2 pk = make_uint2(*(unsigned*)&o0, *(unsigned*)&o1);
        *(uint2*)(orow + (lane + i*32)*4) = pk;
    }
}

__global__ __launch_bounds__(256) void conv_silu_kernel(const float* __restrict__ ck, const float* __restrict__ cb)
{
    int l = blockIdx.x;
    int c8 = threadIdx.x * 8;
    float acc[8];
    {
        float4 b0 = *(const float4*)(cb + c8);
        float4 b1 = *(const float4*)(cb + c8 + 4);
        acc[0]=b0.x; acc[1]=b0.y; acc[2]=b0.z; acc[3]=b0.w;
        acc[4]=b1.x; acc[5]=b1.y; acc[6]=b1.z; acc[7]=b1.w;
    }
    float4 kt[8];
#pragma unroll
    for (int j=0;j<8;j++) kt[j] = *(const float4*)(ck + (c8+j)*4);
#pragma unroll
    for (int t=0;t<4;t++){
        int ls = l - t;
        if (ls < 0) break;
        uint4 u = *(const uint4*)(g_proj_bf + (size_t)ls*(2*DIN) + c8);
        __nv_bfloat162* bp = (__nv_bfloat162*)&u;
        float tap[8];
#pragma unroll
        for (int j=0;j<4;j++){ float2 f = __bfloat1622float2(bp[j]); tap[2*j]=f.x; tap[2*j+1]=f.y; }
#pragma unroll
        for (int j=0;j<8;j++)
            acc[j] = fmaf(tap[j], ((float*)&kt[j])[t], acc[j]);
    }
    __nv_bfloat162 o[4];
#pragma unroll
    for (int j=0;j<4;j++){
        float a0 = acc[2*j],   r0 = a0 * fsigmoid(a0);
        float a1 = acc[2*j+1], r1 = a1 * fsigmoid(a1);
        o[j] = __floats2bfloat162_rn(r0, r1);
    }
    *(uint4*)(g_xc_bf + (size_t)l*DIN + c8) = *(uint4*)o;
}

#define GROWS 16
__global__ __launch_bounds__(256) void gates_kernel(
    const float* __restrict__ igw, const float* __restrict__ igb,
    const float* __restrict__ fgw, const float* __restrict__ fgb)
{
    extern __shared__ bf16 gbuf[];
    int l0 = blockIdx.x*GROWS, tid = threadIdx.x;
    const int CH = DIN/8;
    for (int i = tid; i < GROWS*3*CH; i += 256){
        int rr = i / (3*CH); int rem = i - rr*3*CH;
        int a = rem / CH;    int ch = rem - a*CH;
        const bf16* src = (a==0 ? g_q_bf : a==1 ? g_k_bf : g_v_bf) + (size_t)(l0+rr)*DIN + ch*8;
        *(uint4*)&gbuf[(size_t)rr*3*DIN + a*DIN + ch*8] = *(const uint4*)src;
    }
    __syncthreads();
    int w = tid >> 5, lane = tid & 31;
    const float* iw = igw + (size_t)w*3*DIN;
    const float* fw = fgw + (size_t)w*3*DIN;
    float si[GROWS] = {}, sf[GROWS] = {};
    for (int j = lane*8; j < 3*DIN; j += 256){
        float4 wi0 = *(const float4*)(iw + j), wi1 = *(const float4*)(iw + j + 4);
        float4 wf0 = *(const float4*)(fw + j), wf1 = *(const float4*)(fw + j + 4);
#pragma unroll
        for (int rr=0; rr<GROWS; rr++){
            uint4 u = *(uint4*)&gbuf[(size_t)rr*3*DIN + j];
            __nv_bfloat162* bp = (__nv_bfloat162*)&u;
            float2 g0 = __bfloat1622float2(bp[0]);
            float2 g1 = __bfloat1622float2(bp[1]);
            float2 g2 = __bfloat1622float2(bp[2]);
            float2 g3 = __bfloat1622float2(bp[3]);
            si[rr] = fmaf(g0.x, wi0.x, si[rr]); si[rr] = fmaf(g0.y, wi0.y, si[rr]);
            si[rr] = fmaf(g1.x, wi0.z, si[rr]); si[rr] = fmaf(g1.y, wi0.w, si[rr]);
            si[rr] = fmaf(g2.x, wi1.x, si[rr]); si[rr] = fmaf(g2.y, wi1.y, si[rr]);
            si[rr] = fmaf(g3.x, wi1.z, si[rr]); si[rr] = fmaf(g3.y, wi1.w, si[rr]);
            sf[rr] = fmaf(g0.x, wf0.x, sf[rr]); sf[rr] = fmaf(g0.y, wf0.y, sf[rr]);
            sf[rr] = fmaf(g1.x, wf0.z, sf[rr]); sf[rr] = fmaf(g1.y, wf0.w, sf[rr]);
            sf[rr] = fmaf(g2.x, wf1.x, sf[rr]); sf[rr] = fmaf(g2.y, wf1.y, sf[rr]);
            sf[rr] = fmaf(g3.x, wf1.z, sf[rr]); sf[rr] = fmaf(g3.y, wf1.w, sf[rr]);
        }
    }
#pragma unroll
    for (int off=16; off>0; off>>=1){
#pragma unroll
        for (int rr=0;rr<GROWS;rr++){
            si[rr] += __shfl_xor_sync(0xffffffffu, si[rr], off);
            sf[rr] += __shfl_xor_sync(0xffffffffu, sf[rr], off);
        }
    }
    if (lane == 0){
#pragma unroll
        for (int rr=0;rr<GROWS;rr++){
            g_ig[w*SEQ + l0+rr] = si[rr] + igb[w];
            g_fg[w*SEQ + l0+rr] = sf[rr] + fgb[w];
        }
    }
}

__global__ __launch_bounds__(256) void scan_kernel()
{
    __shared__ float lf[SEQ];
    __shared__ float tot[256];
    int h = blockIdx.x, tid = threadIdx.x;
    for (int m = tid; m < SEQ; m += 256){
        float f = g_fg[h*SEQ + m];
        lf[m] = fminf(f, 0.f) - log1pf(expf(-fabsf(f)));
    }
    __syncthreads();
    int base = tid * 8;
    float csl[8];
    float run = 0.f;
#pragma unroll
    for (int j=0;j<8;j++){ run += lf[base+j]; csl[j] = run; }
    tot[tid] = run; __syncthreads();
    for (int off=1; off<256; off<<=1){
        float v = (tid >= off) ? tot[tid-off] : 0.f;
        __syncthreads();
        tot[tid] += v;
        __syncthreads();
    }
    float excl = tot[tid] - run;
    float cs[8], cml[8];
    float rmax = -INFINITY;
#pragma unroll
    for (int j=0;j<8;j++){
        cs[j] = csl[j] + excl;
        float col = g_ig[h*SEQ + base + j] - cs[j];
        g_colt[h*SEQ + base + j] = col;
        rmax = fmaxf(rmax, col);
        cml[j] = rmax;
    }
    tot[tid] = rmax; __syncthreads();
    for (int off=1; off<256; off<<=1){
        float v = (tid >= off) ? tot[tid-off] : -INFINITY;
        __syncthreads();
        tot[tid] = fmaxf(tot[tid], v);
        __syncthreads();
    }
    float em = (tid > 0) ? tot[tid-1] : -INFINITY;
#pragma unroll
    for (int j=0;j<8;j++){
        float rm = fmaxf(em, cml[j]);
        g_rowt[h*SEQ + base + j] = -rm;
        g_expn[h*SEQ + base + j] = expf(-(cs[j] + rm));
    }
}

__global__ void normreduce_kernel()
{
    int idx = blockIdx.x*256 + threadIdx.x;
    if (idx >= NHEAD*SEQ) return;
    int h = idx >> 11, l = idx & (SEQ-1);
    int nt = (l >> 7) + 1;
    float s = 0.f;
    for (int t=0; t<nt; t++) s += g_psum[((size_t)h*16 + t)*SEQ + l];
    float n = fmaxf(fabsf(s), g_expn[idx]) + 1e-6f;
    g_inrm[idx] = 1.0f / n;
}

__global__ __launch_bounds__(256) void gn_kernel(const float* __restrict__ gnw,
    const float* __restrict__ gnb, const float* __restrict__ skip)
{
    int l = blockIdx.x, tid = threadIdx.x, w = tid >> 5, lane = tid & 31;
    int c0 = w*DHEAD + lane*8;
    float4 h0 = *(const float4*)(g_hfl + (size_t)l*DIN + c0);
    float4 h1 = *(const float4*)(g_hfl + (size_t)l*DIN + c0 + 4);
    float vals[8] = {h0.x,h0.y,h0.z,h0.w,h1.x,h1.y,h1.z,h1.w};
    float s = 0.f, ss = 0.f;
#pragma unroll
    for (int j=0;j<8;j++){ s += vals[j]; ss += vals[j]*vals[j]; }
#pragma unroll
    for (int off=16; off>0; off>>=1){
        s  += __shfl_xor_sync(0xffffffffu, s,  off);
        ss += __shfl_xor_sync(0xffffffffu, ss, off);
    }
    float mean = s * (1.f/DHEAD);
    float var  = ss * (1.f/DHEAD) - mean*mean;
    float rstd = rsqrtf(var + 1e-5f);
    float4 gw0 = *(const float4*)(gnw + c0), gw1 = *(const float4*)(gnw + c0 + 4);
    float4 gb0 = *(const float4*)(gnb + c0), gb1 = *(const float4*)(gnb + c0 + 4);
    float4 sk0 = *(const float4*)(skip + c0), sk1 = *(const float4*)(skip + c0 + 4);
    uint4 uxc = *(const uint4*)(g_xc_bf + (size_t)l*DIN + c0);
    uint4 urs = *(const uint4*)(g_proj_bf + (size_t)l*(2*DIN) + DIN + c0);
    float gwv[8] = {gw0.x,gw0.y,gw0.z,gw0.w,gw1.x,gw1.y,gw1.z,gw1.w};
    float gbv[8] = {gb0.x,gb0.y,gb0.z,gb0.w,gb1.x,gb1.y,gb1.z,gb1.w};
    float skv[8] = {sk0.x,sk0.y,sk0.z,sk0.w,sk1.x,sk1.y,sk1.z,sk1.w};
    float xcv[8], rsv[8];
    {
        __nv_bfloat162* bx = (__nv_bfloat162*)&uxc;
        __nv_bfloat162* br = (__nv_bfloat162*)&urs;
#pragma unroll
        for (int j=0;j<4;j++){
            float2 fx = __bfloat1622float2(bx[j]); xcv[2*j]=fx.x; xcv[2*j+1]=fx.y;
            float2 fr = __bfloat1622float2(br[j]); rsv[2*j]=fr.x; rsv[2*j+1]=fr.y;
        }
    }
    __nv_bfloat162 o[4];
#pragma unroll
    for (int j=0;j<4;j++){
        float y0, y1;
        {
            float hn = (vals[2*j] - mean) * rstd;
            float h2 = hn*gwv[2*j] + gbv[2*j] + skv[2*j]*xcv[2*j];
            float r  = rsv[2*j];
            y0 = h2 * (r * fsigmoid(r));
        }
        {
            float hn = (vals[2*j+1] - mean) * rstd;
            float h2 = hn*gwv[2*j+1] + gbv[2*j+1] + skv[2*j+1]*xcv[2*j+1];
            float r  = rsv[2*j+1];
            y1 = h2 * (r * fsigmoid(r));
        }
        o[j] = __floats2bfloat162_rn(y0, y1);
    }
    *(uint4*)(g_yin_bf + (size_t)l*DIN + c0) = *(uint4*)o;
}

// ---------------- launch ----------------
extern "C" void kernel_launch(void* const* d_in, const int* in_sizes, int n_in,
                              void* d_out, int out_size)
{
    (void)in_sizes; (void)n_in; (void)out_size;
    const float* x    = (const float*)d_in[0];
    const float* ln1w = (const float*)d_in[2];
    const float* winw = (const float*)d_in[3];
    const float* winb = (const float*)d_in[4];
    const float* woutw= (const float*)d_in[5];
    const float* ck   = (const float*)d_in[6];
    const float* cb   = (const float*)d_in[7];
    const float* wq   = (const float*)d_in[8];
    const float* wk   = (const float*)d_in[9];
    const float* wv   = (const float*)d_in[10];
    const float* igw  = (const float*)d_in[11];
    const float* igb  = (const float*)d_in[12];
    const float* fgw  = (const float*)d_in[13];
    const float* fgb  = (const float*)d_in[14];
    const float* gnw  = (const float*)d_in[15];
    const float* gnb  = (const float*)d_in[16];
    const float* skip = (const float*)d_in[17];
    const float* ln2w = (const float*)d_in[18];
    const float* ffnw = (const float*)d_in[19];
    const float* ffnow= (const float*)d_in[20];
    float* out = (float*)d_out;

    static int attr_set = 0;
    if (!attr_set){
        cudaFuncSetAttribute(mma_nt_bf,    cudaFuncAttributeMaxDynamicSharedMemorySize, SMEM_GEMM);
        cudaFuncSetAttribute(mma_ffn1,     cudaFuncAttributeMaxDynamicSharedMemorySize, SMEM_GEMM);
        cudaFuncSetAttribute(mma_qkv,      cudaFuncAttributeMaxDynamicSharedMemorySize, SMEM_GEMM);
        cudaFuncSetAttribute(mma_score_bf, cudaFuncAttributeMaxDynamicSharedMemorySize, SMEM_GEMM);
        cudaFuncSetAttribute(mma_pav_bf,   cudaFuncAttributeMaxDynamicSharedMemorySize, SMEM_GEMM);
        cudaFuncSetAttribute(gates_kernel, cudaFuncAttributeMaxDynamicSharedMemorySize, GROWS*3*DIN*2);
        attr_set = 1;
    }

    float *x2;
    bf16 *hln,*projb,*winwb,*woutwb,*ffnowb,*yinb,*hfb,*g2b;
    cudaGetSymbolAddress((void**)&x2,    g_x2);
    cudaGetSymbolAddress((void**)&hln,   g_hln_bf);
    cudaGetSymbolAddress((void**)&projb, g_proj_bf);
    cudaGetSymbolAddress((void**)&winwb, g_winw_bf);
    cudaGetSymbolAddress((void**)&woutwb,g_woutw_bf);
    cudaGetSymbolAddress((void**)&ffnowb,g_ffnow_bf);
    cudaGetSymbolAddress((void**)&yinb,  g_yin_bf);
    cudaGetSymbolAddress((void**)&hfb,   g_hf_bf);
    cudaGetSymbolAddress((void**)&g2b,   g_g2_bf);

    dim3 tb(32, 8);

    // 0. hln = LN(x) -> bf16
    layernorm_bf<<<SEQ/8, 256>>>(x, ln1w, hln, DMOD);
    // 1. all weight converts (winw/woutw/ffnow plain + ffnw interleaved)
    convert_weights<<<(CW_N0+CW_N1+CW_N2+CW_N3+255)/256, 256>>>(winw, woutw, ffnw, ffnow);
    // 2. all per-head weight transposes
    transpose_w_all<<<dim3(8,8,24), tb>>>(wq, wk, wv);
    // 3. proj = hln @ win^T + b -> bf16
    mma_nt_bf<<<dim3(4096/BN, SEQ/BM), 256, SMEM_GEMM>>>(hln, winwb, winb, 0,
        (float*)0, projb, DMOD, DMOD, DMOD, 0, 0, 2*DIN);
    // 4. xc = silu(conv(xi)) -> bf16
    conv_silu_kernel<<<SEQ, 256>>>(ck, cb);
    // 5. fused q/k/v (bf16, per-head input slices)  <-- ncu -s 5 profiles this
    mma_qkv<<<dim3(2, SEQ/BM, 3*NHEAD), 256, SMEM_GEMM>>>();
    // 6. vt
    transpose_v_bf<<<dim3(SEQ/32, DHEAD/32, NHEAD), tb>>>();
    // 7. gates
    gates_kernel<<<SEQ/GROWS, 256, GROWS*3*DIN*2>>>(igw, igb, fgw, fgb);
    // 8. per-head scans
    scan_kernel<<<NHEAD, 256>>>();
    // 9. C = (QK^T/16)*D (bf16) + fused tile row-sums
    mma_score_bf<<<dim3(SEQ/BN, SEQ/BM, NHEAD), 256, SMEM_GEMM>>>();
    // 10. reduce partials
    normreduce_kernel<<<NHEAD*SEQ/256, 256>>>();
    // 11. hflat = (C*invnorm) @ V
    mma_pav_bf<<<dim3(2, SEQ/BM, NHEAD), 256, SMEM_GEMM>>>();
    // 12. group norm + skip*xc, * silu(res) -> bf16
    gn_kernel<<<SEQ, 256>>>(gnw, gnb, skip);
    // 13. x2 = x + yin @ wout^T (fp32)
    mma_nt_bf<<<dim3(DMOD/BN, SEQ/BM), 256, SMEM_GEMM>>>(yinb, woutwb, 0, x,
        x2, (bf16*)0, DIN, DIN, DIN, DMOD, DMOD, 0);
    // 14. hf = LN(x2) -> bf16
    layernorm_bf<<<SEQ/8, 256>>>(x2, ln2w, hfb, DMOD);
    // 15. g2 = gelu(a)*z fused into ffn-in GEMM (interleaved weights)
    mma_ffn1<<<dim3(4096/BN, SEQ/BM), 256, SMEM_GEMM>>>();
    // 16. out = x2 + g2 @ ffn_wout^T (fp32)
    mma_nt_bf<<<dim3(DMOD/BN, SEQ/BM), 256, SMEM_GEMM>>>(g2b, ffnowb, 0, x2,
        out, (bf16*)0, DHID, DHID, DHID, DMOD, DMOD, 0);
}

// round 11
// speedup vs baseline: 6.2891x; 1.0082x over previous
#include <cuda_runtime.h>
#include <cuda_bf16.h>
#include <math.h>

#define SEQ   2048
#define DMOD  1024
#define DIN   2048
#define NHEAD 8
#define DHEAD 256
#define DHID  2048

typedef __nv_bfloat16 bf16;

// ---------------- scratch (allocation-free: __device__ globals) ----------------
__device__ float g_ig  [NHEAD*SEQ];
__device__ float g_fg  [NHEAD*SEQ];
__device__ float g_rowt[NHEAD*SEQ];
__device__ float g_colt[NHEAD*SEQ];
__device__ float g_expn[NHEAD*SEQ];
__device__ float g_psum[NHEAD*16*SEQ];
__device__ float g_hfl [SEQ*DIN];
__device__ float g_x2  [SEQ*DMOD];
__device__ float g_sk0 [SEQ*DMOD];
__device__ float g_sk1 [SEQ*DMOD];

__device__ bf16 g_hln_bf [SEQ*DMOD];
__device__ bf16 g_proj_bf[SEQ*2*DIN];
__device__ bf16 g_xc_bf  [SEQ*DIN];
__device__ bf16 g_q_bf   [SEQ*DIN];
__device__ bf16 g_k_bf   [SEQ*DIN];
__device__ bf16 g_v_bf   [SEQ*DIN];
__device__ bf16 g_vt_bf  [(size_t)NHEAD*DHEAD*SEQ];
__device__ bf16 g_C_bf   [(size_t)NHEAD*SEQ*SEQ];
__device__ bf16 g_yin_bf [SEQ*DIN];
__device__ bf16 g_hf_bf  [SEQ*DMOD];
__device__ bf16 g_g2_bf  [SEQ*DHID];
__device__ bf16 g_winw_bf[2*DIN*DMOD];
__device__ bf16 g_woutw_bf[DMOD*DIN];
__device__ bf16 g_ffnw_bf[2*DHID*DMOD];   // ROW-REORDERED: row 2t = a-row t, row 2t+1 = z-row DHID+t
__device__ bf16 g_ffnow_bf[DMOD*DHID];
__device__ bf16 g_wqt_bf[NHEAD*DHEAD*DHEAD];
__device__ bf16 g_wkt_bf[NHEAD*DHEAD*DHEAD];
__device__ bf16 g_wvt_bf[NHEAD*DHEAD*DHEAD];

// ---------------- tile config ----------------
#define BM 128
#define BN 128
#define BKB 64                   // bf16 elements per stage (128B rows)
#define TILEB 16384              // 128 rows x 128B
#define SMEM_GEMM (6*TILEB)      // triple-buffered A+B = 96KB

__device__ __forceinline__ unsigned sw128(unsigned o){ return o ^ ((o>>3)&0x70); }

__device__ __forceinline__ void cp16(void* smem_dst, const void* gsrc){
    unsigned s = (unsigned)__cvta_generic_to_shared(smem_dst);
    asm volatile("cp.async.cg.shared.global [%0], [%1], 16;" :: "r"(s), "l"(gsrc));
}
#define CP_COMMIT() asm volatile("cp.async.commit_group;")
#define CP_WAIT(n)  asm volatile("cp.async.wait_group %0;" :: "n"(n))

__device__ __forceinline__ void ldsm4(unsigned r[4], const void* p){
    unsigned a = (unsigned)__cvta_generic_to_shared(p);
    asm volatile("ldmatrix.sync.aligned.m8n8.x4.shared.b16 {%0,%1,%2,%3}, [%4];"
        : "=r"(r[0]),"=r"(r[1]),"=r"(r[2]),"=r"(r[3]) : "r"(a));
}

#define MMA_BF16(d, a, b) \
  asm volatile("mma.sync.aligned.m16n8k16.row.col.f32.bf16.bf16.f32 " \
    "{%0,%1,%2,%3},{%4,%5,%6,%7},{%8,%9},{%0,%1,%2,%3};" \
    : "+f"((d)[0]),"+f"((d)[1]),"+f"((d)[2]),"+f"((d)[3]) \
    : "r"((a)[0]),"r"((a)[1]),"r"((a)[2]),"r"((a)[3]),"r"((b)[0]),"r"((b)[1]))

// fast-math helpers (bit-invisible under bf16 output quantization — verified R7==R8)
__device__ __forceinline__ float ftanh(float x){
    float y; asm("tanh.approx.f32 %0, %1;" : "=f"(y) : "f"(x)); return y;
}
__device__ __forceinline__ float fsigmoid(float x){ return 1.f / (1.f + __expf(-x)); }
__device__ __forceinline__ float fgelu(float a){
    float t = ftanh(0.7978845608028654f * (a + 0.044715f*a*a*a));
    return 0.5f * a * (1.f + t);
}

__device__ __forceinline__ void stage_bf(const bf16* __restrict__ src, int ld,
      int row0, int k0, char* S, int tid)
{
#pragma unroll
    for (int it=0; it<4; it++){
        int idx = it*256 + tid;
        int r = idx>>3, ch = idx&7;
        cp16(S + sw128(r*128 + ch*16), src + (size_t)(row0+r)*ld + k0 + ch*8);
    }
}

__device__ __forceinline__ void compute_bf(const char* __restrict__ As,
    const char* __restrict__ Bs, float acc[4][4][4], int lane, int wm, int wn)
{
    const int l15 = lane&15, lh = lane>>4, l7 = lane&7, lb3 = (lane>>3)&1;
#pragma unroll
    for (int kk=0;kk<4;kk++){
        unsigned a[4][4];
#pragma unroll
        for (int mt=0;mt<4;mt++)
            ldsm4(a[mt], As + sw128((wm + mt*16 + l15)*128 + (kk*2 + lh)*16));
        unsigned b[2][4];
#pragma unroll
        for (int bp=0;bp<2;bp++){
            unsigned row = wn + bp*16 + lh*8 + l7;
            ldsm4(b[bp], Bs + sw128(row*128 + (kk*2 + lb3)*16));
        }
#pragma unroll
        for (int mt=0;mt<4;mt++)
#pragma unroll
            for (int nt=0;nt<4;nt++)
                MMA_BF16(acc[mt][nt], a[mt], b[nt>>1] + (nt&1)*2);
    }
}

// 3-stage cp.async pipeline, one barrier per K-step
__device__ __forceinline__ void gemm_loop_bf(const bf16* __restrict__ A, int lda,
    const bf16* __restrict__ B, int ldb, int m0, int n0, int K,
    char* smem, float acc[4][4][4], int tid, int lane, int wm, int wn)
{
    const int nsteps = K >> 6;
    stage_bf(A, lda, m0, 0, smem, tid);
    stage_bf(B, ldb, n0, 0, smem + TILEB, tid);
    CP_COMMIT();
    if (nsteps > 1){
        stage_bf(A, lda, m0, BKB, smem + 2*TILEB, tid);
        stage_bf(B, ldb, n0, BKB, smem + 3*TILEB, tid);
        CP_COMMIT();
    }
    for (int s=0; s<nsteps; s++){
        if (s+1 < nsteps) { CP_WAIT(1); } else { CP_WAIT(0); }
        __syncthreads();
        if (s+2 < nsteps){
            char* T = smem + ((s+2)%3)*2*TILEB;
            stage_bf(A, lda, m0, (s+2)*BKB, T, tid);
            stage_bf(B, ldb, n0, (s+2)*BKB, T + TILEB, tid);
            CP_COMMIT();
        }
        char* Cur = smem + (s%3)*2*TILEB;
        compute_bf(Cur, Cur + TILEB, acc, lane, wm, wn);
    }
    __syncthreads();   // smem safe for reuse after loop
}

// ---------------- GEMM kernels ----------------

// C[m,n] = sum_k A[m,k]*B[n,k] (+bias) (+resid); optional fp32 out, optional bf16 out
__global__ __launch_bounds__(256, 2) void mma_nt_bf(
    const bf16* __restrict__ A, const bf16* __restrict__ B,
    const float* __restrict__ bias, const float* __restrict__ resid,
    float* __restrict__ Cf, bf16* __restrict__ Cb,
    int K, int lda, int ldb, int ldc, int ldr, int ldcb)
{
    extern __shared__ char smem[];
    const int tid=threadIdx.x, lane=tid&31, wid=tid>>5;
    const int wm=(wid>>2)*64, wn=(wid&3)*32;
    const int m0=blockIdx.y*BM, n0=blockIdx.x*BN;
    float acc[4][4][4] = {};
    gemm_loop_bf(A, lda, B, ldb, m0, n0, K, smem, acc, tid, lane, wm, wn);
    const int gr=lane>>2, gc=lane&3;
#pragma unroll
    for (int mt=0;mt<4;mt++){
#pragma unroll
        for (int nt=0;nt<4;nt++){
            int row = m0+wm+mt*16+gr;
            int col = n0+wn+nt*8+gc*2;
            float b0=0.f,b1=0.f;
            if (bias){ b0=bias[col]; b1=bias[col+1]; }
            float r00=0,r01=0,r10=0,r11=0;
            if (resid){
                const float* rp  = resid + (size_t)row*ldr + col;
                const float* rp2 = resid + (size_t)(row+8)*ldr + col;
                r00=rp[0]; r01=rp[1]; r10=rp2[0]; r11=rp2[1];
            }
            float v00=acc[mt][nt][0]+b0+r00, v01=acc[mt][nt][1]+b1+r01;
            float v10=acc[mt][nt][2]+b0+r10, v11=acc[mt][nt][3]+b1+r11;
            if (Cf){
                *(float2*)(Cf + (size_t)row*ldc + col)     = make_float2(v00,v01);
                *(float2*)(Cf + (size_t)(row+8)*ldc + col) = make_float2(v10,v11);
            }
            if (Cb){
                *(__nv_bfloat162*)(Cb + (size_t)row*ldcb + col)     = __floats2bfloat162_rn(v00,v01);
                *(__nv_bfloat162*)(Cb + (size_t)(row+8)*ldcb + col) = __floats2bfloat162_rn(v10,v11);
            }
        }
    }
}

// split-K=2 NT GEMM: z-half writes partial fp32 sums to g_sk0/g_sk1 (N = DMOD)
__global__ __launch_bounds__(256, 2) void mma_nt_sk(
    const bf16* __restrict__ A, const bf16* __restrict__ B,
    int Khalf, int lda, int ldb)
{
    extern __shared__ char smem[];
    const int tid=threadIdx.x, lane=tid&31, wid=tid>>5;
    const int wm=(wid>>2)*64, wn=(wid&3)*32;
    const int m0=blockIdx.y*BM, n0=blockIdx.x*BN;
    const int koff = blockIdx.z * Khalf;
    float* P = blockIdx.z ? g_sk1 : g_sk0;
    float acc[4][4][4] = {};
    gemm_loop_bf(A + koff, lda, B + koff, ldb, m0, n0, Khalf, smem, acc, tid, lane, wm, wn);
    const int gr=lane>>2, gc=lane&3;
#pragma unroll
    for (int mt=0;mt<4;mt++){
#pragma unroll
        for (int nt=0;nt<4;nt++){
            int row = m0+wm+mt*16+gr;
            int col = n0+wn+nt*8+gc*2;
            *(float2*)(P + (size_t)row*DMOD + col)     = make_float2(acc[mt][nt][0],acc[mt][nt][1]);
            *(float2*)(P + (size_t)(row+8)*DMOD + col) = make_float2(acc[mt][nt][2],acc[mt][nt][3]);
        }
    }
}

// ffn-in GEMM with fused GELU-pair epilogue (interleaved weights).
__global__ __launch_bounds__(256, 2) void mma_ffn1()
{
    extern __shared__ char smem[];
    const int tid=threadIdx.x, lane=tid&31, wid=tid>>5;
    const int wm=(wid>>2)*64, wn=(wid&3)*32;
    const int m0=blockIdx.y*BM, n0=blockIdx.x*BN;
    float acc[4][4][4] = {};
    gemm_loop_bf(g_hf_bf, DMOD, g_ffnw_bf, DMOD, m0, n0, DMOD, smem, acc, tid, lane, wm, wn);
    const int gr=lane>>2, gc=lane&3;
#pragma unroll
    for (int mt=0;mt<4;mt++){
#pragma unroll
        for (int nt=0;nt<4;nt++){
            int row = m0+wm+mt*16+gr;
            int col = n0+wn+nt*8+gc*2;   // even: a, odd: z
            int t = col >> 1;
            g_g2_bf[(size_t)row*DHID + t]     = __float2bfloat16_rn(fgelu(acc[mt][nt][0]) * acc[mt][nt][1]);
            g_g2_bf[(size_t)(row+8)*DHID + t] = __float2bfloat16_rn(fgelu(acc[mt][nt][2]) * acc[mt][nt][3]);
        }
    }
}

// fused q/k/v: grid.z = which*NHEAD + h; per-head input slice (head_lin semantics).
__global__ __launch_bounds__(256, 2) void mma_qkv()
{
    const int z = blockIdx.z;
    const int which = z >> 3;      // 0=q, 1=k, 2=v
    const int h = z & 7;
    const bf16* A; int lda; const bf16* B; bf16* C;
    if (which == 0){ A = g_xc_bf   + h*DHEAD; lda = DIN;   B = g_wqt_bf + h*DHEAD*DHEAD; C = g_q_bf + h*DHEAD; }
    else if (which == 1){ A = g_xc_bf + h*DHEAD; lda = DIN; B = g_wkt_bf + h*DHEAD*DHEAD; C = g_k_bf + h*DHEAD; }
    else { A = g_proj_bf + h*DHEAD; lda = 2*DIN; B = g_wvt_bf + h*DHEAD*DHEAD; C = g_v_bf + h*DHEAD; }
    extern __shared__ char smem[];
    const int tid=threadIdx.x, lane=tid&31, wid=tid>>5;
    const int wm=(wid>>2)*64, wn=(wid&3)*32;
    const int m0=blockIdx.y*BM, n0=blockIdx.x*BN;
    float acc[4][4][4] = {};
    gemm_loop_bf(A, lda, B, DHEAD, m0, n0, DHEAD, smem, acc, tid, lane, wm, wn);
    const int gr=lane>>2, gc=lane&3;
#pragma unroll
    for (int mt=0;mt<4;mt++){
#pragma unroll
        for (int nt=0;nt<4;nt++){
            int row = m0+wm+mt*16+gr;
            int col = n0+wn+nt*8+gc*2;
            *(__nv_bfloat162*)(C + (size_t)row*DIN + col)     = __floats2bfloat162_rn(acc[mt][nt][0],acc[mt][nt][1]);
            *(__nv_bfloat162*)(C + (size_t)(row+8)*DIN + col) = __floats2bfloat162_rn(acc[mt][nt][2],acc[mt][nt][3]);
        }
    }
}

// scores: C[h][l,m] = (q·k)/16 * exp(rowt[l]+colt[m]) masked; bf16 out + fp32 tile row-sums
__global__ __launch_bounds__(256, 2) void mma_score_bf()
{
    const int h  = blockIdx.z;
    const int l0 = blockIdx.y * BM;
    const int m0 = blockIdx.x * BN;
    if (m0 >= l0 + BM) return;   // fully-masked tile: skipped (never read downstream)
    extern __shared__ char smem[];
    const bf16* A = g_q_bf + h*DHEAD;
    const bf16* B = g_k_bf + h*DHEAD;
    const int tid=threadIdx.x, lane=tid&31, wid=tid>>5;
    const int wm=(wid>>2)*64, wn=(wid&3)*32;
    float acc[4][4][4] = {};
    gemm_loop_bf(A, DIN, B, DIN, l0, m0, DHEAD, smem, acc, tid, lane, wm, wn);

    float* sred = (float*)smem;   // safe: gemm_loop ends with syncthreads
    const float* rt = g_rowt + h*SEQ;
    const float* ct = g_colt + h*SEQ;
    bf16* Cb = g_C_bf + (size_t)h*SEQ*SEQ;
    const int gr=lane>>2, gc=lane&3;
#pragma unroll
    for (int mt=0;mt<4;mt++){
        int l = l0+wm+mt*16+gr;
        float rl0 = rt[l], rl1 = rt[l+8];
        float rs0 = 0.f, rs1 = 0.f;
#pragma unroll
        for (int nt=0;nt<4;nt++){
            int m = m0+wn+nt*8+gc*2;
            float cm0 = ct[m], cm1 = ct[m+1];
            float v00 = (m   <= l  ) ? acc[mt][nt][0]*0.0625f*__expf(rl0+cm0) : 0.f;
            float v01 = (m+1 <= l  ) ? acc[mt][nt][1]*0.0625f*__expf(rl0+cm1) : 0.f;
            float v10 = (m   <= l+8) ? acc[mt][nt][2]*0.0625f*__expf(rl1+cm0) : 0.f;
            float v11 = (m+1 <= l+8) ? acc[mt][nt][3]*0.0625f*__expf(rl1+cm1) : 0.f;
            rs0 += v00 + v01;
            rs1 += v10 + v11;
            *(__nv_bfloat162*)(Cb + (size_t)l*SEQ + m)     = __floats2bfloat162_rn(v00,v01);
            *(__nv_bfloat162*)(Cb + (size_t)(l+8)*SEQ + m) = __floats2bfloat162_rn(v10,v11);
        }
        rs0 += __shfl_xor_sync(0xffffffffu, rs0, 1);
        rs0 += __shfl_xor_sync(0xffffffffu, rs0, 2);
        rs1 += __shfl_xor_sync(0xffffffffu, rs1, 1);
        rs1 += __shfl_xor_sync(0xffffffffu, rs1, 2);
        if (gc == 0){
            sred[(wm+mt*16+gr)*4   + (wid&3)] = rs0;
            sred[(wm+mt*16+gr+8)*4 + (wid&3)] = rs1;
        }
    }
    __syncthreads();
    if (tid < 128){
        float s = sred[tid*4] + sred[tid*4+1] + sred[tid*4+2] + sred[tid*4+3];
        g_psum[((size_t)h*16 + blockIdx.x)*SEQ + l0 + tid] = s;
    }
}

// hflat[l, h*256+d] = invnorm[h,l] * sum_{m<=l} C[h][l,m]*vt[h][d][m]
// inv-norm computed in-kernel from psum partials (normreduce fused).
__global__ __launch_bounds__(256, 2) void mma_pav_bf()
{
    const int h  = blockIdx.z;
    const int l0 = blockIdx.y * BM;
    const int n0 = blockIdx.x * BN;
    extern __shared__ char smem[];
    __shared__ float inrm_s[BM];
    const int tid=threadIdx.x, lane=tid&31, wid=tid>>5;
    if (tid < BM){
        int l = l0 + tid;
        int ntl = (l >> 7) + 1;
        float s = 0.f;
        for (int t=0; t<ntl; t++) s += g_psum[((size_t)h*16 + t)*SEQ + l];
        float n = fmaxf(fabsf(s), g_expn[h*SEQ + l]) + 1e-6f;
        inrm_s[tid] = 1.0f / n;
    }
    const bf16* A = g_C_bf + (size_t)h*SEQ*SEQ;
    const bf16* B = g_vt_bf + (size_t)h*DHEAD*SEQ;
    const int Kmax = l0 + BM;   // causal bound
    const int wm=(wid>>2)*64, wn=(wid&3)*32;
    float acc[4][4][4] = {};
    gemm_loop_bf(A, SEQ, B, SEQ, l0, n0, Kmax, smem, acc, tid, lane, wm, wn);
    const int gr=lane>>2, gc=lane&3;
#pragma unroll
    for (int mt=0;mt<4;mt++){
#pragma unroll
        for (int nt=0;nt<4;nt++){
            int lr = wm+mt*16+gr;
            int l = l0+lr;
            int col = n0+wn+nt*8+gc*2;
            float s0 = inrm_s[lr];
            float s1 = inrm_s[lr+8];
            float* c0 = g_hfl + (size_t)l*DIN + h*DHEAD + col;
            float* c1 = g_hfl + (size_t)(l+8)*DIN + h*DHEAD + col;
            *(float2*)c0 = make_float2(acc[mt][nt][0]*s0, acc[mt][nt][1]*s0);
            *(float2*)c1 = make_float2(acc[mt][nt][2]*s1, acc[mt][nt][3]*s1);
        }
    }
}

// ---------------- weight prep ----------------
#define CW_N0 524288   // winw  4M elems / 8
#define CW_N1 262144   // woutw 2M / 8
#define CW_N2 262144   // ffnow 2M / 8
#define CW_N3 524288   // ffnw  4M / 8 (remapped)
__device__ __forceinline__ void cvt8(const float* s, bf16* d){
    float4 a = ((const float4*)s)[0], b = ((const float4*)s)[1];
    __nv_bfloat162 o[4] = { __floats2bfloat162_rn(a.x,a.y), __floats2bfloat162_rn(a.z,a.w),
                            __floats2bfloat162_rn(b.x,b.y), __floats2bfloat162_rn(b.z,b.w) };
    *(uint4*)d = *(uint4*)o;
}
__global__ void convert_weights(const float* __restrict__ winw, const float* __restrict__ woutw,
                                const float* __restrict__ ffnw, const float* __restrict__ ffnow)
{
    int i = blockIdx.x*256 + threadIdx.x;
    if (i < CW_N0){
        cvt8(winw + (size_t)i*8, g_winw_bf + (size_t)i*8);
    } else if (i < CW_N0+CW_N1){
        int j = i - CW_N0;
        cvt8(woutw + (size_t)j*8, g_woutw_bf + (size_t)j*8);
    } else if (i < CW_N0+CW_N1+CW_N2){
        int j = i - CW_N0 - CW_N1;
        cvt8(ffnow + (size_t)j*8, g_ffnow_bf + (size_t)j*8);
    } else {
        int j = i - CW_N0 - CW_N1 - CW_N2;
        if (j < CW_N3){
            int r = j >> 7, c8 = (j & 127) * 8;
            int src = (r & 1) ? (DHID + (r>>1)) : (r>>1);
            cvt8(ffnw + (size_t)src*DMOD + c8, g_ffnw_bf + (size_t)r*DMOD + c8);
        }
    }
}

__global__ void transpose_w_all(const float* __restrict__ wq, const float* __restrict__ wk,
                                const float* __restrict__ wv)
{
    __shared__ float t[32][33];
    int z = blockIdx.z;
    int which = z >> 3, h = z & 7;
    const float* I = (which==0 ? wq : which==1 ? wk : wv) + (size_t)h*DHEAD*DHEAD;
    bf16* O = (which==0 ? g_wqt_bf : which==1 ? g_wkt_bf : g_wvt_bf) + (size_t)h*DHEAD*DHEAD;
    int k0 = blockIdx.y*32, d0 = blockIdx.x*32;
    int x = threadIdx.x, y = threadIdx.y;
#pragma unroll
    for (int i=0;i<32;i+=8) t[y+i][x] = I[(size_t)(k0+y+i)*DHEAD + d0 + x];
    __syncthreads();
#pragma unroll
    for (int i=0;i<32;i+=8) O[(size_t)(d0+y+i)*DHEAD + k0 + x] = __float2bfloat16_rn(t[x][y+i]);
}

__global__ void transpose_v_bf()
{
    __shared__ float t[32][33];
    int h = blockIdx.z;
    int m0 = blockIdx.x*32, d0 = blockIdx.y*32;
    int x = threadIdx.x, y = threadIdx.y;
#pragma unroll
    for (int i=0;i<32;i+=8) t[y+i][x] = __bfloat162float(g_v_bf[(size_t)(m0+y+i)*DIN + h*DHEAD + d0 + x]);
    __syncthreads();
#pragma unroll
    for (int i=0;i<32;i+=8)
        g_vt_bf[((size_t)h*DHEAD + d0+y+i)*SEQ + m0 + x] = __float2bfloat16_rn(t[x][y+i]);
}

// ---------------- elementwise / reduction kernels ----------------
// warp-per-row layernorm (cols = 1024)
__global__ __launch_bounds__(256) void layernorm_bf(const float* __restrict__ x,
    const float* __restrict__ w, bf16* __restrict__ out, int cols)
{
    int wrp = threadIdx.x >> 5, lane = threadIdx.x & 31;
    int row = blockIdx.x*8 + wrp;
    const float* xr = x + (size_t)row*cols;
    float4 v[8];
    float s = 0.f, ss = 0.f;
#pragma unroll
    for (int i=0;i<8;i++){
        v[i] = ((const float4*)xr)[lane + i*32];
        s  += v[i].x + v[i].y + v[i].z + v[i].w;
        ss += v[i].x*v[i].x + v[i].y*v[i].y + v[i].z*v[i].z + v[i].w*v[i].w;
    }
#pragma unroll
    for (int off=16; off>0; off>>=1){
        s  += __shfl_xor_sync(0xffffffffu, s,  off);
        ss += __shfl_xor_sync(0xffffffffu, ss, off);
    }
    float mean = s / cols;
    float var  = ss / cols - mean*mean;
    float rstd = rsqrtf(var + 1e-5f);
    bf16* orow = out + (size_t)row*cols;
#pragma unroll
    for (int i=0;i<8;i++){
        float4 wv = ((const float4*)w)[lane + i*32];
        __nv_bfloat162 o0 = __floats2bfloat162_rn((v[i].x-mean)*rstd*wv.x, (v[i].y-mean)*rstd*wv.y);
        __nv_bfloat162 o1 = __floats2bfloat162_rn((v[i].z-mean)*rstd*wv.z, (v[i].w-mean)*rstd*wv.w);
        uint2 pk = make_uint2(*(unsigned*)&o0, *(unsigned*)&o1);
        *(uint2*)(orow + (lane + i*32)*4) = pk;
    }
}

// x2 = x + P0 + P1; hf = LN(x2)*w; writes x2 fp32 and hf bf16 (split-K combine + LN fused)
__global__ __launch_bounds__(256) void ln_combine(const float* __restrict__ x,
    const float* __restrict__ w, bf16* __restrict__ out, float* __restrict__ x2)
{
    const int cols = DMOD;
    int wrp = threadIdx.x >> 5, lane = threadIdx.x & 31;
    int row = blockIdx.x*8 + wrp;
    const float* xr = x + (size_t)row*cols;
    const float* p0 = g_sk0 + (size_t)row*cols;
    const float* p1 = g_sk1 + (size_t)row*cols;
    float4 v[8];
    float s = 0.f, ss = 0.f;
#pragma unroll
    for (int i=0;i<8;i++){
        float4 a = ((const float4*)xr)[lane + i*32];
        float4 b = ((const float4*)p0)[lane + i*32];
        float4 c = ((const float4*)p1)[lane + i*32];
        v[i] = make_float4(a.x+b.x+c.x, a.y+b.y+c.y, a.z+b.z+c.z, a.w+b.w+c.w);
        s  += v[i].x + v[i].y + v[i].z + v[i].w;
        ss += v[i].x*v[i].x + v[i].y*v[i].y + v[i].z*v[i].z + v[i].w*v[i].w;
    }
#pragma unroll
    for (int off=16; off>0; off>>=1){
        s  += __shfl_xor_sync(0xffffffffu, s,  off);
        ss += __shfl_xor_sync(0xffffffffu, ss, off);
    }
    float mean = s / cols;
    float var  = ss / cols - mean*mean;
    float rstd = rsqrtf(var + 1e-5f);
    bf16* orow = out + (size_t)row*cols;
    float* x2r = x2 + (size_t)row*cols;
#pragma unroll
    for (int i=0;i<8;i++){
        ((float4*)x2r)[lane + i*32] = v[i];
        float4 wv = ((const float4*)w)[lane + i*32];
        __nv_bfloat162 o0 = __floats2bfloat162_rn((v[i].x-mean)*rstd*wv.x, (v[i].y-mean)*rstd*wv.y);
        __nv_bfloat162 o1 = __floats2bfloat162_rn((v[i].z-mean)*rstd*wv.z, (v[i].w-mean)*rstd*wv.w);
        uint2 pk = make_uint2(*(unsigned*)&o0, *(unsigned*)&o1);
        *(uint2*)(orow + (lane + i*32)*4) = pk;
    }
}

// out = x2 + Q0 + Q1 (final split-K combine), float4 vectorized
__global__ void final_combine(float* __restrict__ out)
{
    int i = blockIdx.x*256 + threadIdx.x;
    if (i >= SEQ*DMOD/4) return;
    float4 a = ((const float4*)g_x2)[i];
    float4 b = ((const float4*)g_sk0)[i];
    float4 c = ((const float4*)g_sk1)[i];
    ((float4*)out)[i] = make_float4(a.x+b.x+c.x, a.y+b.y+c.y, a.z+b.z+c.z, a.w+b.w+c.w);
}

__global__ __launch_bounds__(256) void conv_silu_kernel(const float* __restrict__ ck, const float* __restrict__ cb)
{
    int l = blockIdx.x;
    int c8 = threadIdx.x * 8;
    float acc[8];
    {
        float4 b0 = *(const float4*)(cb + c8);
        float4 b1 = *(const float4*)(cb + c8 + 4);
        acc[0]=b0.x; acc[1]=b0.y; acc[2]=b0.z; acc[3]=b0.w;
        acc[4]=b1.x; acc[5]=b1.y; acc[6]=b1.z; acc[7]=b1.w;
    }
    float4 kt[8];
#pragma unroll
    for (int j=0;j<8;j++) kt[j] = *(const float4*)(ck + (c8+j)*4);
#pragma unroll
    for (int t=0;t<4;t++){
        int ls = l - t;
        if (ls < 0) break;
        uint4 u = *(const uint4*)(g_proj_bf + (size_t)ls*(2*DIN) + c8);
        __nv_bfloat162* bp = (__nv_bfloat162*)&u;
        float tap[8];
#pragma unroll
        for (int j=0;j<4;j++){ float2 f = __bfloat1622float2(bp[j]); tap[2*j]=f.x; tap[2*j+1]=f.y; }
#pragma unroll
        for (int j=0;j<8;j++)
            acc[j] = fmaf(tap[j], ((float*)&kt[j])[t], acc[j]);
    }
    __nv_bfloat162 o[4];
#pragma unroll
    for (int j=0;j<4;j++){
        float a0 = acc[2*j],   r0 = a0 * fsigmoid(a0);
        float a1 = acc[2*j+1], r1 = a1 * fsigmoid(a1);
        o[j] = __floats2bfloat162_rn(r0, r1);
    }
    *(uint4*)(g_xc_bf + (size_t)l*DIN + c8) = *(uint4*)o;
}

#define GROWS 16
__global__ __launch_bounds__(256) void gates_kernel(
    const float* __restrict__ igw, const float* __restrict__ igb,
    const float* __restrict__ fgw, const float* __restrict__ fgb)
{
    extern __shared__ bf16 gbuf[];
    int l0 = blockIdx.x*GROWS, tid = threadIdx.x;
    const int CH = DIN/8;
    for (int i = tid; i < GROWS*3*CH; i += 256){
        int rr = i / (3*CH); int rem = i - rr*3*CH;
        int a = rem / CH;    int ch = rem - a*CH;
        const bf16* src = (a==0 ? g_q_bf : a==1 ? g_k_bf : g_v_bf) + (size_t)(l0+rr)*DIN + ch*8;
        *(uint4*)&gbuf[(size_t)rr*3*DIN + a*DIN + ch*8] = *(const uint4*)src;
    }
    __syncthreads();
    int w = tid >> 5, lane = tid & 31;
    const float* iw = igw + (size_t)w*3*DIN;
    const float* fw = fgw + (size_t)w*3*DIN;
    float si[GROWS] = {}, sf[GROWS] = {};
    for (int j = lane*8; j < 3*DIN; j += 256){
        float4 wi0 = *(const float4*)(iw + j), wi1 = *(const float4*)(iw + j + 4);
        float4 wf0 = *(const float4*)(fw + j), wf1 = *(const float4*)(fw + j + 4);
#pragma unroll
        for (int rr=0; rr<GROWS; rr++){
            uint4 u = *(uint4*)&gbuf[(size_t)rr*3*DIN + j];
            __nv_bfloat162* bp = (__nv_bfloat162*)&u;
            float2 g0 = __bfloat1622float2(bp[0]);
            float2 g1 = __bfloat1622float2(bp[1]);
            float2 g2 = __bfloat1622float2(bp[2]);
            float2 g3 = __bfloat1622float2(bp[3]);
            si[rr] = fmaf(g0.x, wi0.x, si[rr]); si[rr] = fmaf(g0.y, wi0.y, si[rr]);
            si[rr] = fmaf(g1.x, wi0.z, si[rr]); si[rr] = fmaf(g1.y, wi0.w, si[rr]);
            si[rr] = fmaf(g2.x, wi1.x, si[rr]); si[rr] = fmaf(g2.y, wi1.y, si[rr]);
            si[rr] = fmaf(g3.x, wi1.z, si[rr]); si[rr] = fmaf(g3.y, wi1.w, si[rr]);
            sf[rr] = fmaf(g0.x, wf0.x, sf[rr]); sf[rr] = fmaf(g0.y, wf0.y, sf[rr]);
            sf[rr] = fmaf(g1.x, wf0.z, sf[rr]); sf[rr] = fmaf(g1.y, wf0.w, sf[rr]);
            sf[rr] = fmaf(g2.x, wf1.x, sf[rr]); sf[rr] = fmaf(g2.y, wf1.y, sf[rr]);
            sf[rr] = fmaf(g3.x, wf1.z, sf[rr]); sf[rr] = fmaf(g3.y, wf1.w, sf[rr]);
        }
    }
#pragma unroll
    for (int off=16; off>0; off>>=1){
#pragma unroll
        for (int rr=0;rr<GROWS;rr++){
            si[rr] += __shfl_xor_sync(0xffffffffu, si[rr], off);
            sf[rr] += __shfl_xor_sync(0xffffffffu, sf[rr], off);
        }
    }
    if (lane == 0){
#pragma unroll
        for (int rr=0;rr<GROWS;rr++){
            g_ig[w*SEQ + l0+rr] = si[rr] + igb[w];
            g_fg[w*SEQ + l0+rr] = sf[rr] + fgb[w];
        }
    }
}

__global__ __launch_bounds__(256) void scan_kernel()
{
    __shared__ float lf[SEQ];
    __shared__ float tot[256];
    int h = blockIdx.x, tid = threadIdx.x;
    for (int m = tid; m < SEQ; m += 256){
        float f = g_fg[h*SEQ + m];
        lf[m] = fminf(f, 0.f) - log1pf(expf(-fabsf(f)));
    }
    __syncthreads();
    int base = tid * 8;
    float csl[8];
    float run = 0.f;
#pragma unroll
    for (int j=0;j<8;j++){ run += lf[base+j]; csl[j] = run; }
    tot[tid] = run; __syncthreads();
    for (int off=1; off<256; off<<=1){
        float v = (tid >= off) ? tot[tid-off] : 0.f;
        __syncthreads();
        tot[tid] += v;
        __syncthreads();
    }
    float excl = tot[tid] - run;
    float cs[8], cml[8];
    float rmax = -INFINITY;
#pragma unroll
    for (int j=0;j<8;j++){
        cs[j] = csl[j] + excl;
        float col = g_ig[h*SEQ + base + j] - cs[j];
        g_colt[h*SEQ + base + j] = col;
        rmax = fmaxf(rmax, col);
        cml[j] = rmax;
    }
    tot[tid] = rmax; __syncthreads();
    for (int off=1; off<256; off<<=1){
        float v = (tid >= off) ? tot[tid-off] : -INFINITY;
        __syncthreads();
        tot[tid] = fmaxf(tot[tid], v);
        __syncthreads();
    }
    float em = (tid > 0) ? tot[tid-1] : -INFINITY;
#pragma unroll
    for (int j=0;j<8;j++){
        float rm = fmaxf(em, cml[j]);
        g_rowt[h*SEQ + base + j] = -rm;
        g_expn[h*SEQ + base + j] = expf(-(cs[j] + rm));
    }
}

__global__ __launch_bounds__(256) void gn_kernel(const float* __restrict__ gnw,
    const float* __restrict__ gnb, const float* __restrict__ skip)
{
    int l = blockIdx.x, tid = threadIdx.x, w = tid >> 5, lane = tid & 31;
    int c0 = w*DHEAD + lane*8;
    float4 h0 = *(const float4*)(g_hfl + (size_t)l*DIN + c0);
    float4 h1 = *(const float4*)(g_hfl + (size_t)l*DIN + c0 + 4);
    float vals[8] = {h0.x,h0.y,h0.z,h0.w,h1.x,h1.y,h1.z,h1.w};
    float s = 0.f, ss = 0.f;
#pragma unroll
    for (int j=0;j<8;j++){ s += vals[j]; ss += vals[j]*vals[j]; }
#pragma unroll
    for (int off=16; off>0; off>>=1){
        s  += __shfl_xor_sync(0xffffffffu, s,  off);
        ss += __shfl_xor_sync(0xffffffffu, ss, off);
    }
    float mean = s * (1.f/DHEAD);
    float var  = ss * (1.f/DHEAD) - mean*mean;
    float rstd = rsqrtf(var + 1e-5f);
    float4 gw0 = *(const float4*)(gnw + c0), gw1 = *(const float4*)(gnw + c0 + 4);
    float4 gb0 = *(const float4*)(gnb + c0), gb1 = *(const float4*)(gnb + c0 + 4);
    float4 sk0 = *(const float4*)(skip + c0), sk1 = *(const float4*)(skip + c0 + 4);
    uint4 uxc = *(const uint4*)(g_xc_bf + (size_t)l*DIN + c0);
    uint4 urs = *(const uint4*)(g_proj_bf + (size_t)l*(2*DIN) + DIN + c0);
    float gwv[8] = {gw0.x,gw0.y,gw0.z,gw0.w,gw1.x,gw1.y,gw1.z,gw1.w};
    float gbv[8] = {gb0.x,gb0.y,gb0.z,gb0.w,gb1.x,gb1.y,gb1.z,gb1.w};
    float skv[8] = {sk0.x,sk0.y,sk0.z,sk0.w,sk1.x,sk1.y,sk1.z,sk1.w};
    float xcv[8], rsv[8];
    {
        __nv_bfloat162* bx = (__nv_bfloat162*)&uxc;
        __nv_bfloat162* br = (__nv_bfloat162*)&urs;
#pragma unroll
        for (int j=0;j<4;j++){
            float2 fx = __bfloat1622float2(bx[j]); xcv[2*j]=fx.x; xcv[2*j+1]=fx.y;
            float2 fr = __bfloat1622float2(br[j]); rsv[2*j]=fr.x; rsv[2*j+1]=fr.y;
        }
    }
    __nv_bfloat162 o[4];
#pragma unroll
    for (int j=0;j<4;j++){
        float y0, y1;
        {
            float hn = (vals[2*j] - mean) * rstd;
            float h2 = hn*gwv[2*j] + gbv[2*j] + skv[2*j]*xcv[2*j];
            float r  = rsv[2*j];
            y0 = h2 * (r * fsigmoid(r));
        }
        {
            float hn = (vals[2*j+1] - mean) * rstd;
            float h2 = hn*gwv[2*j+1] + gbv[2*j+1] + skv[2*j+1]*xcv[2*j+1];
            float r  = rsv[2*j+1];
            y1 = h2 * (r * fsigmoid(r));
        }
        o[j] = __floats2bfloat162_rn(y0, y1);
    }
    *(uint4*)(g_yin_bf + (size_t)l*DIN + c0) = *(uint4*)o;
}

// ---------------- launch ----------------
extern "C" void kernel_launch(void* const* d_in, const int* in_sizes, int n_in,
                              void* d_out, int out_size)
{
    (void)in_sizes; (void)n_in; (void)out_size;
    const float* x    = (const float*)d_in[0];
    const float* ln1w = (const float*)d_in[2];
    const float* winw = (const float*)d_in[3];
    const float* winb = (const float*)d_in[4];
    const float* woutw= (const float*)d_in[5];
    const float* ck   = (const float*)d_in[6];
    const float* cb   = (const float*)d_in[7];
    const float* wq   = (const float*)d_in[8];
    const float* wk   = (const float*)d_in[9];
    const float* wv   = (const float*)d_in[10];
    const float* igw  = (const float*)d_in[11];
    const float* igb  = (const float*)d_in[12];
    const float* fgw  = (const float*)d_in[13];
    const float* fgb  = (const float*)d_in[14];
    const float* gnw  = (const float*)d_in[15];
    const float* gnb  = (const float*)d_in[16];
    const float* skip = (const float*)d_in[17];
    const float* ln2w = (const float*)d_in[18];
    const float* ffnw = (const float*)d_in[19];
    const float* ffnow= (const float*)d_in[20];
    float* out = (float*)d_out;

    static int attr_set = 0;
    if (!attr_set){
        cudaFuncSetAttribute(mma_nt_bf,    cudaFuncAttributeMaxDynamicSharedMemorySize, SMEM_GEMM);
        cudaFuncSetAttribute(mma_nt_sk,    cudaFuncAttributeMaxDynamicSharedMemorySize, SMEM_GEMM);
        cudaFuncSetAttribute(mma_ffn1,     cudaFuncAttributeMaxDynamicSharedMemorySize, SMEM_GEMM);
        cudaFuncSetAttribute(mma_qkv,      cudaFuncAttributeMaxDynamicSharedMemorySize, SMEM_GEMM);
        cudaFuncSetAttribute(mma_score_bf, cudaFuncAttributeMaxDynamicSharedMemorySize, SMEM_GEMM);
        cudaFuncSetAttribute(mma_pav_bf,   cudaFuncAttributeMaxDynamicSharedMemorySize, SMEM_GEMM);
        cudaFuncSetAttribute(gates_kernel, cudaFuncAttributeMaxDynamicSharedMemorySize, GROWS*3*DIN*2);
        attr_set = 1;
    }

    float *x2;
    bf16 *hln,*projb,*winwb,*yinb,*hfb,*g2b;
    cudaGetSymbolAddress((void**)&x2,    g_x2);
    cudaGetSymbolAddress((void**)&hln,   g_hln_bf);
    cudaGetSymbolAddress((void**)&projb, g_proj_bf);
    cudaGetSymbolAddress((void**)&winwb, g_winw_bf);
    cudaGetSymbolAddress((void**)&yinb,  g_yin_bf);
    cudaGetSymbolAddress((void**)&hfb,   g_hf_bf);
    cudaGetSymbolAddress((void**)&g2b,   g_g2_bf);
    bf16 *woutwb, *ffnowb;
    cudaGetSymbolAddress((void**)&woutwb, g_woutw_bf);
    cudaGetSymbolAddress((void**)&ffnowb, g_ffnow_bf);

    dim3 tb(32, 8);

    // 0. hln = LN(x) -> bf16
    layernorm_bf<<<SEQ/8, 256>>>(x, ln1w, hln, DMOD);
    // 1. all weight converts
    convert_weights<<<(CW_N0+CW_N1+CW_N2+CW_N3+255)/256, 256>>>(winw, woutw, ffnw, ffnow);
    // 2. all per-head weight transposes
    transpose_w_all<<<dim3(8,8,24), tb>>>(wq, wk, wv);
    // 3. proj = hln @ win^T + b -> bf16
    mma_nt_bf<<<dim3(4096/BN, SEQ/BM), 256, SMEM_GEMM>>>(hln, winwb, winb, 0,
        (float*)0, projb, DMOD, DMOD, DMOD, 0, 0, 2*DIN);
    // 4. xc = silu(conv(xi)) -> bf16
    conv_silu_kernel<<<SEQ, 256>>>(ck, cb);
    // 5. fused q/k/v
    mma_qkv<<<dim3(2, SEQ/BM, 3*NHEAD), 256, SMEM_GEMM>>>();
    // 6. vt
    transpose_v_bf<<<dim3(SEQ/32, DHEAD/32, NHEAD), tb>>>();
    // 7. gates
    gates_kernel<<<SEQ/GROWS, 256, GROWS*3*DIN*2>>>(igw, igb, fgw, fgb);
    // 8. per-head scans
    scan_kernel<<<NHEAD, 256>>>();
    // 9. C = (QK^T/16)*D (bf16) + fused tile row-sums
    mma_score_bf<<<dim3(SEQ/BN, SEQ/BM, NHEAD), 256, SMEM_GEMM>>>();
    // 10. hflat = (C*invnorm) @ V  (normreduce fused in prologue)
    mma_pav_bf<<<dim3(2, SEQ/BM, NHEAD), 256, SMEM_GEMM>>>();
    // 11. group norm + skip*xc, * silu(res) -> bf16
    gn_kernel<<<SEQ, 256>>>(gnw, gnb, skip);
    // 12. wout GEMM split-K=2 -> partials
    mma_nt_sk<<<dim3(DMOD/BN, SEQ/BM, 2), 256, SMEM_GEMM>>>(yinb, woutwb, DIN/2, DIN, DIN);
    // 13. x2 = x + P0 + P1; hf = LN(x2) (fused combine)
    ln_combine<<<SEQ/8, 256>>>(x, ln2w, hfb, x2);
    // 14. g2 = gelu(a)*z fused into ffn-in GEMM
    mma_ffn1<<<dim3(4096/BN, SEQ/BM), 256, SMEM_GEMM>>>();
    // 15. ffn-out GEMM split-K=2 -> partials
    mma_nt_sk<<<dim3(DMOD/BN, SEQ/BM, 2), 256, SMEM_GEMM>>>(g2b, ffnowb, DHID/2, DHID, DHID);
    // 16. out = x2 + Q0 + Q1
    final_combine<<<SEQ*DMOD/4/256, 256>>>(out);
}